// round 2
// baseline (speedup 1.0000x reference)
#include <cuda_runtime.h>
#include <cuda_bf16.h>

#define N_NODES 50000
#define N_EDGES 800000
#define HEADS 8
#define DOUT 32
#define HD 256          // HEADS*DOUT == IN_FEATS == 256
#define NEG_SLOPE 0.2f

// ---------------- scratch (static device globals; no allocation) -------------
__device__ float g_h [N_NODES * HD];      // projected node features (N,256)
__device__ float g_el[N_NODES * HEADS];   // per-node left attention scalar
__device__ float g_er[N_NODES * HEADS];   // per-node right attention scalar
__device__ float g_s [N_NODES * HEADS];   // softmax denominators
__device__ float g_P [N_EDGES * HEADS];   // per-edge exp(logit)
__device__ float g_C [HEADS * HEADS];     // folded W_e * attn_e  (k-major: C[k*8+h])

// ---------------- K0: fold W_e (8,256) with attn_e (8,32) -> C (8,8) ---------
__global__ void k0_foldC(const float* __restrict__ W_e, const float* __restrict__ attn_e) {
    int t = threadIdx.x;
    if (t < 64) {
        int k = t >> 3, h = t & 7;
        float s = 0.f;
        #pragma unroll
        for (int d = 0; d < DOUT; ++d)
            s += W_e[k * HD + h * DOUT + d] * attn_e[h * DOUT + d];
        g_C[k * 8 + h] = s;
    }
}

// ---------------- packed f32x2 FMA helper ------------------------------------
__device__ __forceinline__ void fma2(unsigned long long& d,
                                     unsigned long long a,
                                     unsigned long long b) {
    asm("fma.rn.f32x2 %0, %1, %2, %0;" : "+l"(d) : "l"(a), "l"(b));
}

union U64F2 { unsigned long long u; float2 f; };

// ---------------- K1: SGEMM  h = feat(50000,256) @ W_src(256,256) ------------
// 128x128 block tile, BK=16, 256 threads, 8x8 microtile via fma.rn.f32x2.
// A fragment stored DUPLICATED in smem ({a,a} pairs) so LDS.128 yields two
// ready broadcast operands; B pairs are natural.
__global__ __launch_bounds__(256) void k1_gemm(const float* __restrict__ A,
                                               const float* __restrict__ B) {
    __shared__ float As2[16][256];  // [k][2*m]  value duplicated: {a,a}
    __shared__ float Bs [16][128];  // [k][n]
    const int t  = threadIdx.x;
    const int tx = t & 15;          // col group (n)
    const int ty = t >> 4;          // row group (m)
    const int bm = blockIdx.x * 128;
    const int bn = blockIdx.y * 128;

    // load indices (each thread: 2 A-float4s + 2 B-float4s per K-tile)
    const int arow0 = t >> 2;            // 0..63
    const int arow1 = arow0 + 64;        // 64..127
    const int kin   = (t & 3) * 4;       // k within tile for A pieces
    const int krow0 = t >> 5;            // 0..7
    const int krow1 = krow0 + 8;         // 8..15
    const int ncol  = (t & 31) * 4;

    const int grow0 = bm + arow0;
    const int grow1 = bm + arow1;
    const float* Ap0 = A + (long)grow0 * HD + kin;
    const float* Ap1 = A + (long)grow1 * HD + kin;
    const float* Bp0 = B + (long)krow0 * HD + bn + ncol;
    const float* Bp1 = B + (long)krow1 * HD + bn + ncol;
    const bool ok0 = grow0 < N_NODES;
    const bool ok1 = grow1 < N_NODES;

    unsigned long long acc[32];         // acc[i*4+j] = float2 pair of out cols
    #pragma unroll
    for (int i = 0; i < 32; ++i) acc[i] = 0ull;

    float4 ra0, ra1, rb0, rb1;

    // prefetch tile 0
    ra0 = ok0 ? *(const float4*)(Ap0) : make_float4(0.f,0.f,0.f,0.f);
    ra1 = ok1 ? *(const float4*)(Ap1) : make_float4(0.f,0.f,0.f,0.f);
    rb0 = *(const float4*)(Bp0);
    rb1 = *(const float4*)(Bp1);

    for (int k0 = 0; k0 < HD; k0 += 16) {
        // store prefetched regs -> smem (A duplicated)
        *(float2*)(&As2[kin + 0][2 * arow0]) = make_float2(ra0.x, ra0.x);
        *(float2*)(&As2[kin + 1][2 * arow0]) = make_float2(ra0.y, ra0.y);
        *(float2*)(&As2[kin + 2][2 * arow0]) = make_float2(ra0.z, ra0.z);
        *(float2*)(&As2[kin + 3][2 * arow0]) = make_float2(ra0.w, ra0.w);
        *(float2*)(&As2[kin + 0][2 * arow1]) = make_float2(ra1.x, ra1.x);
        *(float2*)(&As2[kin + 1][2 * arow1]) = make_float2(ra1.y, ra1.y);
        *(float2*)(&As2[kin + 2][2 * arow1]) = make_float2(ra1.z, ra1.z);
        *(float2*)(&As2[kin + 3][2 * arow1]) = make_float2(ra1.w, ra1.w);
        *(float4*)(&Bs[krow0][ncol]) = rb0;
        *(float4*)(&Bs[krow1][ncol]) = rb1;
        __syncthreads();

        // prefetch next tile while computing this one
        if (k0 + 16 < HD) {
            ra0 = ok0 ? *(const float4*)(Ap0 + k0 + 16) : make_float4(0.f,0.f,0.f,0.f);
            ra1 = ok1 ? *(const float4*)(Ap1 + k0 + 16) : make_float4(0.f,0.f,0.f,0.f);
            rb0 = *(const float4*)(Bp0 + (long)(k0 + 16) * HD);
            rb1 = *(const float4*)(Bp1 + (long)(k0 + 16) * HD);
        }

        #pragma unroll
        for (int k = 0; k < 16; ++k) {
            unsigned long long aa[8], bb[4];
            ulonglong2 q;
            q = *(const ulonglong2*)(&As2[k][ty * 16 + 0]);  aa[0] = q.x; aa[1] = q.y;
            q = *(const ulonglong2*)(&As2[k][ty * 16 + 4]);  aa[2] = q.x; aa[3] = q.y;
            q = *(const ulonglong2*)(&As2[k][ty * 16 + 8]);  aa[4] = q.x; aa[5] = q.y;
            q = *(const ulonglong2*)(&As2[k][ty * 16 + 12]); aa[6] = q.x; aa[7] = q.y;
            q = *(const ulonglong2*)(&Bs[k][tx * 8]);        bb[0] = q.x; bb[1] = q.y;
            q = *(const ulonglong2*)(&Bs[k][tx * 8 + 4]);    bb[2] = q.x; bb[3] = q.y;
            #pragma unroll
            for (int i = 0; i < 8; ++i)
                #pragma unroll
                for (int j = 0; j < 4; ++j)
                    fma2(acc[i * 4 + j], aa[i], bb[j]);
        }
        __syncthreads();
    }

    #pragma unroll
    for (int i = 0; i < 8; ++i) {
        int row = bm + ty * 8 + i;
        if (row < N_NODES) {
            U64F2 c0, c1, c2, c3;
            c0.u = acc[i * 4 + 0]; c1.u = acc[i * 4 + 1];
            c2.u = acc[i * 4 + 2]; c3.u = acc[i * 4 + 3];
            float* o = g_h + (long)row * HD + bn + tx * 8;
            *(float4*)(o)     = make_float4(c0.f.x, c0.f.y, c1.f.x, c1.f.y);
            *(float4*)(o + 4) = make_float4(c2.f.x, c2.f.y, c3.f.x, c3.f.y);
        }
    }
}

// ---------------- K2: per-node el/er, zero s, out = bias ---------------------
// one warp per node; lane handles 8 contiguous floats (head = lane/4)
__global__ __launch_bounds__(256) void k2_node(const float* __restrict__ attn_l,
                                               const float* __restrict__ attn_r,
                                               const float* __restrict__ bias,
                                               float* __restrict__ out) {
    __shared__ float sal[HD], sar[HD], sb[HD];
    int t = threadIdx.x;
    sal[t] = attn_l[t];
    sar[t] = attn_r[t];
    sb[t]  = bias[t];
    __syncthreads();

    int warp = t >> 5, lane = t & 31;
    int n = blockIdx.x * 8 + warp;
    if (n >= N_NODES) return;

    const float4* hp = (const float4*)(g_h + (long)n * HD);
    float4 v0 = hp[lane * 2], v1 = hp[lane * 2 + 1];
    float4 a0 = ((const float4*)sal)[lane * 2], a1 = ((const float4*)sal)[lane * 2 + 1];
    float4 r0 = ((const float4*)sar)[lane * 2], r1 = ((const float4*)sar)[lane * 2 + 1];

    float el = v0.x*a0.x + v0.y*a0.y + v0.z*a0.z + v0.w*a0.w
             + v1.x*a1.x + v1.y*a1.y + v1.z*a1.z + v1.w*a1.w;
    float er = v0.x*r0.x + v0.y*r0.y + v0.z*r0.z + v0.w*r0.w
             + v1.x*r1.x + v1.y*r1.y + v1.z*r1.z + v1.w*r1.w;
    // reduce across the 4 lanes of each head group
    el += __shfl_xor_sync(0xffffffffu, el, 1);
    el += __shfl_xor_sync(0xffffffffu, el, 2);
    er += __shfl_xor_sync(0xffffffffu, er, 1);
    er += __shfl_xor_sync(0xffffffffu, er, 2);
    if ((lane & 3) == 0) {
        g_el[n * HEADS + (lane >> 2)] = el;
        g_er[n * HEADS + (lane >> 2)] = er;
    }
    if (lane < HEADS) g_s[n * HEADS + lane] = 0.f;

    float4* op = (float4*)(out + (long)n * HD);
    op[lane * 2]     = ((const float4*)sb)[lane * 2];
    op[lane * 2 + 1] = ((const float4*)sb)[lane * 2 + 1];
}

// ---------------- K3: per-edge p = exp(leakyrelu(el+er+ee)); s += p ----------
__global__ __launch_bounds__(256) void k3_edge(const float* __restrict__ edge_emb,
                                               const int* __restrict__ src,
                                               const int* __restrict__ dst) {
    __shared__ float Cs[64];
    int t = threadIdx.x;
    if (t < 64) Cs[t] = g_C[t];
    __syncthreads();

    int e = blockIdx.x * blockDim.x + t;
    if (e >= N_EDGES) return;

    int se = src[e], de = dst[e];
    const float4* ep = (const float4*)(edge_emb + (long)e * HEADS);
    float4 e0 = ep[0], e1 = ep[1];
    float ein[8] = {e0.x, e0.y, e0.z, e0.w, e1.x, e1.y, e1.z, e1.w};

    float4 l0 = *(const float4*)(g_el + se * HEADS);
    float4 l1 = *(const float4*)(g_el + se * HEADS + 4);
    float4 r0 = *(const float4*)(g_er + de * HEADS);
    float4 r1 = *(const float4*)(g_er + de * HEADS + 4);
    float elv[8] = {l0.x, l0.y, l0.z, l0.w, l1.x, l1.y, l1.z, l1.w};
    float erv[8] = {r0.x, r0.y, r0.z, r0.w, r1.x, r1.y, r1.z, r1.w};

    float pv[8];
    #pragma unroll
    for (int h = 0; h < 8; ++h) {
        float ee = 0.f;
        #pragma unroll
        for (int k = 0; k < 8; ++k) ee += ein[k] * Cs[k * 8 + h];
        float x = elv[h] + erv[h] + ee;
        x = (x > 0.f) ? x : NEG_SLOPE * x;
        float p = __expf(x);
        pv[h] = p;
        atomicAdd(&g_s[de * HEADS + h], p);
    }
    float4* pp = (float4*)(g_P + (long)e * HEADS);
    pp[0] = make_float4(pv[0], pv[1], pv[2], pv[3]);
    pp[1] = make_float4(pv[4], pv[5], pv[6], pv[7]);
}

// ---------------- K4: weighted aggregation via vector reductions -------------
__device__ __forceinline__ void red_add_v4(float* addr, float a, float b, float c, float d) {
    asm volatile("red.global.add.v4.f32 [%0], {%1, %2, %3, %4};"
                 :: "l"(addr), "f"(a), "f"(b), "f"(c), "f"(d) : "memory");
}

// one warp per edge; lane handles 8 contiguous floats (head = lane/4)
__global__ __launch_bounds__(256) void k4_agg(const int* __restrict__ src,
                                              const int* __restrict__ dst,
                                              float* __restrict__ out) {
    int t = threadIdx.x, warp = t >> 5, lane = t & 31;
    int e = blockIdx.x * 8 + warp;
    if (e >= N_EDGES) return;

    int se = __ldg(&src[e]);
    int de = __ldg(&dst[e]);

    float a = 0.f;
    if (lane < HEADS)
        a = g_P[(long)e * HEADS + lane] / (g_s[de * HEADS + lane] + 1e-9f);
    float alpha = __shfl_sync(0xffffffffu, a, lane >> 2);

    const float4* hp = (const float4*)(g_h + (long)se * HD);
    float4 x = hp[lane * 2];
    float4 y = hp[lane * 2 + 1];

    float* op = out + (long)de * HD + lane * 8;
    red_add_v4(op,     alpha * x.x, alpha * x.y, alpha * x.z, alpha * x.w);
    red_add_v4(op + 4, alpha * y.x, alpha * y.y, alpha * y.z, alpha * y.w);
}

// ---------------- launch ------------------------------------------------------
extern "C" void kernel_launch(void* const* d_in, const int* in_sizes, int n_in,
                              void* d_out, int out_size) {
    const float* feat     = (const float*)d_in[0];
    const float* edge_emb = (const float*)d_in[1];
    const int*   src      = (const int*)  d_in[2];
    const int*   dst      = (const int*)  d_in[3];
    const float* W_src    = (const float*)d_in[4];
    const float* W_e      = (const float*)d_in[5];
    const float* attn_l   = (const float*)d_in[6];
    const float* attn_r   = (const float*)d_in[7];
    const float* attn_e   = (const float*)d_in[8];
    const float* bias     = (const float*)d_in[9];
    float* out = (float*)d_out;

    k0_foldC<<<1, 64>>>(W_e, attn_e);

    dim3 g1((N_NODES + 127) / 128, 2);
    k1_gemm<<<g1, 256>>>(feat, W_src);

    k2_node<<<(N_NODES + 7) / 8, 256>>>(attn_l, attn_r, bias, out);

    k3_edge<<<(N_EDGES + 255) / 256, 256>>>(edge_emb, src, dst);

    k4_agg<<<(N_EDGES + 7) / 8, 256>>>(src, dst, out);
}

// round 4
// speedup vs baseline: 1.2959x; 1.2959x over previous
#include <cuda_runtime.h>
#include <cuda_bf16.h>

#define N_NODES 50000
#define N_EDGES 800000
#define HEADS 8
#define DOUT 32
#define HD 256          // HEADS*DOUT == IN_FEATS == 256
#define NEG_SLOPE 0.2f

// ---------------- scratch (static device globals; no allocation) -------------
__device__ float g_h [N_NODES * HD];      // projected node features (N,256)
__device__ float g_el[N_NODES * HEADS];
__device__ float g_er[N_NODES * HEADS];
__device__ float g_s [N_NODES * HEADS];
__device__ float g_P [N_EDGES * HEADS];
__device__ float g_C [HEADS * HEADS];     // folded W_e * attn_e (k-major)

__device__ __nv_bfloat16 g_Ahi[N_NODES * HD];   // feat split hi
__device__ __nv_bfloat16 g_Alo[N_NODES * HD];   // feat split lo
__device__ __nv_bfloat16 g_Bhi[HD * HD];        // W_src^T split hi  [n][k]
__device__ __nv_bfloat16 g_Blo[HD * HD];        // W_src^T split lo  [n][k]

// ---------------- K0: fold W_e (8,256) with attn_e (8,32) -> C (8,8) ---------
__global__ void k0_foldC(const float* __restrict__ W_e, const float* __restrict__ attn_e) {
    int t = threadIdx.x;
    if (t < 64) {
        int k = t >> 3, h = t & 7;
        float s = 0.f;
        #pragma unroll
        for (int d = 0; d < DOUT; ++d)
            s += W_e[k * HD + h * DOUT + d] * attn_e[h * DOUT + d];
        g_C[k * 8 + h] = s;
    }
}

// ---------------- conv A: feat f32 -> hi/lo bf16 ------------------------------
__global__ __launch_bounds__(256) void kconvA(const float* __restrict__ A) {
    long i = ((long)blockIdx.x * 256 + threadIdx.x) * 4;
    if (i >= (long)N_NODES * HD) return;
    float4 v = *(const float4*)(A + i);
    __nv_bfloat16 h0 = __float2bfloat16(v.x);
    __nv_bfloat16 h1 = __float2bfloat16(v.y);
    __nv_bfloat16 h2 = __float2bfloat16(v.z);
    __nv_bfloat16 h3 = __float2bfloat16(v.w);
    __nv_bfloat16 l0 = __float2bfloat16(v.x - __bfloat162float(h0));
    __nv_bfloat16 l1 = __float2bfloat16(v.y - __bfloat162float(h1));
    __nv_bfloat16 l2 = __float2bfloat16(v.z - __bfloat162float(h2));
    __nv_bfloat16 l3 = __float2bfloat16(v.w - __bfloat162float(h3));
    ((__nv_bfloat162*)(g_Ahi + i))[0] = __nv_bfloat162(h0, h1);
    ((__nv_bfloat162*)(g_Ahi + i))[1] = __nv_bfloat162(h2, h3);
    ((__nv_bfloat162*)(g_Alo + i))[0] = __nv_bfloat162(l0, l1);
    ((__nv_bfloat162*)(g_Alo + i))[1] = __nv_bfloat162(l2, l3);
}

// ---------------- conv B: W_src f32 [k][n] -> hi/lo bf16 transposed [n][k] ---
__global__ void kconvB(const float* __restrict__ B) {
    int k = blockIdx.x;          // 0..255
    int n = threadIdx.x;         // 0..255
    float v = B[k * HD + n];
    __nv_bfloat16 h = __float2bfloat16(v);
    __nv_bfloat16 l = __float2bfloat16(v - __bfloat162float(h));
    g_Bhi[n * HD + k] = h;
    g_Blo[n * HD + k] = l;
}

// ---------------- cp.async helpers -------------------------------------------
__device__ __forceinline__ void cp16(unsigned dst, const void* src, bool pred) {
    asm volatile("cp.async.cg.shared.global [%0], [%1], 16, %2;"
                 :: "r"(dst), "l"(src), "r"(pred ? 16 : 0));
}
__device__ __forceinline__ void cp_commit() {
    asm volatile("cp.async.commit_group;");
}
template <int N> __device__ __forceinline__ void cp_wait() {
    asm volatile("cp.async.wait_group %0;" :: "n"(N));
}

__device__ __forceinline__ void mma16816(float* c, const unsigned* a,
                                         unsigned b0, unsigned b1) {
    asm volatile("mma.sync.aligned.m16n8k16.row.col.f32.bf16.bf16.f32 "
                 "{%0,%1,%2,%3}, {%4,%5,%6,%7}, {%8,%9}, {%0,%1,%2,%3};"
                 : "+f"(c[0]), "+f"(c[1]), "+f"(c[2]), "+f"(c[3])
                 : "r"(a[0]), "r"(a[1]), "r"(a[2]), "r"(a[3]), "r"(b0), "r"(b1));
}

// ---------------- K1: split-bf16 tensor-core GEMM  g_h = feat @ W_src --------
// CTA tile 128x128, BK=16, 8 warps (4x2), warp tile 32x64.
// smem stride 24 bf16 (48B): 16B-aligned chunks + conflict-free frag LDS.
#define BKS 24
__global__ __launch_bounds__(256) void k1_mma() {
    __shared__ __nv_bfloat16 sm[2][4][128 * BKS];   // [stage][Ahi,Alo,Bhi,Blo]

    const int t    = threadIdx.x;
    const int warp = t >> 5;
    const int lane = t & 31;
    const int wm   = warp >> 1;          // 0..3  -> m offset wm*32
    const int wn   = warp & 1;           // 0..1  -> n offset wn*64
    const int bm   = blockIdx.x * 128;
    const int bn   = blockIdx.y * 128;

    // per-thread load slot: one 16B chunk per array per tile
    const int lr = t >> 1;               // row 0..127
    const int lc = (t & 1) * 8;          // k element 0 or 8
    const bool arow_ok = (bm + lr) < N_NODES;
    const long a_goff  = (long)(bm + lr) * HD + lc;
    const long b_goff  = (long)(bn + lr) * HD + lc;
    const unsigned s_off = (unsigned)((lr * BKS + lc) * sizeof(__nv_bfloat16));

    unsigned sbase[2][4];
    #pragma unroll
    for (int s = 0; s < 2; ++s)
        #pragma unroll
        for (int a = 0; a < 4; ++a)
            sbase[s][a] = (unsigned)__cvta_generic_to_shared(&sm[s][a][0]);

    float acc[2][8][4];
    #pragma unroll
    for (int i = 0; i < 2; ++i)
        #pragma unroll
        for (int j = 0; j < 8; ++j)
            #pragma unroll
            for (int q = 0; q < 4; ++q) acc[i][j][q] = 0.f;

    // prologue: tile 0
    {
        cp16(sbase[0][0] + s_off, g_Ahi + a_goff, arow_ok);
        cp16(sbase[0][1] + s_off, g_Alo + a_goff, arow_ok);
        cp16(sbase[0][2] + s_off, g_Bhi + b_goff, true);
        cp16(sbase[0][3] + s_off, g_Blo + b_goff, true);
        cp_commit();
    }

    const int qr = lane >> 2;            // 0..7
    const int qc = (lane & 3) * 2;       // 0,2,4,6

    #pragma unroll 1
    for (int tile = 0; tile < 16; ++tile) {
        if (tile < 15) {
            int st = (tile + 1) & 1;
            int k0 = (tile + 1) * 16;
            cp16(sbase[st][0] + s_off, g_Ahi + a_goff + k0, arow_ok);
            cp16(sbase[st][1] + s_off, g_Alo + a_goff + k0, arow_ok);
            cp16(sbase[st][2] + s_off, g_Bhi + b_goff + k0, true);
            cp16(sbase[st][3] + s_off, g_Blo + b_goff + k0, true);
            cp_commit();
            cp_wait<1>();
        } else {
            cp_wait<0>();
        }
        __syncthreads();

        const int st = tile & 1;
        const __nv_bfloat16* Ah = sm[st][0];
        const __nv_bfloat16* Al = sm[st][1];
        const __nv_bfloat16* Bh = sm[st][2];
        const __nv_bfloat16* Bl = sm[st][3];

        unsigned ah[2][4], al[2][4];
        #pragma unroll
        for (int mt = 0; mt < 2; ++mt) {
            int r = wm * 32 + mt * 16 + qr;
            ah[mt][0] = *(const unsigned*)(Ah + r * BKS + qc);
            ah[mt][1] = *(const unsigned*)(Ah + (r + 8) * BKS + qc);
            ah[mt][2] = *(const unsigned*)(Ah + r * BKS + qc + 8);
            ah[mt][3] = *(const unsigned*)(Ah + (r + 8) * BKS + qc + 8);
            al[mt][0] = *(const unsigned*)(Al + r * BKS + qc);
            al[mt][1] = *(const unsigned*)(Al + (r + 8) * BKS + qc);
            al[mt][2] = *(const unsigned*)(Al + r * BKS + qc + 8);
            al[mt][3] = *(const unsigned*)(Al + (r + 8) * BKS + qc + 8);
        }

        #pragma unroll
        for (int nt = 0; nt < 8; ++nt) {
            int n = wn * 64 + nt * 8 + qr;
            unsigned bh0 = *(const unsigned*)(Bh + n * BKS + qc);
            unsigned bh1 = *(const unsigned*)(Bh + n * BKS + qc + 8);
            unsigned bl0 = *(const unsigned*)(Bl + n * BKS + qc);
            unsigned bl1 = *(const unsigned*)(Bl + n * BKS + qc + 8);
            #pragma unroll
            for (int mt = 0; mt < 2; ++mt) {
                mma16816(acc[mt][nt], ah[mt], bh0, bh1);   // hi*hi
                mma16816(acc[mt][nt], ah[mt], bl0, bl1);   // hi*lo
                mma16816(acc[mt][nt], al[mt], bh0, bh1);   // lo*hi
            }
        }
        __syncthreads();
    }

    // epilogue: write f32 result
    #pragma unroll
    for (int mt = 0; mt < 2; ++mt) {
        int r0 = bm + wm * 32 + mt * 16 + qr;
        #pragma unroll
        for (int nt = 0; nt < 8; ++nt) {
            int cc = bn + wn * 64 + nt * 8 + qc;
            if (r0 < N_NODES)
                *(float2*)(g_h + (long)r0 * HD + cc) =
                    make_float2(acc[mt][nt][0], acc[mt][nt][1]);
            if (r0 + 8 < N_NODES)
                *(float2*)(g_h + (long)(r0 + 8) * HD + cc) =
                    make_float2(acc[mt][nt][2], acc[mt][nt][3]);
        }
    }
}

// ---------------- K2: per-node el/er, zero s, out = bias ---------------------
__global__ __launch_bounds__(256) void k2_node(const float* __restrict__ attn_l,
                                               const float* __restrict__ attn_r,
                                               const float* __restrict__ bias,
                                               float* __restrict__ out) {
    __shared__ float sal[HD], sar[HD], sb[HD];
    int t = threadIdx.x;
    sal[t] = attn_l[t];
    sar[t] = attn_r[t];
    sb[t]  = bias[t];
    __syncthreads();

    int warp = t >> 5, lane = t & 31;
    int n = blockIdx.x * 8 + warp;
    if (n >= N_NODES) return;

    const float4* hp = (const float4*)(g_h + (long)n * HD);
    float4 v0 = hp[lane * 2], v1 = hp[lane * 2 + 1];
    float4 a0 = ((const float4*)sal)[lane * 2], a1 = ((const float4*)sal)[lane * 2 + 1];
    float4 r0 = ((const float4*)sar)[lane * 2], r1 = ((const float4*)sar)[lane * 2 + 1];

    float el = v0.x*a0.x + v0.y*a0.y + v0.z*a0.z + v0.w*a0.w
             + v1.x*a1.x + v1.y*a1.y + v1.z*a1.z + v1.w*a1.w;
    float er = v0.x*r0.x + v0.y*r0.y + v0.z*r0.z + v0.w*r0.w
             + v1.x*r1.x + v1.y*r1.y + v1.z*r1.z + v1.w*r1.w;
    el += __shfl_xor_sync(0xffffffffu, el, 1);
    el += __shfl_xor_sync(0xffffffffu, el, 2);
    er += __shfl_xor_sync(0xffffffffu, er, 1);
    er += __shfl_xor_sync(0xffffffffu, er, 2);
    if ((lane & 3) == 0) {
        g_el[n * HEADS + (lane >> 2)] = el;
        g_er[n * HEADS + (lane >> 2)] = er;
    }
    if (lane < HEADS) g_s[n * HEADS + lane] = 0.f;

    float4* op = (float4*)(out + (long)n * HD);
    op[lane * 2]     = ((const float4*)sb)[lane * 2];
    op[lane * 2 + 1] = ((const float4*)sb)[lane * 2 + 1];
}

// ---------------- K3: per-edge p = exp(leakyrelu(el+er+ee)); s += p ----------
__global__ __launch_bounds__(256) void k3_edge(const float* __restrict__ edge_emb,
                                               const int* __restrict__ src,
                                               const int* __restrict__ dst) {
    __shared__ float Cs[64];
    int t = threadIdx.x;
    if (t < 64) Cs[t] = g_C[t];
    __syncthreads();

    int e = blockIdx.x * blockDim.x + t;
    if (e >= N_EDGES) return;

    int se = src[e], de = dst[e];
    const float4* ep = (const float4*)(edge_emb + (long)e * HEADS);
    float4 e0 = ep[0], e1 = ep[1];
    float ein[8] = {e0.x, e0.y, e0.z, e0.w, e1.x, e1.y, e1.z, e1.w};

    float4 l0 = *(const float4*)(g_el + se * HEADS);
    float4 l1 = *(const float4*)(g_el + se * HEADS + 4);
    float4 r0 = *(const float4*)(g_er + de * HEADS);
    float4 r1 = *(const float4*)(g_er + de * HEADS + 4);
    float elv[8] = {l0.x, l0.y, l0.z, l0.w, l1.x, l1.y, l1.z, l1.w};
    float erv[8] = {r0.x, r0.y, r0.z, r0.w, r1.x, r1.y, r1.z, r1.w};

    float pv[8];
    #pragma unroll
    for (int h = 0; h < 8; ++h) {
        float ee = 0.f;
        #pragma unroll
        for (int k = 0; k < 8; ++k) ee += ein[k] * Cs[k * 8 + h];
        float x = elv[h] + erv[h] + ee;
        x = (x > 0.f) ? x : NEG_SLOPE * x;
        float p = __expf(x);
        pv[h] = p;
        atomicAdd(&g_s[de * HEADS + h], p);
    }
    float4* pp = (float4*)(g_P + (long)e * HEADS);
    pp[0] = make_float4(pv[0], pv[1], pv[2], pv[3]);
    pp[1] = make_float4(pv[4], pv[5], pv[6], pv[7]);
}

// ---------------- K4: weighted aggregation via vector reductions -------------
__device__ __forceinline__ void red_add_v4(float* addr, float a, float b, float c, float d) {
    asm volatile("red.global.add.v4.f32 [%0], {%1, %2, %3, %4};"
                 :: "l"(addr), "f"(a), "f"(b), "f"(c), "f"(d) : "memory");
}

__global__ __launch_bounds__(256) void k4_agg(const int* __restrict__ src,
                                              const int* __restrict__ dst,
                                              float* __restrict__ out) {
    int t = threadIdx.x, warp = t >> 5, lane = t & 31;
    int e = blockIdx.x * 8 + warp;
    if (e >= N_EDGES) return;

    int se = __ldg(&src[e]);
    int de = __ldg(&dst[e]);

    float a = 0.f;
    if (lane < HEADS)
        a = g_P[(long)e * HEADS + lane] / (g_s[de * HEADS + lane] + 1e-9f);
    float alpha = __shfl_sync(0xffffffffu, a, lane >> 2);

    const float4* hp = (const float4*)(g_h + (long)se * HD);
    float4 x = hp[lane * 2];
    float4 y = hp[lane * 2 + 1];

    float* op = out + (long)de * HD + lane * 8;
    red_add_v4(op,     alpha * x.x, alpha * x.y, alpha * x.z, alpha * x.w);
    red_add_v4(op + 4, alpha * y.x, alpha * y.y, alpha * y.z, alpha * y.w);
}

// ---------------- launch ------------------------------------------------------
extern "C" void kernel_launch(void* const* d_in, const int* in_sizes, int n_in,
                              void* d_out, int out_size) {
    const float* feat     = (const float*)d_in[0];
    const float* edge_emb = (const float*)d_in[1];
    const int*   src      = (const int*)  d_in[2];
    const int*   dst      = (const int*)  d_in[3];
    const float* W_src    = (const float*)d_in[4];
    const float* W_e      = (const float*)d_in[5];
    const float* attn_l   = (const float*)d_in[6];
    const float* attn_r   = (const float*)d_in[7];
    const float* attn_e   = (const float*)d_in[8];
    const float* bias     = (const float*)d_in[9];
    float* out = (float*)d_out;

    k0_foldC<<<1, 64>>>(W_e, attn_e);

    kconvA<<<(N_NODES * HD / 4 + 255) / 256, 256>>>(feat);
    kconvB<<<HD, HD>>>(W_src);

    dim3 g1((N_NODES + 127) / 128, 2);
    k1_mma<<<g1, 256>>>();

    k2_node<<<(N_NODES + 7) / 8, 256>>>(attn_l, attn_r, bias, out);

    k3_edge<<<(N_EDGES + 255) / 256, 256>>>(edge_emb, src, dst);

    k4_agg<<<(N_EDGES + 7) / 8, 256>>>(src, dst, out);
}

// round 5
// speedup vs baseline: 1.6371x; 1.2633x over previous
#include <cuda_runtime.h>
#include <cuda_bf16.h>

#define N_NODES 50000
#define N_EDGES 800000
#define HEADS 8
#define DOUT 32
#define HD 256          // HEADS*DOUT == IN_FEATS == 256
#define NEG_SLOPE 0.2f

// ---------------- scratch (static device globals; no allocation) -------------
__device__ float g_h [N_NODES * HD];      // projected node features (N,256)
__device__ float g_el[N_NODES * HEADS];
__device__ float g_er[N_NODES * HEADS];
__device__ float g_C [HEADS * HEADS];     // folded W_e * attn_e (k-major)

__device__ __nv_bfloat16 g_Ahi[N_NODES * HD];   // feat split hi
__device__ __nv_bfloat16 g_Alo[N_NODES * HD];   // feat split lo
__device__ __nv_bfloat16 g_Bhi[HD * HD];        // W_src^T split hi  [n][k]
__device__ __nv_bfloat16 g_Blo[HD * HD];        // W_src^T split lo  [n][k]

// CSR-by-dst scratch
__device__ int g_cnt  [N_NODES];          // in-degree
__device__ int g_start[N_NODES];          // exclusive prefix
__device__ int g_cur  [N_NODES];          // scatter cursors
__device__ int g_order[N_EDGES];          // edge ids grouped by dst

// ---------------- K0: fold W_e (8,256) with attn_e (8,32) -> C (8,8) ---------
__global__ void k0_foldC(const float* __restrict__ W_e, const float* __restrict__ attn_e) {
    int t = threadIdx.x;
    if (t < 64) {
        int k = t >> 3, h = t & 7;
        float s = 0.f;
        #pragma unroll
        for (int d = 0; d < DOUT; ++d)
            s += W_e[k * HD + h * DOUT + d] * attn_e[h * DOUT + d];
        g_C[k * 8 + h] = s;
    }
}

// ---------------- conv A: feat f32 -> hi/lo bf16 ------------------------------
__global__ __launch_bounds__(256) void kconvA(const float* __restrict__ A) {
    long i = ((long)blockIdx.x * 256 + threadIdx.x) * 4;
    if (i >= (long)N_NODES * HD) return;
    float4 v = *(const float4*)(A + i);
    __nv_bfloat16 h0 = __float2bfloat16(v.x);
    __nv_bfloat16 h1 = __float2bfloat16(v.y);
    __nv_bfloat16 h2 = __float2bfloat16(v.z);
    __nv_bfloat16 h3 = __float2bfloat16(v.w);
    __nv_bfloat16 l0 = __float2bfloat16(v.x - __bfloat162float(h0));
    __nv_bfloat16 l1 = __float2bfloat16(v.y - __bfloat162float(h1));
    __nv_bfloat16 l2 = __float2bfloat16(v.z - __bfloat162float(h2));
    __nv_bfloat16 l3 = __float2bfloat16(v.w - __bfloat162float(h3));
    ((__nv_bfloat162*)(g_Ahi + i))[0] = __nv_bfloat162(h0, h1);
    ((__nv_bfloat162*)(g_Ahi + i))[1] = __nv_bfloat162(h2, h3);
    ((__nv_bfloat162*)(g_Alo + i))[0] = __nv_bfloat162(l0, l1);
    ((__nv_bfloat162*)(g_Alo + i))[1] = __nv_bfloat162(l2, l3);
}

// ---------------- conv B: W_src f32 [k][n] -> hi/lo bf16 transposed [n][k] ---
__global__ void kconvB(const float* __restrict__ B) {
    int k = blockIdx.x;          // 0..255
    int n = threadIdx.x;         // 0..255
    float v = B[k * HD + n];
    __nv_bfloat16 h = __float2bfloat16(v);
    __nv_bfloat16 l = __float2bfloat16(v - __bfloat162float(h));
    g_Bhi[n * HD + k] = h;
    g_Blo[n * HD + k] = l;
}

// ---------------- cp.async helpers -------------------------------------------
__device__ __forceinline__ void cp16(unsigned dst, const void* src, bool pred) {
    asm volatile("cp.async.cg.shared.global [%0], [%1], 16, %2;"
                 :: "r"(dst), "l"(src), "r"(pred ? 16 : 0));
}
__device__ __forceinline__ void cp_commit() {
    asm volatile("cp.async.commit_group;");
}
template <int N> __device__ __forceinline__ void cp_wait() {
    asm volatile("cp.async.wait_group %0;" :: "n"(N));
}

__device__ __forceinline__ void mma16816(float* c, const unsigned* a,
                                         unsigned b0, unsigned b1) {
    asm volatile("mma.sync.aligned.m16n8k16.row.col.f32.bf16.bf16.f32 "
                 "{%0,%1,%2,%3}, {%4,%5,%6,%7}, {%8,%9}, {%0,%1,%2,%3};"
                 : "+f"(c[0]), "+f"(c[1]), "+f"(c[2]), "+f"(c[3])
                 : "r"(a[0]), "r"(a[1]), "r"(a[2]), "r"(a[3]), "r"(b0), "r"(b1));
}

// ---------------- K1: split-bf16 tensor-core GEMM  g_h = feat @ W_src --------
#define BKS 24
__global__ __launch_bounds__(256) void k1_mma() {
    __shared__ __nv_bfloat16 sm[2][4][128 * BKS];   // [stage][Ahi,Alo,Bhi,Blo]

    const int t    = threadIdx.x;
    const int warp = t >> 5;
    const int lane = t & 31;
    const int wm   = warp >> 1;
    const int wn   = warp & 1;
    const int bm   = blockIdx.x * 128;
    const int bn   = blockIdx.y * 128;

    const int lr = t >> 1;
    const int lc = (t & 1) * 8;
    const bool arow_ok = (bm + lr) < N_NODES;
    const long a_goff  = (long)(bm + lr) * HD + lc;
    const long b_goff  = (long)(bn + lr) * HD + lc;
    const unsigned s_off = (unsigned)((lr * BKS + lc) * sizeof(__nv_bfloat16));

    unsigned sbase[2][4];
    #pragma unroll
    for (int s = 0; s < 2; ++s)
        #pragma unroll
        for (int a = 0; a < 4; ++a)
            sbase[s][a] = (unsigned)__cvta_generic_to_shared(&sm[s][a][0]);

    float acc[2][8][4];
    #pragma unroll
    for (int i = 0; i < 2; ++i)
        #pragma unroll
        for (int j = 0; j < 8; ++j)
            #pragma unroll
            for (int q = 0; q < 4; ++q) acc[i][j][q] = 0.f;

    {
        cp16(sbase[0][0] + s_off, g_Ahi + a_goff, arow_ok);
        cp16(sbase[0][1] + s_off, g_Alo + a_goff, arow_ok);
        cp16(sbase[0][2] + s_off, g_Bhi + b_goff, true);
        cp16(sbase[0][3] + s_off, g_Blo + b_goff, true);
        cp_commit();
    }

    const int qr = lane >> 2;
    const int qc = (lane & 3) * 2;

    #pragma unroll 1
    for (int tile = 0; tile < 16; ++tile) {
        if (tile < 15) {
            int st = (tile + 1) & 1;
            int k0 = (tile + 1) * 16;
            cp16(sbase[st][0] + s_off, g_Ahi + a_goff + k0, arow_ok);
            cp16(sbase[st][1] + s_off, g_Alo + a_goff + k0, arow_ok);
            cp16(sbase[st][2] + s_off, g_Bhi + b_goff + k0, true);
            cp16(sbase[st][3] + s_off, g_Blo + b_goff + k0, true);
            cp_commit();
            cp_wait<1>();
        } else {
            cp_wait<0>();
        }
        __syncthreads();

        const int st = tile & 1;
        const __nv_bfloat16* Ah = sm[st][0];
        const __nv_bfloat16* Al = sm[st][1];
        const __nv_bfloat16* Bh = sm[st][2];
        const __nv_bfloat16* Bl = sm[st][3];

        unsigned ah[2][4], al[2][4];
        #pragma unroll
        for (int mt = 0; mt < 2; ++mt) {
            int r = wm * 32 + mt * 16 + qr;
            ah[mt][0] = *(const unsigned*)(Ah + r * BKS + qc);
            ah[mt][1] = *(const unsigned*)(Ah + (r + 8) * BKS + qc);
            ah[mt][2] = *(const unsigned*)(Ah + r * BKS + qc + 8);
            ah[mt][3] = *(const unsigned*)(Ah + (r + 8) * BKS + qc + 8);
            al[mt][0] = *(const unsigned*)(Al + r * BKS + qc);
            al[mt][1] = *(const unsigned*)(Al + (r + 8) * BKS + qc);
            al[mt][2] = *(const unsigned*)(Al + r * BKS + qc + 8);
            al[mt][3] = *(const unsigned*)(Al + (r + 8) * BKS + qc + 8);
        }

        #pragma unroll
        for (int nt = 0; nt < 8; ++nt) {
            int n = wn * 64 + nt * 8 + qr;
            unsigned bh0 = *(const unsigned*)(Bh + n * BKS + qc);
            unsigned bh1 = *(const unsigned*)(Bh + n * BKS + qc + 8);
            unsigned bl0 = *(const unsigned*)(Bl + n * BKS + qc);
            unsigned bl1 = *(const unsigned*)(Bl + n * BKS + qc + 8);
            #pragma unroll
            for (int mt = 0; mt < 2; ++mt) {
                mma16816(acc[mt][nt], ah[mt], bh0, bh1);
                mma16816(acc[mt][nt], ah[mt], bl0, bl1);
                mma16816(acc[mt][nt], al[mt], bh0, bh1);
            }
        }
        __syncthreads();
    }

    #pragma unroll
    for (int mt = 0; mt < 2; ++mt) {
        int r0 = bm + wm * 32 + mt * 16 + qr;
        #pragma unroll
        for (int nt = 0; nt < 8; ++nt) {
            int cc = bn + wn * 64 + nt * 8 + qc;
            if (r0 < N_NODES)
                *(float2*)(g_h + (long)r0 * HD + cc) =
                    make_float2(acc[mt][nt][0], acc[mt][nt][1]);
            if (r0 + 8 < N_NODES)
                *(float2*)(g_h + (long)(r0 + 8) * HD + cc) =
                    make_float2(acc[mt][nt][2], acc[mt][nt][3]);
        }
    }
}

// ---------------- K2: per-node el/er ------------------------------------------
__global__ __launch_bounds__(256) void k2_node(const float* __restrict__ attn_l,
                                               const float* __restrict__ attn_r) {
    __shared__ float sal[HD], sar[HD];
    int t = threadIdx.x;
    sal[t] = attn_l[t];
    sar[t] = attn_r[t];
    __syncthreads();

    int warp = t >> 5, lane = t & 31;
    int n = blockIdx.x * 8 + warp;
    if (n >= N_NODES) return;

    const float4* hp = (const float4*)(g_h + (long)n * HD);
    float4 v0 = hp[lane * 2], v1 = hp[lane * 2 + 1];
    float4 a0 = ((const float4*)sal)[lane * 2], a1 = ((const float4*)sal)[lane * 2 + 1];
    float4 r0 = ((const float4*)sar)[lane * 2], r1 = ((const float4*)sar)[lane * 2 + 1];

    float el = v0.x*a0.x + v0.y*a0.y + v0.z*a0.z + v0.w*a0.w
             + v1.x*a1.x + v1.y*a1.y + v1.z*a1.z + v1.w*a1.w;
    float er = v0.x*r0.x + v0.y*r0.y + v0.z*r0.z + v0.w*r0.w
             + v1.x*r1.x + v1.y*r1.y + v1.z*r1.z + v1.w*r1.w;
    el += __shfl_xor_sync(0xffffffffu, el, 1);
    el += __shfl_xor_sync(0xffffffffu, el, 2);
    er += __shfl_xor_sync(0xffffffffu, er, 1);
    er += __shfl_xor_sync(0xffffffffu, er, 2);
    if ((lane & 3) == 0) {
        g_el[n * HEADS + (lane >> 2)] = el;
        g_er[n * HEADS + (lane >> 2)] = er;
    }
}

// ---------------- CSR build ----------------------------------------------------
__global__ void kzero() {
    int i = blockIdx.x * 256 + threadIdx.x;
    if (i < N_NODES) g_cnt[i] = 0;
}

__global__ void khist(const int* __restrict__ dst) {
    int e = blockIdx.x * 256 + threadIdx.x;
    if (e < N_EDGES) atomicAdd(&g_cnt[dst[e]], 1);
}

// single block, 1024 threads: exclusive scan of g_cnt -> g_start, g_cur
__global__ __launch_bounds__(1024) void kscan() {
    __shared__ int wsum[32];
    __shared__ int run;
    int t = threadIdx.x, lane = t & 31, w = t >> 5;
    if (t == 0) run = 0;
    __syncthreads();
    for (int base = 0; base < N_NODES; base += 1024) {
        int i = base + t;
        int v = (i < N_NODES) ? g_cnt[i] : 0;
        int sv = v;
        #pragma unroll
        for (int d = 1; d < 32; d <<= 1) {
            int x = __shfl_up_sync(0xffffffffu, sv, d);
            if (lane >= d) sv += x;
        }
        if (lane == 31) wsum[w] = sv;
        __syncthreads();
        if (w == 0) {
            int ws = wsum[lane];
            #pragma unroll
            for (int d = 1; d < 32; d <<= 1) {
                int x = __shfl_up_sync(0xffffffffu, ws, d);
                if (lane >= d) ws += x;
            }
            wsum[lane] = ws;
        }
        __syncthreads();
        int excl = sv - v + ((w > 0) ? wsum[w - 1] : 0);
        if (i < N_NODES) {
            g_start[i] = run + excl;
            g_cur[i]   = run + excl;
        }
        __syncthreads();
        if (t == 1023) run += wsum[31];
        __syncthreads();
    }
}

__global__ void kscatter(const int* __restrict__ dst) {
    int e = blockIdx.x * 256 + threadIdx.x;
    if (e >= N_EDGES) return;
    int pos = atomicAdd(&g_cur[dst[e]], 1);
    g_order[pos] = e;
}

// ---------------- K4f: fused softmax + aggregation, one warp per dst node ----
__global__ __launch_bounds__(256) void k4f(const float* __restrict__ edge_emb,
                                           const int* __restrict__ src,
                                           const float* __restrict__ bias,
                                           float* __restrict__ out) {
    __shared__ float Cs[64];
    __shared__ float sb[HD];
    int t = threadIdx.x;
    if (t < 64) Cs[t] = g_C[t];
    sb[t] = bias[t];
    __syncthreads();

    int warp = t >> 5, lane = t & 31;
    int node = blockIdx.x * 8 + warp;
    if (node >= N_NODES) return;

    int beg = g_start[node];
    int deg = g_cnt[node];

    float er_h = 0.f;
    float c0[8];
    if (lane < HEADS) {
        er_h = g_er[node * HEADS + lane];
        #pragma unroll
        for (int k = 0; k < 8; ++k) c0[k] = Cs[k * 8 + lane];   // column for my head
    }

    float acc[8] = {0.f, 0.f, 0.f, 0.f, 0.f, 0.f, 0.f, 0.f};
    float s = 0.f;

    for (int j = beg; j < beg + deg; ++j) {
        int e  = g_order[j];                     // lane-uniform
        int se = src[e];                         // lane-uniform

        float p = 0.f;
        if (lane < HEADS) {
            float el = g_el[se * HEADS + lane];
            const float4* ep = (const float4*)(edge_emb + (long)e * HEADS);
            float4 e0 = ep[0], e1 = ep[1];
            float ee = e0.x * c0[0] + e0.y * c0[1] + e0.z * c0[2] + e0.w * c0[3]
                     + e1.x * c0[4] + e1.y * c0[5] + e1.z * c0[6] + e1.w * c0[7];
            float x = el + er_h + ee;
            x = (x > 0.f) ? x : NEG_SLOPE * x;
            p = __expf(x);
            s += p;
        }
        float alpha = __shfl_sync(0xffffffffu, p, lane >> 2);

        const float4* hp = (const float4*)(g_h + (long)se * HD);
        float4 x0 = hp[lane * 2];
        float4 x1 = hp[lane * 2 + 1];
        acc[0] += alpha * x0.x; acc[1] += alpha * x0.y;
        acc[2] += alpha * x0.z; acc[3] += alpha * x0.w;
        acc[4] += alpha * x1.x; acc[5] += alpha * x1.y;
        acc[6] += alpha * x1.z; acc[7] += alpha * x1.w;
    }

    float sh  = __shfl_sync(0xffffffffu, s, lane >> 2);
    float inv = 1.f / (sh + 1e-9f);

    float* op = out + (long)node * HD + lane * 8;
    const float* bp = sb + lane * 8;
    *(float4*)(op)     = make_float4(acc[0] * inv + bp[0], acc[1] * inv + bp[1],
                                     acc[2] * inv + bp[2], acc[3] * inv + bp[3]);
    *(float4*)(op + 4) = make_float4(acc[4] * inv + bp[4], acc[5] * inv + bp[5],
                                     acc[6] * inv + bp[6], acc[7] * inv + bp[7]);
}

// ---------------- launch ------------------------------------------------------
extern "C" void kernel_launch(void* const* d_in, const int* in_sizes, int n_in,
                              void* d_out, int out_size) {
    const float* feat     = (const float*)d_in[0];
    const float* edge_emb = (const float*)d_in[1];
    const int*   src      = (const int*)  d_in[2];
    const int*   dst      = (const int*)  d_in[3];
    const float* W_src    = (const float*)d_in[4];
    const float* W_e      = (const float*)d_in[5];
    const float* attn_l   = (const float*)d_in[6];
    const float* attn_r   = (const float*)d_in[7];
    const float* attn_e   = (const float*)d_in[8];
    const float* bias     = (const float*)d_in[9];
    float* out = (float*)d_out;

    // CSR build first (independent of GEMM)
    kzero   <<<(N_NODES + 255) / 256, 256>>>();
    khist   <<<(N_EDGES + 255) / 256, 256>>>(dst);
    kscan   <<<1, 1024>>>();
    kscatter<<<(N_EDGES + 255) / 256, 256>>>(dst);

    k0_foldC<<<1, 64>>>(W_e, attn_e);
    kconvA<<<(N_NODES * HD / 4 + 255) / 256, 256>>>(feat);
    kconvB<<<HD, HD>>>(W_src);

    dim3 g1((N_NODES + 127) / 128, 2);
    k1_mma<<<g1, 256>>>();

    k2_node<<<(N_NODES + 7) / 8, 256>>>(attn_l, attn_r);

    k4f<<<(N_NODES + 7) / 8, 256>>>(edge_emb, src, bias, out);
}

// round 6
// speedup vs baseline: 1.9260x; 1.1765x over previous
#include <cuda_runtime.h>
#include <cuda_bf16.h>
#include <cuda_fp16.h>

#define N_NODES 50000
#define N_EDGES 800000
#define HEADS 8
#define DOUT 32
#define HD 256          // HEADS*DOUT == IN_FEATS == 256
#define NEG_SLOPE 0.2f
#define NB_SCAN 196     // ceil(N_NODES/256)

// ---------------- scratch (static device globals; no allocation) -------------
__device__ float g_h [N_NODES * HD];      // projected node features f32
__device__ __half g_hh[N_NODES * HD];     // projected node features fp16 (for gather)
__device__ float g_el[N_NODES * HEADS];
__device__ float g_er[N_NODES * HEADS];
__device__ float g_C [HEADS * HEADS];     // folded W_e * attn_e (k-major)

__device__ __nv_bfloat16 g_Ahi[N_NODES * HD];   // feat split hi
__device__ __nv_bfloat16 g_Alo[N_NODES * HD];   // feat split lo
__device__ __nv_bfloat16 g_Bhi[HD * HD];        // W_src^T split hi  [n][k]
__device__ __nv_bfloat16 g_Blo[HD * HD];        // W_src^T split lo  [n][k]

// CSR-by-dst scratch
__device__ int g_cnt  [N_NODES];          // in-degree
__device__ int g_start[N_NODES];          // exclusive prefix
__device__ int g_cur  [N_NODES];          // scatter cursors
__device__ int g_order[N_EDGES];          // edge ids grouped by dst
__device__ int g_osrc [N_EDGES];          // src node ids grouped by dst
__device__ int g_bsum [NB_SCAN];          // scan block sums

// ---------------- K0: fold W_e (8,256) with attn_e (8,32) -> C (8,8) ---------
__global__ void k0_foldC(const float* __restrict__ W_e, const float* __restrict__ attn_e) {
    int t = threadIdx.x;
    if (t < 64) {
        int k = t >> 3, h = t & 7;
        float s = 0.f;
        #pragma unroll
        for (int d = 0; d < DOUT; ++d)
            s += W_e[k * HD + h * DOUT + d] * attn_e[h * DOUT + d];
        g_C[k * 8 + h] = s;
    }
}

// ---------------- conv A: feat f32 -> hi/lo bf16 ------------------------------
__global__ __launch_bounds__(256) void kconvA(const float* __restrict__ A) {
    long i = ((long)blockIdx.x * 256 + threadIdx.x) * 4;
    if (i >= (long)N_NODES * HD) return;
    float4 v = *(const float4*)(A + i);
    __nv_bfloat16 h0 = __float2bfloat16(v.x);
    __nv_bfloat16 h1 = __float2bfloat16(v.y);
    __nv_bfloat16 h2 = __float2bfloat16(v.z);
    __nv_bfloat16 h3 = __float2bfloat16(v.w);
    __nv_bfloat16 l0 = __float2bfloat16(v.x - __bfloat162float(h0));
    __nv_bfloat16 l1 = __float2bfloat16(v.y - __bfloat162float(h1));
    __nv_bfloat16 l2 = __float2bfloat16(v.z - __bfloat162float(h2));
    __nv_bfloat16 l3 = __float2bfloat16(v.w - __bfloat162float(h3));
    ((__nv_bfloat162*)(g_Ahi + i))[0] = __nv_bfloat162(h0, h1);
    ((__nv_bfloat162*)(g_Ahi + i))[1] = __nv_bfloat162(h2, h3);
    ((__nv_bfloat162*)(g_Alo + i))[0] = __nv_bfloat162(l0, l1);
    ((__nv_bfloat162*)(g_Alo + i))[1] = __nv_bfloat162(l2, l3);
}

// ---------------- conv B: W_src f32 [k][n] -> hi/lo bf16 transposed [n][k] ---
__global__ void kconvB(const float* __restrict__ B) {
    int k = blockIdx.x;          // 0..255
    int n = threadIdx.x;         // 0..255
    float v = B[k * HD + n];
    __nv_bfloat16 h = __float2bfloat16(v);
    __nv_bfloat16 l = __float2bfloat16(v - __bfloat162float(h));
    g_Bhi[n * HD + k] = h;
    g_Blo[n * HD + k] = l;
}

// ---------------- cp.async helpers -------------------------------------------
__device__ __forceinline__ void cp16(unsigned dst, const void* src, bool pred) {
    asm volatile("cp.async.cg.shared.global [%0], [%1], 16, %2;"
                 :: "r"(dst), "l"(src), "r"(pred ? 16 : 0));
}
__device__ __forceinline__ void cp_commit() {
    asm volatile("cp.async.commit_group;");
}
template <int N> __device__ __forceinline__ void cp_wait() {
    asm volatile("cp.async.wait_group %0;" :: "n"(N));
}

__device__ __forceinline__ void mma16816(float* c, const unsigned* a,
                                         unsigned b0, unsigned b1) {
    asm volatile("mma.sync.aligned.m16n8k16.row.col.f32.bf16.bf16.f32 "
                 "{%0,%1,%2,%3}, {%4,%5,%6,%7}, {%8,%9}, {%0,%1,%2,%3};"
                 : "+f"(c[0]), "+f"(c[1]), "+f"(c[2]), "+f"(c[3])
                 : "r"(a[0]), "r"(a[1]), "r"(a[2]), "r"(a[3]), "r"(b0), "r"(b1));
}

// ---------------- K1: split-bf16 tensor-core GEMM  g_h = feat @ W_src --------
#define BKS 24
__global__ __launch_bounds__(256) void k1_mma() {
    __shared__ __nv_bfloat16 sm[2][4][128 * BKS];   // [stage][Ahi,Alo,Bhi,Blo]

    const int t    = threadIdx.x;
    const int warp = t >> 5;
    const int lane = t & 31;
    const int wm   = warp >> 1;
    const int wn   = warp & 1;
    const int bm   = blockIdx.x * 128;
    const int bn   = blockIdx.y * 128;

    const int lr = t >> 1;
    const int lc = (t & 1) * 8;
    const bool arow_ok = (bm + lr) < N_NODES;
    const long a_goff  = (long)(bm + lr) * HD + lc;
    const long b_goff  = (long)(bn + lr) * HD + lc;
    const unsigned s_off = (unsigned)((lr * BKS + lc) * sizeof(__nv_bfloat16));

    unsigned sbase[2][4];
    #pragma unroll
    for (int s = 0; s < 2; ++s)
        #pragma unroll
        for (int a = 0; a < 4; ++a)
            sbase[s][a] = (unsigned)__cvta_generic_to_shared(&sm[s][a][0]);

    float acc[2][8][4];
    #pragma unroll
    for (int i = 0; i < 2; ++i)
        #pragma unroll
        for (int j = 0; j < 8; ++j)
            #pragma unroll
            for (int q = 0; q < 4; ++q) acc[i][j][q] = 0.f;

    {
        cp16(sbase[0][0] + s_off, g_Ahi + a_goff, arow_ok);
        cp16(sbase[0][1] + s_off, g_Alo + a_goff, arow_ok);
        cp16(sbase[0][2] + s_off, g_Bhi + b_goff, true);
        cp16(sbase[0][3] + s_off, g_Blo + b_goff, true);
        cp_commit();
    }

    const int qr = lane >> 2;
    const int qc = (lane & 3) * 2;

    #pragma unroll 1
    for (int tile = 0; tile < 16; ++tile) {
        if (tile < 15) {
            int st = (tile + 1) & 1;
            int k0 = (tile + 1) * 16;
            cp16(sbase[st][0] + s_off, g_Ahi + a_goff + k0, arow_ok);
            cp16(sbase[st][1] + s_off, g_Alo + a_goff + k0, arow_ok);
            cp16(sbase[st][2] + s_off, g_Bhi + b_goff + k0, true);
            cp16(sbase[st][3] + s_off, g_Blo + b_goff + k0, true);
            cp_commit();
            cp_wait<1>();
        } else {
            cp_wait<0>();
        }
        __syncthreads();

        const int st = tile & 1;
        const __nv_bfloat16* Ah = sm[st][0];
        const __nv_bfloat16* Al = sm[st][1];
        const __nv_bfloat16* Bh = sm[st][2];
        const __nv_bfloat16* Bl = sm[st][3];

        unsigned ah[2][4], al[2][4];
        #pragma unroll
        for (int mt = 0; mt < 2; ++mt) {
            int r = wm * 32 + mt * 16 + qr;
            ah[mt][0] = *(const unsigned*)(Ah + r * BKS + qc);
            ah[mt][1] = *(const unsigned*)(Ah + (r + 8) * BKS + qc);
            ah[mt][2] = *(const unsigned*)(Ah + r * BKS + qc + 8);
            ah[mt][3] = *(const unsigned*)(Ah + (r + 8) * BKS + qc + 8);
            al[mt][0] = *(const unsigned*)(Al + r * BKS + qc);
            al[mt][1] = *(const unsigned*)(Al + (r + 8) * BKS + qc);
            al[mt][2] = *(const unsigned*)(Al + r * BKS + qc + 8);
            al[mt][3] = *(const unsigned*)(Al + (r + 8) * BKS + qc + 8);
        }

        #pragma unroll
        for (int nt = 0; nt < 8; ++nt) {
            int n = wn * 64 + nt * 8 + qr;
            unsigned bh0 = *(const unsigned*)(Bh + n * BKS + qc);
            unsigned bh1 = *(const unsigned*)(Bh + n * BKS + qc + 8);
            unsigned bl0 = *(const unsigned*)(Bl + n * BKS + qc);
            unsigned bl1 = *(const unsigned*)(Bl + n * BKS + qc + 8);
            #pragma unroll
            for (int mt = 0; mt < 2; ++mt) {
                mma16816(acc[mt][nt], ah[mt], bh0, bh1);
                mma16816(acc[mt][nt], ah[mt], bl0, bl1);
                mma16816(acc[mt][nt], al[mt], bh0, bh1);
            }
        }
        __syncthreads();
    }

    #pragma unroll
    for (int mt = 0; mt < 2; ++mt) {
        int r0 = bm + wm * 32 + mt * 16 + qr;
        #pragma unroll
        for (int nt = 0; nt < 8; ++nt) {
            int cc = bn + wn * 64 + nt * 8 + qc;
            if (r0 < N_NODES) {
                *(float2*)(g_h + (long)r0 * HD + cc) =
                    make_float2(acc[mt][nt][0], acc[mt][nt][1]);
                *(__half2*)(g_hh + (long)r0 * HD + cc) =
                    __floats2half2_rn(acc[mt][nt][0], acc[mt][nt][1]);
            }
            if (r0 + 8 < N_NODES) {
                *(float2*)(g_h + (long)(r0 + 8) * HD + cc) =
                    make_float2(acc[mt][nt][2], acc[mt][nt][3]);
                *(__half2*)(g_hh + (long)(r0 + 8) * HD + cc) =
                    __floats2half2_rn(acc[mt][nt][2], acc[mt][nt][3]);
            }
        }
    }
}

// ---------------- K2: per-node el/er ------------------------------------------
__global__ __launch_bounds__(256) void k2_node(const float* __restrict__ attn_l,
                                               const float* __restrict__ attn_r) {
    __shared__ float sal[HD], sar[HD];
    int t = threadIdx.x;
    sal[t] = attn_l[t];
    sar[t] = attn_r[t];
    __syncthreads();

    int warp = t >> 5, lane = t & 31;
    int n = blockIdx.x * 8 + warp;
    if (n >= N_NODES) return;

    const float4* hp = (const float4*)(g_h + (long)n * HD);
    float4 v0 = hp[lane * 2], v1 = hp[lane * 2 + 1];
    float4 a0 = ((const float4*)sal)[lane * 2], a1 = ((const float4*)sal)[lane * 2 + 1];
    float4 r0 = ((const float4*)sar)[lane * 2], r1 = ((const float4*)sar)[lane * 2 + 1];

    float el = v0.x*a0.x + v0.y*a0.y + v0.z*a0.z + v0.w*a0.w
             + v1.x*a1.x + v1.y*a1.y + v1.z*a1.z + v1.w*a1.w;
    float er = v0.x*r0.x + v0.y*r0.y + v0.z*r0.z + v0.w*r0.w
             + v1.x*r1.x + v1.y*r1.y + v1.z*r1.z + v1.w*r1.w;
    el += __shfl_xor_sync(0xffffffffu, el, 1);
    el += __shfl_xor_sync(0xffffffffu, el, 2);
    er += __shfl_xor_sync(0xffffffffu, er, 1);
    er += __shfl_xor_sync(0xffffffffu, er, 2);
    if ((lane & 3) == 0) {
        g_el[n * HEADS + (lane >> 2)] = el;
        g_er[n * HEADS + (lane >> 2)] = er;
    }
}

// ---------------- CSR build ----------------------------------------------------
__global__ void khist(const int* __restrict__ dst) {
    int e = blockIdx.x * 256 + threadIdx.x;
    if (e < N_EDGES) atomicAdd(&g_cnt[dst[e]], 1);
}

// phase 1: per-block scan of 256 counts, write local-exclusive + block sum
__global__ __launch_bounds__(256) void kscan_part() {
    __shared__ int ws[8];
    int t = threadIdx.x, lane = t & 31, w = t >> 5;
    int i = blockIdx.x * 256 + t;
    int v = (i < N_NODES) ? g_cnt[i] : 0;
    int sv = v;
    #pragma unroll
    for (int d = 1; d < 32; d <<= 1) {
        int x = __shfl_up_sync(0xffffffffu, sv, d);
        if (lane >= d) sv += x;
    }
    if (lane == 31) ws[w] = sv;
    __syncthreads();
    if (t < 8) {
        int x = ws[t];
        #pragma unroll
        for (int d = 1; d < 8; d <<= 1) {
            int y = __shfl_up_sync(0xffu, x, d);
            if (t >= d) x += y;
        }
        ws[t] = x;
    }
    __syncthreads();
    int excl = sv - v + ((w > 0) ? ws[w - 1] : 0);
    if (i < N_NODES) g_start[i] = excl;
    if (t == 255) g_bsum[blockIdx.x] = ws[7];
}

// phase 2: one block scans the 196 block sums to exclusive prefixes
__global__ __launch_bounds__(256) void kscan_top() {
    __shared__ int ws[8];
    int t = threadIdx.x, lane = t & 31, w = t >> 5;
    int v = (t < NB_SCAN) ? g_bsum[t] : 0;
    int sv = v;
    #pragma unroll
    for (int d = 1; d < 32; d <<= 1) {
        int x = __shfl_up_sync(0xffffffffu, sv, d);
        if (lane >= d) sv += x;
    }
    if (lane == 31) ws[w] = sv;
    __syncthreads();
    if (t < 8) {
        int x = ws[t];
        #pragma unroll
        for (int d = 1; d < 8; d <<= 1) {
            int y = __shfl_up_sync(0xffu, x, d);
            if (t >= d) x += y;
        }
        ws[t] = x;
    }
    __syncthreads();
    int excl = sv - v + ((w > 0) ? ws[w - 1] : 0);
    if (t < NB_SCAN) g_bsum[t] = excl;
}

// phase 3: add block offsets, init cursors
__global__ __launch_bounds__(256) void kscan_add() {
    int i = blockIdx.x * 256 + threadIdx.x;
    if (i < N_NODES) {
        int s = g_start[i] + g_bsum[blockIdx.x];
        g_start[i] = s;
        g_cur[i]   = s;
    }
}

__global__ void kscatter(const int* __restrict__ src, const int* __restrict__ dst) {
    int e = blockIdx.x * 256 + threadIdx.x;
    if (e >= N_EDGES) return;
    int pos = atomicAdd(&g_cur[dst[e]], 1);
    g_order[pos] = e;
    g_osrc[pos]  = src[e];
}

// ---------------- K4f: fused softmax + aggregation, one warp per dst node ----
__global__ __launch_bounds__(256) void k4f(const float* __restrict__ edge_emb,
                                           const float* __restrict__ bias,
                                           float* __restrict__ out) {
    __shared__ float Cs[64];
    __shared__ float sb[HD];
    int t = threadIdx.x;
    if (t < 64) Cs[t] = g_C[t];
    sb[t] = bias[t];
    __syncthreads();

    int warp = t >> 5, lane = t & 31;
    int node = blockIdx.x * 8 + warp;
    if (node >= N_NODES) return;

    int beg = g_start[node];
    int deg = g_cnt[node];

    float er_h = 0.f;
    float c0[8];
    if (lane < HEADS) {
        er_h = g_er[node * HEADS + lane];
        #pragma unroll
        for (int k = 0; k < 8; ++k) c0[k] = Cs[k * 8 + lane];
    }

    float acc[8] = {0.f, 0.f, 0.f, 0.f, 0.f, 0.f, 0.f, 0.f};
    float s = 0.f;

    for (int j = beg; j < beg + deg; ++j) {
        int e  = g_order[j];                     // independent loads
        int se = g_osrc[j];

        float p = 0.f;
        if (lane < HEADS) {
            float el = g_el[se * HEADS + lane];
            const float4* ep = (const float4*)(edge_emb + (long)e * HEADS);
            float4 e0 = ep[0], e1 = ep[1];
            float ee = e0.x * c0[0] + e0.y * c0[1] + e0.z * c0[2] + e0.w * c0[3]
                     + e1.x * c0[4] + e1.y * c0[5] + e1.z * c0[6] + e1.w * c0[7];
            float x = el + er_h + ee;
            x = (x > 0.f) ? x : NEG_SLOPE * x;
            p = __expf(x);
            s += p;
        }
        float alpha = __shfl_sync(0xffffffffu, p, lane >> 2);

        // fp16 gather: 8 halves = 16 B per lane
        uint4 raw = *(const uint4*)(g_hh + (long)se * HD + lane * 8);
        float2 f0 = __half22float2(*(__half2*)&raw.x);
        float2 f1 = __half22float2(*(__half2*)&raw.y);
        float2 f2 = __half22float2(*(__half2*)&raw.z);
        float2 f3 = __half22float2(*(__half2*)&raw.w);
        acc[0] += alpha * f0.x; acc[1] += alpha * f0.y;
        acc[2] += alpha * f1.x; acc[3] += alpha * f1.y;
        acc[4] += alpha * f2.x; acc[5] += alpha * f2.y;
        acc[6] += alpha * f3.x; acc[7] += alpha * f3.y;
    }

    float sh  = __shfl_sync(0xffffffffu, s, lane >> 2);
    float inv = 1.f / (sh + 1e-9f);

    float* op = out + (long)node * HD + lane * 8;
    const float* bp = sb + lane * 8;
    *(float4*)(op)     = make_float4(acc[0] * inv + bp[0], acc[1] * inv + bp[1],
                                     acc[2] * inv + bp[2], acc[3] * inv + bp[3]);
    *(float4*)(op + 4) = make_float4(acc[4] * inv + bp[4], acc[5] * inv + bp[5],
                                     acc[6] * inv + bp[6], acc[7] * inv + bp[7]);
}

// ---------------- launch ------------------------------------------------------
extern "C" void kernel_launch(void* const* d_in, const int* in_sizes, int n_in,
                              void* d_out, int out_size) {
    const float* feat     = (const float*)d_in[0];
    const float* edge_emb = (const float*)d_in[1];
    const int*   src      = (const int*)  d_in[2];
    const int*   dst      = (const int*)  d_in[3];
    const float* W_src    = (const float*)d_in[4];
    const float* W_e      = (const float*)d_in[5];
    const float* attn_l   = (const float*)d_in[6];
    const float* attn_r   = (const float*)d_in[7];
    const float* attn_e   = (const float*)d_in[8];
    const float* bias     = (const float*)d_in[9];
    float* out = (float*)d_out;

    // CSR build
    void* cnt_ptr = nullptr;
    cudaGetSymbolAddress(&cnt_ptr, g_cnt);
    cudaMemsetAsync(cnt_ptr, 0, N_NODES * sizeof(int));
    khist     <<<(N_EDGES + 255) / 256, 256>>>(dst);
    kscan_part<<<NB_SCAN, 256>>>();
    kscan_top <<<1, 256>>>();
    kscan_add <<<NB_SCAN, 256>>>();
    kscatter  <<<(N_EDGES + 255) / 256, 256>>>(src, dst);

    k0_foldC<<<1, 64>>>(W_e, attn_e);
    kconvA<<<(N_NODES * HD / 4 + 255) / 256, 256>>>(feat);
    kconvB<<<HD, HD>>>(W_src);

    dim3 g1((N_NODES + 127) / 128, 2);
    k1_mma<<<g1, 256>>>();

    k2_node<<<(N_NODES + 7) / 8, 256>>>(attn_l, attn_r);

    k4f<<<(N_NODES + 7) / 8, 256>>>(edge_emb, bias, out);
}

// round 8
// speedup vs baseline: 2.1584x; 1.1206x over previous
#include <cuda_runtime.h>
#include <cuda_bf16.h>
#include <cuda_fp16.h>

#define N_NODES 50000
#define N_EDGES 800000
#define HEADS 8
#define DOUT 32
#define HD 256          // HEADS*DOUT == IN_FEATS == 256
#define NEG_SLOPE 0.2f
#define NB_SCAN 196     // ceil(N_NODES/256)

// ---------------- scratch (static device globals; no allocation) -------------
__device__ float g_h [N_NODES * HD];      // projected node features f32
__device__ __half g_hh[N_NODES * HD];     // projected node features fp16 (for gather)
__device__ float g_el[N_NODES * HEADS];
__device__ float g_er[N_NODES * HEADS];
__device__ float g_C [HEADS * HEADS];     // folded W_e * attn_e (k-major)

__device__ __nv_bfloat16 g_Bhi[HD * HD];  // W_src^T split hi  [n][k]
__device__ __nv_bfloat16 g_Blo[HD * HD];  // W_src^T split lo  [n][k]

// CSR-by-dst scratch
__device__ int g_cnt  [N_NODES];
__device__ int g_start[N_NODES];
__device__ int g_cur  [N_NODES];
__device__ int g_order[N_EDGES];
__device__ int g_osrc [N_EDGES];
__device__ int g_bsum [NB_SCAN];

// ---------------- K0: fold W_e (8,256) with attn_e (8,32) -> C (8,8) ---------
__global__ void k0_foldC(const float* __restrict__ W_e, const float* __restrict__ attn_e) {
    int t = threadIdx.x;
    if (t < 64) {
        int k = t >> 3, h = t & 7;
        float s = 0.f;
        #pragma unroll
        for (int d = 0; d < DOUT; ++d)
            s += W_e[k * HD + h * DOUT + d] * attn_e[h * DOUT + d];
        g_C[k * 8 + h] = s;
    }
}

// ---------------- conv B: W_src f32 [k][n] -> hi/lo bf16 transposed [n][k] ---
__global__ void kconvB(const float* __restrict__ B) {
    int k = blockIdx.x;          // 0..255
    int n = threadIdx.x;         // 0..255
    float v = B[k * HD + n];
    __nv_bfloat16 h = __float2bfloat16(v);
    __nv_bfloat16 l = __float2bfloat16(v - __bfloat162float(h));
    g_Bhi[n * HD + k] = h;
    g_Blo[n * HD + k] = l;
}

// ---------------- cp.async helpers -------------------------------------------
__device__ __forceinline__ void cp16(unsigned dst, const void* src, bool pred) {
    asm volatile("cp.async.cg.shared.global [%0], [%1], 16, %2;"
                 :: "r"(dst), "l"(src), "r"(pred ? 16 : 0));
}
__device__ __forceinline__ void cp_commit() {
    asm volatile("cp.async.commit_group;");
}
template <int N> __device__ __forceinline__ void cp_wait() {
    asm volatile("cp.async.wait_group %0;" :: "n"(N));
}

__device__ __forceinline__ void mma16816(float* c, const unsigned* a,
                                         unsigned b0, unsigned b1) {
    asm volatile("mma.sync.aligned.m16n8k16.row.col.f32.bf16.bf16.f32 "
                 "{%0,%1,%2,%3}, {%4,%5,%6,%7}, {%8,%9}, {%0,%1,%2,%3};"
                 : "+f"(c[0]), "+f"(c[1]), "+f"(c[2]), "+f"(c[3])
                 : "r"(a[0]), "r"(a[1]), "r"(a[2]), "r"(a[3]), "r"(b0), "r"(b1));
}

// truncation split of 2 consecutive f32 -> packed bf16x2 hi (exact) + lo (rn)
__device__ __forceinline__ void split2(float2 f, unsigned& hi, unsigned& lo) {
    unsigned ux = __float_as_uint(f.x), uy = __float_as_uint(f.y);
    hi = __byte_perm(ux, uy, 0x7632);                 // {hi16(y), hi16(x)}
    float hx = __uint_as_float(ux & 0xffff0000u);
    float hy = __uint_as_float(uy & 0xffff0000u);
    __nv_bfloat162 l = __floats2bfloat162_rn(f.x - hx, f.y - hy);
    lo = *(unsigned*)&l;
}

// ---------------- K1: split-bf16 tensor-core GEMM  g_h = feat @ W_src --------
// CTA 128x128, BK=16, 8 warps, warp tile 32x64. A kept f32 in smem, split in regs.
#define BKS  24      // bf16 B row stride
#define BKSF 20      // f32 A row stride
__global__ __launch_bounds__(256, 2) void k1_mma(const float* __restrict__ A) {
    __shared__ float         smA [2][128 * BKSF];   // 2 x 10.25 KB
    __shared__ __nv_bfloat16 smBh[2][128 * BKS];    // 2 x 6 KB
    __shared__ __nv_bfloat16 smBl[2][128 * BKS];    // 2 x 6 KB

    const int t    = threadIdx.x;
    const int warp = t >> 5;
    const int lane = t & 31;
    const int wm   = warp >> 1;
    const int wn   = warp & 1;
    const int bm   = blockIdx.x * 128;
    const int bn   = blockIdx.y * 128;

    const int lr = t >> 1;               // row 0..127
    const int lc = (t & 1) * 8;          // k base 0 or 8
    const bool arow_ok = (bm + lr) < N_NODES;
    const long a_goff  = (long)(bm + lr) * HD + lc;
    const long b_goff  = (long)(bn + lr) * HD + lc;
    const unsigned sA_off = (unsigned)((lr * BKSF + lc) * sizeof(float));
    const unsigned sB_off = (unsigned)((lr * BKS + lc) * sizeof(__nv_bfloat16));

    unsigned aA[2], aBh[2], aBl[2];
    #pragma unroll
    for (int s = 0; s < 2; ++s) {
        aA [s] = (unsigned)__cvta_generic_to_shared(&smA [s][0]) + sA_off;
        aBh[s] = (unsigned)__cvta_generic_to_shared(&smBh[s][0]) + sB_off;
        aBl[s] = (unsigned)__cvta_generic_to_shared(&smBl[s][0]) + sB_off;
    }

    float acc[2][8][4];
    #pragma unroll
    for (int i = 0; i < 2; ++i)
        #pragma unroll
        for (int j = 0; j < 8; ++j)
            #pragma unroll
            for (int q = 0; q < 4; ++q) acc[i][j][q] = 0.f;

    // prologue: tile 0 (A: two 16B chunks of f32; B: 16B hi + 16B lo)
    {
        cp16(aA[0],      A + a_goff,     arow_ok);
        cp16(aA[0] + 16, A + a_goff + 4, arow_ok);
        cp16(aBh[0], g_Bhi + b_goff, true);
        cp16(aBl[0], g_Blo + b_goff, true);
        cp_commit();
    }

    const int qr = lane >> 2;            // 0..7
    const int qc = (lane & 3) * 2;       // 0,2,4,6

    #pragma unroll 1
    for (int tile = 0; tile < 16; ++tile) {
        if (tile < 15) {
            int st = (tile + 1) & 1;
            int k0 = (tile + 1) * 16;
            cp16(aA[st],      A + a_goff + k0,     arow_ok);
            cp16(aA[st] + 16, A + a_goff + k0 + 4, arow_ok);
            cp16(aBh[st], g_Bhi + b_goff + k0, true);
            cp16(aBl[st], g_Blo + b_goff + k0, true);
            cp_commit();
            cp_wait<1>();
        } else {
            cp_wait<0>();
        }
        __syncthreads();

        const int st = tile & 1;
        const float* Af = smA[st];
        const __nv_bfloat16* Bh = smBh[st];
        const __nv_bfloat16* Bl = smBl[st];

        unsigned ah[2][4], al[2][4];
        #pragma unroll
        for (int mt = 0; mt < 2; ++mt) {
            int r = wm * 32 + mt * 16 + qr;
            float2 f0 = *(const float2*)(Af + r * BKSF + qc);
            float2 f1 = *(const float2*)(Af + (r + 8) * BKSF + qc);
            float2 f2 = *(const float2*)(Af + r * BKSF + qc + 8);
            float2 f3 = *(const float2*)(Af + (r + 8) * BKSF + qc + 8);
            split2(f0, ah[mt][0], al[mt][0]);
            split2(f1, ah[mt][1], al[mt][1]);
            split2(f2, ah[mt][2], al[mt][2]);
            split2(f3, ah[mt][3], al[mt][3]);
        }

        #pragma unroll
        for (int nt = 0; nt < 8; ++nt) {
            int n = wn * 64 + nt * 8 + qr;
            unsigned bh0 = *(const unsigned*)(Bh + n * BKS + qc);
            unsigned bh1 = *(const unsigned*)(Bh + n * BKS + qc + 8);
            unsigned bl0 = *(const unsigned*)(Bl + n * BKS + qc);
            unsigned bl1 = *(const unsigned*)(Bl + n * BKS + qc + 8);
            #pragma unroll
            for (int mt = 0; mt < 2; ++mt) {
                mma16816(acc[mt][nt], ah[mt], bh0, bh1);   // hi*hi
                mma16816(acc[mt][nt], ah[mt], bl0, bl1);   // hi*lo
                mma16816(acc[mt][nt], al[mt], bh0, bh1);   // lo*hi
            }
        }
        __syncthreads();
    }

    // epilogue: f32 + fp16 copies
    #pragma unroll
    for (int mt = 0; mt < 2; ++mt) {
        int r0 = bm + wm * 32 + mt * 16 + qr;
        #pragma unroll
        for (int nt = 0; nt < 8; ++nt) {
            int cc = bn + wn * 64 + nt * 8 + qc;
            if (r0 < N_NODES) {
                *(float2*)(g_h + (long)r0 * HD + cc) =
                    make_float2(acc[mt][nt][0], acc[mt][nt][1]);
                *(__half2*)(g_hh + (long)r0 * HD + cc) =
                    __floats2half2_rn(acc[mt][nt][0], acc[mt][nt][1]);
            }
            if (r0 + 8 < N_NODES) {
                *(float2*)(g_h + (long)(r0 + 8) * HD + cc) =
                    make_float2(acc[mt][nt][2], acc[mt][nt][3]);
                *(__half2*)(g_hh + (long)(r0 + 8) * HD + cc) =
                    __floats2half2_rn(acc[mt][nt][2], acc[mt][nt][3]);
            }
        }
    }
}

// ---------------- K2: per-node el/er ------------------------------------------
__global__ __launch_bounds__(256) void k2_node(const float* __restrict__ attn_l,
                                               const float* __restrict__ attn_r) {
    __shared__ float sal[HD], sar[HD];
    int t = threadIdx.x;
    sal[t] = attn_l[t];
    sar[t] = attn_r[t];
    __syncthreads();

    int warp = t >> 5, lane = t & 31;
    int n = blockIdx.x * 8 + warp;
    if (n >= N_NODES) return;

    const float4* hp = (const float4*)(g_h + (long)n * HD);
    float4 v0 = hp[lane * 2], v1 = hp[lane * 2 + 1];
    float4 a0 = ((const float4*)sal)[lane * 2], a1 = ((const float4*)sal)[lane * 2 + 1];
    float4 r0 = ((const float4*)sar)[lane * 2], r1 = ((const float4*)sar)[lane * 2 + 1];

    float el = v0.x*a0.x + v0.y*a0.y + v0.z*a0.z + v0.w*a0.w
             + v1.x*a1.x + v1.y*a1.y + v1.z*a1.z + v1.w*a1.w;
    float er = v0.x*r0.x + v0.y*r0.y + v0.z*r0.z + v0.w*r0.w
             + v1.x*r1.x + v1.y*r1.y + v1.z*r1.z + v1.w*r1.w;
    el += __shfl_xor_sync(0xffffffffu, el, 1);
    el += __shfl_xor_sync(0xffffffffu, el, 2);
    er += __shfl_xor_sync(0xffffffffu, er, 1);
    er += __shfl_xor_sync(0xffffffffu, er, 2);
    if ((lane & 3) == 0) {
        g_el[n * HEADS + (lane >> 2)] = el;
        g_er[n * HEADS + (lane >> 2)] = er;
    }
}

// ---------------- CSR build ----------------------------------------------------
__global__ void khist(const int* __restrict__ dst) {
    int e = blockIdx.x * 256 + threadIdx.x;
    if (e < N_EDGES) atomicAdd(&g_cnt[dst[e]], 1);
}

__global__ __launch_bounds__(256) void kscan_part() {
    __shared__ int ws[8];
    int t = threadIdx.x, lane = t & 31, w = t >> 5;
    int i = blockIdx.x * 256 + t;
    int v = (i < N_NODES) ? g_cnt[i] : 0;
    int sv = v;
    #pragma unroll
    for (int d = 1; d < 32; d <<= 1) {
        int x = __shfl_up_sync(0xffffffffu, sv, d);
        if (lane >= d) sv += x;
    }
    if (lane == 31) ws[w] = sv;
    __syncthreads();
    if (t < 8) {
        int x = ws[t];
        #pragma unroll
        for (int d = 1; d < 8; d <<= 1) {
            int y = __shfl_up_sync(0xffu, x, d);
            if (t >= d) x += y;
        }
        ws[t] = x;
    }
    __syncthreads();
    int excl = sv - v + ((w > 0) ? ws[w - 1] : 0);
    if (i < N_NODES) g_start[i] = excl;
    if (t == 255) g_bsum[blockIdx.x] = ws[7];
}

__global__ __launch_bounds__(256) void kscan_top() {
    __shared__ int ws[8];
    int t = threadIdx.x, lane = t & 31, w = t >> 5;
    int v = (t < NB_SCAN) ? g_bsum[t] : 0;
    int sv = v;
    #pragma unroll
    for (int d = 1; d < 32; d <<= 1) {
        int x = __shfl_up_sync(0xffffffffu, sv, d);
        if (lane >= d) sv += x;
    }
    if (lane == 31) ws[w] = sv;
    __syncthreads();
    if (t < 8) {
        int x = ws[t];
        #pragma unroll
        for (int d = 1; d < 8; d <<= 1) {
            int y = __shfl_up_sync(0xffu, x, d);
            if (t >= d) x += y;
        }
        ws[t] = x;
    }
    __syncthreads();
    int excl = sv - v + ((w > 0) ? ws[w - 1] : 0);
    if (t < NB_SCAN) g_bsum[t] = excl;
}

__global__ __launch_bounds__(256) void kscan_add() {
    int i = blockIdx.x * 256 + threadIdx.x;
    if (i < N_NODES) {
        int s = g_start[i] + g_bsum[blockIdx.x];
        g_start[i] = s;
        g_cur[i]   = s;
    }
}

__global__ void kscatter(const int* __restrict__ src, const int* __restrict__ dst) {
    int e = blockIdx.x * 256 + threadIdx.x;
    if (e >= N_EDGES) return;
    int pos = atomicAdd(&g_cur[dst[e]], 1);
    g_order[pos] = e;
    g_osrc[pos]  = src[e];
}

// ---------------- K4f: fused softmax + aggregation, one warp per dst node ----
__global__ __launch_bounds__(256) void k4f(const float* __restrict__ edge_emb,
                                           const float* __restrict__ bias,
                                           float* __restrict__ out) {
    __shared__ float Cs[64];
    __shared__ float sb[HD];
    int t = threadIdx.x;
    if (t < 64) Cs[t] = g_C[t];
    sb[t] = bias[t];
    __syncthreads();

    int warp = t >> 5, lane = t & 31;
    int node = blockIdx.x * 8 + warp;
    if (node >= N_NODES) return;

    int beg = g_start[node];
    int end = beg + g_cnt[node];

    float er_h = 0.f;
    float c0[8];
    if (lane < HEADS) {
        er_h = g_er[node * HEADS + lane];
        #pragma unroll
        for (int k = 0; k < 8; ++k) c0[k] = Cs[k * 8 + lane];
    }

    float acc[8] = {0.f, 0.f, 0.f, 0.f, 0.f, 0.f, 0.f, 0.f};
    float s = 0.f;

    int j = beg;
    for (; j + 1 < end; j += 2) {
        int e0 = g_order[j],     s0 = g_osrc[j];
        int e1 = g_order[j + 1], s1 = g_osrc[j + 1];

        // issue both gathers up front (independent chains)
        uint4 ra = *(const uint4*)(g_hh + (long)s0 * HD + lane * 8);
        uint4 rb = *(const uint4*)(g_hh + (long)s1 * HD + lane * 8);

        float p0 = 0.f, p1 = 0.f;
        if (lane < HEADS) {
            float el0 = g_el[s0 * HEADS + lane];
            float el1 = g_el[s1 * HEADS + lane];
            const float4* ea = (const float4*)(edge_emb + (long)e0 * HEADS);
            const float4* eb = (const float4*)(edge_emb + (long)e1 * HEADS);
            float4 a0v = ea[0], a1v = ea[1];
            float4 b0v = eb[0], b1v = eb[1];
            float ee0 = a0v.x*c0[0] + a0v.y*c0[1] + a0v.z*c0[2] + a0v.w*c0[3]
                      + a1v.x*c0[4] + a1v.y*c0[5] + a1v.z*c0[6] + a1v.w*c0[7];
            float ee1 = b0v.x*c0[0] + b0v.y*c0[1] + b0v.z*c0[2] + b0v.w*c0[3]
                      + b1v.x*c0[4] + b1v.y*c0[5] + b1v.z*c0[6] + b1v.w*c0[7];
            float x0 = el0 + er_h + ee0;
            float x1 = el1 + er_h + ee1;
            x0 = (x0 > 0.f) ? x0 : NEG_SLOPE * x0;
            x1 = (x1 > 0.f) ? x1 : NEG_SLOPE * x1;
            p0 = __expf(x0);
            p1 = __expf(x1);
            s += p0 + p1;
        }
        float al0 = __shfl_sync(0xffffffffu, p0, lane >> 2);
        float al1 = __shfl_sync(0xffffffffu, p1, lane >> 2);

        float2 f0 = __half22float2(*(__half2*)&ra.x);
        float2 f1 = __half22float2(*(__half2*)&ra.y);
        float2 f2 = __half22float2(*(__half2*)&ra.z);
        float2 f3 = __half22float2(*(__half2*)&ra.w);
        acc[0] += al0 * f0.x; acc[1] += al0 * f0.y;
        acc[2] += al0 * f1.x; acc[3] += al0 * f1.y;
        acc[4] += al0 * f2.x; acc[5] += al0 * f2.y;
        acc[6] += al0 * f3.x; acc[7] += al0 * f3.y;
        f0 = __half22float2(*(__half2*)&rb.x);
        f1 = __half22float2(*(__half2*)&rb.y);
        f2 = __half22float2(*(__half2*)&rb.z);
        f3 = __half22float2(*(__half2*)&rb.w);
        acc[0] += al1 * f0.x; acc[1] += al1 * f0.y;
        acc[2] += al1 * f1.x; acc[3] += al1 * f1.y;
        acc[4] += al1 * f2.x; acc[5] += al1 * f2.y;
        acc[6] += al1 * f3.x; acc[7] += al1 * f3.y;
    }
    if (j < end) {
        int e0 = g_order[j], s0 = g_osrc[j];
        uint4 ra = *(const uint4*)(g_hh + (long)s0 * HD + lane * 8);
        float p0 = 0.f;
        if (lane < HEADS) {
            float el0 = g_el[s0 * HEADS + lane];
            const float4* ea = (const float4*)(edge_emb + (long)e0 * HEADS);
            float4 a0v = ea[0], a1v = ea[1];
            float ee0 = a0v.x*c0[0] + a0v.y*c0[1] + a0v.z*c0[2] + a0v.w*c0[3]
                      + a1v.x*c0[4] + a1v.y*c0[5] + a1v.z*c0[6] + a1v.w*c0[7];
            float x0 = el0 + er_h + ee0;
            x0 = (x0 > 0.f) ? x0 : NEG_SLOPE * x0;
            p0 = __expf(x0);
            s += p0;
        }
        float al0 = __shfl_sync(0xffffffffu, p0, lane >> 2);
        float2 f0 = __half22float2(*(__half2*)&ra.x);
        float2 f1 = __half22float2(*(__half2*)&ra.y);
        float2 f2 = __half22float2(*(__half2*)&ra.z);
        float2 f3 = __half22float2(*(__half2*)&ra.w);
        acc[0] += al0 * f0.x; acc[1] += al0 * f0.y;
        acc[2] += al0 * f1.x; acc[3] += al0 * f1.y;
        acc[4] += al0 * f2.x; acc[5] += al0 * f2.y;
        acc[6] += al0 * f3.x; acc[7] += al0 * f3.y;
    }

    float sh  = __shfl_sync(0xffffffffu, s, lane >> 2);
    float inv = 1.f / (sh + 1e-9f);

    float* op = out + (long)node * HD + lane * 8;
    const float* bp = sb + lane * 8;
    *(float4*)(op)     = make_float4(acc[0] * inv + bp[0], acc[1] * inv + bp[1],
                                     acc[2] * inv + bp[2], acc[3] * inv + bp[3]);
    *(float4*)(op + 4) = make_float4(acc[4] * inv + bp[4], acc[5] * inv + bp[5],
                                     acc[6] * inv + bp[6], acc[7] * inv + bp[7]);
}

// ---------------- launch ------------------------------------------------------
extern "C" void kernel_launch(void* const* d_in, const int* in_sizes, int n_in,
                              void* d_out, int out_size) {
    const float* feat     = (const float*)d_in[0];
    const float* edge_emb = (const float*)d_in[1];
    const int*   src      = (const int*)  d_in[2];
    const int*   dst      = (const int*)  d_in[3];
    const float* W_src    = (const float*)d_in[4];
    const float* W_e      = (const float*)d_in[5];
    const float* attn_l   = (const float*)d_in[6];
    const float* attn_r   = (const float*)d_in[7];
    const float* attn_e   = (const float*)d_in[8];
    const float* bias     = (const float*)d_in[9];
    float* out = (float*)d_out;

    // CSR build
    void* cnt_ptr = nullptr;
    cudaGetSymbolAddress(&cnt_ptr, g_cnt);
    cudaMemsetAsync(cnt_ptr, 0, N_NODES * sizeof(int));
    khist     <<<(N_EDGES + 255) / 256, 256>>>(dst);
    kscan_part<<<NB_SCAN, 256>>>();
    kscan_top <<<1, 256>>>();
    kscan_add <<<NB_SCAN, 256>>>();
    kscatter  <<<(N_EDGES + 255) / 256, 256>>>(src, dst);

    k0_foldC<<<1, 64>>>(W_e, attn_e);
    kconvB<<<HD, HD>>>(W_src);

    dim3 g1((N_NODES + 127) / 128, 2);
    k1_mma<<<g1, 256>>>(feat);

    k2_node<<<(N_NODES + 7) / 8, 256>>>(attn_l, attn_r);

    k4f<<<(N_NODES + 7) / 8, 256>>>(edge_emb, bias, out);
}

// round 9
// speedup vs baseline: 2.3972x; 1.1106x over previous
#include <cuda_runtime.h>
#include <cuda_bf16.h>
#include <cuda_fp16.h>

#define N_NODES 50000
#define N_EDGES 800000
#define HEADS 8
#define DOUT 32
#define HD 256          // HEADS*DOUT == IN_FEATS == 256
#define NEG_SLOPE 0.2f
#define NB_SCAN 196     // ceil(N_NODES/256)

// ---------------- scratch (static device globals; no allocation) -------------
__device__ float g_h [N_NODES * HD];      // projected node features f32
__device__ __half g_hh[N_NODES * HD];     // projected node features fp16 (gather)
__device__ float g_el[N_NODES * HEADS];
__device__ float g_er[N_NODES * HEADS];
__device__ float g_C [HEADS * HEADS];     // folded W_e * attn_e (k-major)

__device__ __nv_bfloat16 g_Bhi[HD * HD];  // W_src^T split hi  [n][k]
__device__ __nv_bfloat16 g_Blo[HD * HD];  // W_src^T split lo  [n][k]

// CSR-by-dst scratch
__device__ int   g_cnt  [N_NODES];
__device__ int   g_start[N_NODES];
__device__ int   g_cur  [N_NODES];
__device__ int   g_osrc [N_EDGES];        // src ids grouped by dst
__device__ float g_ee   [N_EDGES * HEADS];// edge attention term grouped by dst
__device__ int   g_bsum [NB_SCAN];

// ---------------- K0: fold W_e (8,256) with attn_e (8,32) -> C (8,8) ---------
__global__ void k0_foldC(const float* __restrict__ W_e, const float* __restrict__ attn_e) {
    int t = threadIdx.x;
    if (t < 64) {
        int k = t >> 3, h = t & 7;
        float s = 0.f;
        #pragma unroll
        for (int d = 0; d < DOUT; ++d)
            s += W_e[k * HD + h * DOUT + d] * attn_e[h * DOUT + d];
        g_C[k * 8 + h] = s;
    }
}

// ---------------- conv B: W_src f32 [k][n] -> hi/lo bf16 transposed [n][k] ---
__global__ void kconvB(const float* __restrict__ B) {
    int k = blockIdx.x;
    int n = threadIdx.x;
    float v = B[k * HD + n];
    __nv_bfloat16 h = __float2bfloat16(v);
    __nv_bfloat16 l = __float2bfloat16(v - __bfloat162float(h));
    g_Bhi[n * HD + k] = h;
    g_Blo[n * HD + k] = l;
}

// ---------------- cp.async helpers -------------------------------------------
__device__ __forceinline__ void cp16(unsigned dst, const void* src, bool pred) {
    asm volatile("cp.async.cg.shared.global [%0], [%1], 16, %2;"
                 :: "r"(dst), "l"(src), "r"(pred ? 16 : 0));
}
__device__ __forceinline__ void cp_commit() {
    asm volatile("cp.async.commit_group;");
}
template <int N> __device__ __forceinline__ void cp_wait() {
    asm volatile("cp.async.wait_group %0;" :: "n"(N));
}

__device__ __forceinline__ void mma16816(float* c, const unsigned* a,
                                         unsigned b0, unsigned b1) {
    asm volatile("mma.sync.aligned.m16n8k16.row.col.f32.bf16.bf16.f32 "
                 "{%0,%1,%2,%3}, {%4,%5,%6,%7}, {%8,%9}, {%0,%1,%2,%3};"
                 : "+f"(c[0]), "+f"(c[1]), "+f"(c[2]), "+f"(c[3])
                 : "r"(a[0]), "r"(a[1]), "r"(a[2]), "r"(a[3]), "r"(b0), "r"(b1));
}

// truncation split of 2 consecutive f32 -> packed bf16x2 hi (exact) + lo (rn)
__device__ __forceinline__ void split2(float2 f, unsigned& hi, unsigned& lo) {
    unsigned ux = __float_as_uint(f.x), uy = __float_as_uint(f.y);
    hi = __byte_perm(ux, uy, 0x7632);
    float hx = __uint_as_float(ux & 0xffff0000u);
    float hy = __uint_as_float(uy & 0xffff0000u);
    __nv_bfloat162 l = __floats2bfloat162_rn(f.x - hx, f.y - hy);
    lo = *(unsigned*)&l;
}

// ---------------- K1: split-bf16 tensor-core GEMM + fused el/er --------------
#define BKS  24      // bf16 B row stride
#define BKSF 20      // f32 A row stride
__global__ __launch_bounds__(256, 2) void k1_mma(const float* __restrict__ A,
                                                 const float* __restrict__ attn_l,
                                                 const float* __restrict__ attn_r) {
    __shared__ float         smA [2][128 * BKSF];
    __shared__ __nv_bfloat16 smBh[2][128 * BKS];
    __shared__ __nv_bfloat16 smBl[2][128 * BKS];

    const int t    = threadIdx.x;
    const int warp = t >> 5;
    const int lane = t & 31;
    const int wm   = warp >> 1;
    const int wn   = warp & 1;
    const int bm   = blockIdx.x * 128;
    const int bn   = blockIdx.y * 128;

    const int lr = t >> 1;
    const int lc = (t & 1) * 8;
    const bool arow_ok = (bm + lr) < N_NODES;
    const long a_goff  = (long)(bm + lr) * HD + lc;
    const long b_goff  = (long)(bn + lr) * HD + lc;
    const unsigned sA_off = (unsigned)((lr * BKSF + lc) * sizeof(float));
    const unsigned sB_off = (unsigned)((lr * BKS + lc) * sizeof(__nv_bfloat16));

    unsigned aA[2], aBh[2], aBl[2];
    #pragma unroll
    for (int s = 0; s < 2; ++s) {
        aA [s] = (unsigned)__cvta_generic_to_shared(&smA [s][0]) + sA_off;
        aBh[s] = (unsigned)__cvta_generic_to_shared(&smBh[s][0]) + sB_off;
        aBl[s] = (unsigned)__cvta_generic_to_shared(&smBl[s][0]) + sB_off;
    }

    float acc[2][8][4];
    #pragma unroll
    for (int i = 0; i < 2; ++i)
        #pragma unroll
        for (int j = 0; j < 8; ++j)
            #pragma unroll
            for (int q = 0; q < 4; ++q) acc[i][j][q] = 0.f;

    {
        cp16(aA[0],      A + a_goff,     arow_ok);
        cp16(aA[0] + 16, A + a_goff + 4, arow_ok);
        cp16(aBh[0], g_Bhi + b_goff, true);
        cp16(aBl[0], g_Blo + b_goff, true);
        cp_commit();
    }

    const int qr = lane >> 2;
    const int qc = (lane & 3) * 2;

    #pragma unroll 1
    for (int tile = 0; tile < 16; ++tile) {
        if (tile < 15) {
            int st = (tile + 1) & 1;
            int k0 = (tile + 1) * 16;
            cp16(aA[st],      A + a_goff + k0,     arow_ok);
            cp16(aA[st] + 16, A + a_goff + k0 + 4, arow_ok);
            cp16(aBh[st], g_Bhi + b_goff + k0, true);
            cp16(aBl[st], g_Blo + b_goff + k0, true);
            cp_commit();
            cp_wait<1>();
        } else {
            cp_wait<0>();
        }
        __syncthreads();

        const int st = tile & 1;
        const float* Af = smA[st];
        const __nv_bfloat16* Bh = smBh[st];
        const __nv_bfloat16* Bl = smBl[st];

        unsigned ah[2][4], al[2][4];
        #pragma unroll
        for (int mt = 0; mt < 2; ++mt) {
            int r = wm * 32 + mt * 16 + qr;
            float2 f0 = *(const float2*)(Af + r * BKSF + qc);
            float2 f1 = *(const float2*)(Af + (r + 8) * BKSF + qc);
            float2 f2 = *(const float2*)(Af + r * BKSF + qc + 8);
            float2 f3 = *(const float2*)(Af + (r + 8) * BKSF + qc + 8);
            split2(f0, ah[mt][0], al[mt][0]);
            split2(f1, ah[mt][1], al[mt][1]);
            split2(f2, ah[mt][2], al[mt][2]);
            split2(f3, ah[mt][3], al[mt][3]);
        }

        #pragma unroll
        for (int nt = 0; nt < 8; ++nt) {
            int n = wn * 64 + nt * 8 + qr;
            unsigned bh0 = *(const unsigned*)(Bh + n * BKS + qc);
            unsigned bh1 = *(const unsigned*)(Bh + n * BKS + qc + 8);
            unsigned bl0 = *(const unsigned*)(Bl + n * BKS + qc);
            unsigned bl1 = *(const unsigned*)(Bl + n * BKS + qc + 8);
            #pragma unroll
            for (int mt = 0; mt < 2; ++mt) {
                mma16816(acc[mt][nt], ah[mt], bh0, bh1);
                mma16816(acc[mt][nt], ah[mt], bl0, bl1);
                mma16816(acc[mt][nt], al[mt], bh0, bh1);
            }
        }
        __syncthreads();
    }

    // attention weights for this thread's 16 columns (2 per nt)
    float wl[8][2], wr[8][2];
    #pragma unroll
    for (int nt = 0; nt < 8; ++nt) {
        int cc = bn + wn * 64 + nt * 8 + qc;
        float2 l2 = *(const float2*)(attn_l + cc);
        float2 r2 = *(const float2*)(attn_r + cc);
        wl[nt][0] = l2.x; wl[nt][1] = l2.y;
        wr[nt][0] = r2.x; wr[nt][1] = r2.y;
    }
    const int h0 = (bn + wn * 64) >> 5;     // head of nt<4, nt>=4 -> h0+1

    // epilogue: stores + fused el/er partial reduction
    #pragma unroll
    for (int mt = 0; mt < 2; ++mt) {
        int r0 = bm + wm * 32 + mt * 16 + qr;
        float elA[2] = {0.f, 0.f}, erA[2] = {0.f, 0.f};   // row r0: head h0, h0+1
        float elB[2] = {0.f, 0.f}, erB[2] = {0.f, 0.f};   // row r0+8
        #pragma unroll
        for (int nt = 0; nt < 8; ++nt) {
            int hg = nt >> 2;
            int cc = bn + wn * 64 + nt * 8 + qc;
            if (r0 < N_NODES) {
                *(float2*)(g_h + (long)r0 * HD + cc) =
                    make_float2(acc[mt][nt][0], acc[mt][nt][1]);
                *(__half2*)(g_hh + (long)r0 * HD + cc) =
                    __floats2half2_rn(acc[mt][nt][0], acc[mt][nt][1]);
            }
            if (r0 + 8 < N_NODES) {
                *(float2*)(g_h + (long)(r0 + 8) * HD + cc) =
                    make_float2(acc[mt][nt][2], acc[mt][nt][3]);
                *(__half2*)(g_hh + (long)(r0 + 8) * HD + cc) =
                    __floats2half2_rn(acc[mt][nt][2], acc[mt][nt][3]);
            }
            elA[hg] += acc[mt][nt][0] * wl[nt][0] + acc[mt][nt][1] * wl[nt][1];
            erA[hg] += acc[mt][nt][0] * wr[nt][0] + acc[mt][nt][1] * wr[nt][1];
            elB[hg] += acc[mt][nt][2] * wl[nt][0] + acc[mt][nt][3] * wl[nt][1];
            erB[hg] += acc[mt][nt][2] * wr[nt][0] + acc[mt][nt][3] * wr[nt][1];
        }
        if (r0 < N_NODES) {
            atomicAdd(&g_el[r0 * HEADS + h0],     elA[0]);
            atomicAdd(&g_el[r0 * HEADS + h0 + 1], elA[1]);
            atomicAdd(&g_er[r0 * HEADS + h0],     erA[0]);
            atomicAdd(&g_er[r0 * HEADS + h0 + 1], erA[1]);
        }
        if (r0 + 8 < N_NODES) {
            atomicAdd(&g_el[(r0 + 8) * HEADS + h0],     elB[0]);
            atomicAdd(&g_el[(r0 + 8) * HEADS + h0 + 1], elB[1]);
            atomicAdd(&g_er[(r0 + 8) * HEADS + h0],     erB[0]);
            atomicAdd(&g_er[(r0 + 8) * HEADS + h0 + 1], erB[1]);
        }
    }
}

// ---------------- CSR build ----------------------------------------------------
__global__ void khist(const int* __restrict__ dst) {
    int e = blockIdx.x * 256 + threadIdx.x;
    if (e < N_EDGES) atomicAdd(&g_cnt[dst[e]], 1);
}

__global__ __launch_bounds__(256) void kscan_part() {
    __shared__ int ws[8];
    int t = threadIdx.x, lane = t & 31, w = t >> 5;
    int i = blockIdx.x * 256 + t;
    int v = (i < N_NODES) ? g_cnt[i] : 0;
    int sv = v;
    #pragma unroll
    for (int d = 1; d < 32; d <<= 1) {
        int x = __shfl_up_sync(0xffffffffu, sv, d);
        if (lane >= d) sv += x;
    }
    if (lane == 31) ws[w] = sv;
    __syncthreads();
    if (t < 8) {
        int x = ws[t];
        #pragma unroll
        for (int d = 1; d < 8; d <<= 1) {
            int y = __shfl_up_sync(0xffu, x, d);
            if (t >= d) x += y;
        }
        ws[t] = x;
    }
    __syncthreads();
    int excl = sv - v + ((w > 0) ? ws[w - 1] : 0);
    if (i < N_NODES) g_start[i] = excl;
    if (t == 255) g_bsum[blockIdx.x] = ws[7];
}

__global__ __launch_bounds__(256) void kscan_top() {
    __shared__ int ws[8];
    int t = threadIdx.x, lane = t & 31, w = t >> 5;
    int v = (t < NB_SCAN) ? g_bsum[t] : 0;
    int sv = v;
    #pragma unroll
    for (int d = 1; d < 32; d <<= 1) {
        int x = __shfl_up_sync(0xffffffffu, sv, d);
        if (lane >= d) sv += x;
    }
    if (lane == 31) ws[w] = sv;
    __syncthreads();
    if (t < 8) {
        int x = ws[t];
        #pragma unroll
        for (int d = 1; d < 8; d <<= 1) {
            int y = __shfl_up_sync(0xffu, x, d);
            if (t >= d) x += y;
        }
        ws[t] = x;
    }
    __syncthreads();
    int excl = sv - v + ((w > 0) ? ws[w - 1] : 0);
    if (t < NB_SCAN) g_bsum[t] = excl;
}

__global__ __launch_bounds__(256) void kscan_add() {
    int i = blockIdx.x * 256 + threadIdx.x;
    if (i < N_NODES) {
        int s = g_start[i] + g_bsum[blockIdx.x];
        g_start[i] = s;
        g_cur[i]   = s;
    }
}

// scatter + fold edge_emb @ C into g_ee (grouped by dst)
__global__ __launch_bounds__(256) void kscatter(const int* __restrict__ src,
                                                const int* __restrict__ dst,
                                                const float* __restrict__ edge_emb) {
    __shared__ float Cs[64];
    int t = threadIdx.x;
    if (t < 64) Cs[t] = g_C[t];
    __syncthreads();

    int e = blockIdx.x * 256 + t;
    if (e >= N_EDGES) return;
    int pos = atomicAdd(&g_cur[dst[e]], 1);
    g_osrc[pos] = src[e];

    const float4* ep = (const float4*)(edge_emb + (long)e * HEADS);
    float4 e0 = ep[0], e1 = ep[1];
    float ein[8] = {e0.x, e0.y, e0.z, e0.w, e1.x, e1.y, e1.z, e1.w};
    float ee[8];
    #pragma unroll
    for (int h = 0; h < 8; ++h) {
        float s = 0.f;
        #pragma unroll
        for (int k = 0; k < 8; ++k) s += ein[k] * Cs[k * 8 + h];
        ee[h] = s;
    }
    float4* op = (float4*)(g_ee + (long)pos * HEADS);
    op[0] = make_float4(ee[0], ee[1], ee[2], ee[3]);
    op[1] = make_float4(ee[4], ee[5], ee[6], ee[7]);
}

// ---------------- K4f: fused softmax + aggregation, one warp per dst node ----
__device__ __forceinline__ float edge_p(int s0, int j, float er_h, int lane) {
    float el0 = g_el[s0 * HEADS + lane];
    float ee0 = g_ee[(long)j * HEADS + lane];
    float x = el0 + er_h + ee0;
    x = (x > 0.f) ? x : NEG_SLOPE * x;
    return __expf(x);
}

__device__ __forceinline__ void accum(float* acc, float a, uint4 r) {
    float2 f0 = __half22float2(*(__half2*)&r.x);
    float2 f1 = __half22float2(*(__half2*)&r.y);
    float2 f2 = __half22float2(*(__half2*)&r.z);
    float2 f3 = __half22float2(*(__half2*)&r.w);
    acc[0] += a * f0.x; acc[1] += a * f0.y;
    acc[2] += a * f1.x; acc[3] += a * f1.y;
    acc[4] += a * f2.x; acc[5] += a * f2.y;
    acc[6] += a * f3.x; acc[7] += a * f3.y;
}

__global__ __launch_bounds__(256) void k4f(const float* __restrict__ bias,
                                           float* __restrict__ out) {
    __shared__ float sb[HD];
    int t = threadIdx.x;
    sb[t] = bias[t];
    __syncthreads();

    int warp = t >> 5, lane = t & 31;
    int node = blockIdx.x * 8 + warp;
    if (node >= N_NODES) return;

    int beg = g_start[node];
    int end = beg + g_cnt[node];

    float er_h = (lane < HEADS) ? g_er[node * HEADS + lane] : 0.f;

    float acc[8] = {0.f, 0.f, 0.f, 0.f, 0.f, 0.f, 0.f, 0.f};
    float s = 0.f;

    int j = beg;
    for (; j + 3 < end; j += 4) {
        int s0 = g_osrc[j],     s1 = g_osrc[j + 1];
        int s2 = g_osrc[j + 2], s3 = g_osrc[j + 3];

        uint4 ra = *(const uint4*)(g_hh + (long)s0 * HD + lane * 8);
        uint4 rb = *(const uint4*)(g_hh + (long)s1 * HD + lane * 8);
        uint4 rc = *(const uint4*)(g_hh + (long)s2 * HD + lane * 8);
        uint4 rd = *(const uint4*)(g_hh + (long)s3 * HD + lane * 8);

        float p0 = 0.f, p1 = 0.f, p2 = 0.f, p3 = 0.f;
        if (lane < HEADS) {
            p0 = edge_p(s0, j,     er_h, lane);
            p1 = edge_p(s1, j + 1, er_h, lane);
            p2 = edge_p(s2, j + 2, er_h, lane);
            p3 = edge_p(s3, j + 3, er_h, lane);
            s += (p0 + p1) + (p2 + p3);
        }
        int sl = lane >> 2;
        accum(acc, __shfl_sync(0xffffffffu, p0, sl), ra);
        accum(acc, __shfl_sync(0xffffffffu, p1, sl), rb);
        accum(acc, __shfl_sync(0xffffffffu, p2, sl), rc);
        accum(acc, __shfl_sync(0xffffffffu, p3, sl), rd);
    }
    for (; j < end; ++j) {
        int s0 = g_osrc[j];
        uint4 ra = *(const uint4*)(g_hh + (long)s0 * HD + lane * 8);
        float p0 = 0.f;
        if (lane < HEADS) {
            p0 = edge_p(s0, j, er_h, lane);
            s += p0;
        }
        accum(acc, __shfl_sync(0xffffffffu, p0, lane >> 2), ra);
    }

    float sh  = __shfl_sync(0xffffffffu, s, lane >> 2);
    float inv = 1.f / (sh + 1e-9f);

    float* op = out + (long)node * HD + lane * 8;
    const float* bp = sb + lane * 8;
    *(float4*)(op)     = make_float4(acc[0] * inv + bp[0], acc[1] * inv + bp[1],
                                     acc[2] * inv + bp[2], acc[3] * inv + bp[3]);
    *(float4*)(op + 4) = make_float4(acc[4] * inv + bp[4], acc[5] * inv + bp[5],
                                     acc[6] * inv + bp[6], acc[7] * inv + bp[7]);
}

// ---------------- launch ------------------------------------------------------
extern "C" void kernel_launch(void* const* d_in, const int* in_sizes, int n_in,
                              void* d_out, int out_size) {
    const float* feat     = (const float*)d_in[0];
    const float* edge_emb = (const float*)d_in[1];
    const int*   src      = (const int*)  d_in[2];
    const int*   dst      = (const int*)  d_in[3];
    const float* W_src    = (const float*)d_in[4];
    const float* W_e      = (const float*)d_in[5];
    const float* attn_l   = (const float*)d_in[6];
    const float* attn_r   = (const float*)d_in[7];
    const float* attn_e   = (const float*)d_in[8];
    const float* bias     = (const float*)d_in[9];
    float* out = (float*)d_out;

    void *cnt_ptr = nullptr, *el_ptr = nullptr, *er_ptr = nullptr;
    cudaGetSymbolAddress(&cnt_ptr, g_cnt);
    cudaGetSymbolAddress(&el_ptr,  g_el);
    cudaGetSymbolAddress(&er_ptr,  g_er);

    k0_foldC<<<1, 64>>>(W_e, attn_e);

    cudaMemsetAsync(cnt_ptr, 0, N_NODES * sizeof(int));
    khist     <<<(N_EDGES + 255) / 256, 256>>>(dst);
    kscan_part<<<NB_SCAN, 256>>>();
    kscan_top <<<1, 256>>>();
    kscan_add <<<NB_SCAN, 256>>>();
    kscatter  <<<(N_EDGES + 255) / 256, 256>>>(src, dst, edge_emb);

    kconvB<<<HD, HD>>>(W_src);

    cudaMemsetAsync(el_ptr, 0, N_NODES * HEADS * sizeof(float));
    cudaMemsetAsync(er_ptr, 0, N_NODES * HEADS * sizeof(float));

    dim3 g1((N_NODES + 127) / 128, 2);
    k1_mma<<<g1, 256>>>(feat, attn_l, attn_r);

    k4f<<<(N_NODES + 7) / 8, 256>>>(bias, out);
}

// round 11
// speedup vs baseline: 2.5255x; 1.0535x over previous
#include <cuda_runtime.h>
#include <cuda_bf16.h>
#include <cuda_fp16.h>

#define N_NODES 50000
#define N_EDGES 800000
#define HEADS 8
#define DOUT 32
#define HD 256          // HEADS*DOUT == IN_FEATS == 256
#define NEG_SLOPE 0.2f
#define NB_SCAN 196     // ceil(N_NODES/256)

// ---------------- scratch (static device globals; no allocation) -------------
__device__ float g_h [N_NODES * HD];      // projected node features f32
__device__ __half g_hh[N_NODES * HD];     // projected node features fp16 (gather)
__device__ float g_el[N_NODES * HEADS];
__device__ float g_er[N_NODES * HEADS];
__device__ float g_C [HEADS * HEADS];     // folded W_e * attn_e (k-major)

__device__ __nv_bfloat16 g_Bhi[HD * HD];  // W_src^T split hi  [n][k]
__device__ __nv_bfloat16 g_Blo[HD * HD];  // W_src^T split lo  [n][k]

// CSR-by-dst scratch
__device__ int   g_cnt  [N_NODES];
__device__ int   g_start[N_NODES];
__device__ int   g_cur  [N_NODES];
__device__ int   g_osrc [N_EDGES];        // src ids grouped by dst
__device__ float g_ee   [N_EDGES * HEADS];// edge attention term grouped by dst
__device__ int   g_bsum [NB_SCAN];

// ---------------- conv B: W_src f32 [k][n] -> hi/lo bf16 transposed [n][k] ---
__global__ void kconvB(const float* __restrict__ B) {
    int k = blockIdx.x;
    int n = threadIdx.x;
    float v = B[k * HD + n];
    __nv_bfloat16 h = __float2bfloat16(v);
    __nv_bfloat16 l = __float2bfloat16(v - __bfloat162float(h));
    g_Bhi[n * HD + k] = h;
    g_Blo[n * HD + k] = l;
}

// ---------------- cp.async helpers -------------------------------------------
__device__ __forceinline__ void cp16(unsigned dst, const void* src, bool pred) {
    asm volatile("cp.async.cg.shared.global [%0], [%1], 16, %2;"
                 :: "r"(dst), "l"(src), "r"(pred ? 16 : 0));
}
__device__ __forceinline__ void cp_commit() {
    asm volatile("cp.async.commit_group;");
}
template <int N> __device__ __forceinline__ void cp_wait() {
    asm volatile("cp.async.wait_group %0;" :: "n"(N));
}

__device__ __forceinline__ void mma16816(float* c, const unsigned* a,
                                         unsigned b0, unsigned b1) {
    asm volatile("mma.sync.aligned.m16n8k16.row.col.f32.bf16.bf16.f32 "
                 "{%0,%1,%2,%3}, {%4,%5,%6,%7}, {%8,%9}, {%0,%1,%2,%3};"
                 : "+f"(c[0]), "+f"(c[1]), "+f"(c[2]), "+f"(c[3])
                 : "r"(a[0]), "r"(a[1]), "r"(a[2]), "r"(a[3]), "r"(b0), "r"(b1));
}

// truncation split of 2 consecutive f32 -> packed bf16x2 hi (exact) + lo (rn)
__device__ __forceinline__ void split2(float2 f, unsigned& hi, unsigned& lo) {
    unsigned ux = __float_as_uint(f.x), uy = __float_as_uint(f.y);
    hi = __byte_perm(ux, uy, 0x7632);
    float hx = __uint_as_float(ux & 0xffff0000u);
    float hy = __uint_as_float(uy & 0xffff0000u);
    __nv_bfloat162 l = __floats2bfloat162_rn(f.x - hx, f.y - hy);
    lo = *(unsigned*)&l;
}

// ---------------- K1: split-bf16 tensor-core GEMM + fused el/er --------------
#define BKS  24      // bf16 B row stride
#define BKSF 20      // f32 A row stride
__global__ __launch_bounds__(256, 2) void k1_mma(const float* __restrict__ A,
                                                 const float* __restrict__ attn_l,
                                                 const float* __restrict__ attn_r) {
    __shared__ float         smA [2][128 * BKSF];
    __shared__ __nv_bfloat16 smBh[2][128 * BKS];
    __shared__ __nv_bfloat16 smBl[2][128 * BKS];

    const int t    = threadIdx.x;
    const int warp = t >> 5;
    const int lane = t & 31;
    const int wm   = warp >> 1;
    const int wn   = warp & 1;
    const int bm   = blockIdx.x * 128;
    const int bn   = blockIdx.y * 128;

    const int lr = t >> 1;
    const int lc = (t & 1) * 8;
    const bool arow_ok = (bm + lr) < N_NODES;
    const long a_goff  = (long)(bm + lr) * HD + lc;
    const long b_goff  = (long)(bn + lr) * HD + lc;
    const unsigned sA_off = (unsigned)((lr * BKSF + lc) * sizeof(float));
    const unsigned sB_off = (unsigned)((lr * BKS + lc) * sizeof(__nv_bfloat16));

    unsigned aA[2], aBh[2], aBl[2];
    #pragma unroll
    for (int s = 0; s < 2; ++s) {
        aA [s] = (unsigned)__cvta_generic_to_shared(&smA [s][0]) + sA_off;
        aBh[s] = (unsigned)__cvta_generic_to_shared(&smBh[s][0]) + sB_off;
        aBl[s] = (unsigned)__cvta_generic_to_shared(&smBl[s][0]) + sB_off;
    }

    float acc[2][8][4];
    #pragma unroll
    for (int i = 0; i < 2; ++i)
        #pragma unroll
        for (int j = 0; j < 8; ++j)
            #pragma unroll
            for (int q = 0; q < 4; ++q) acc[i][j][q] = 0.f;

    {
        cp16(aA[0],      A + a_goff,     arow_ok);
        cp16(aA[0] + 16, A + a_goff + 4, arow_ok);
        cp16(aBh[0], g_Bhi + b_goff, true);
        cp16(aBl[0], g_Blo + b_goff, true);
        cp_commit();
    }

    const int qr = lane >> 2;
    const int qc = (lane & 3) * 2;

    #pragma unroll 1
    for (int tile = 0; tile < 16; ++tile) {
        if (tile < 15) {
            int st = (tile + 1) & 1;
            int k0 = (tile + 1) * 16;
            cp16(aA[st],      A + a_goff + k0,     arow_ok);
            cp16(aA[st] + 16, A + a_goff + k0 + 4, arow_ok);
            cp16(aBh[st], g_Bhi + b_goff + k0, true);
            cp16(aBl[st], g_Blo + b_goff + k0, true);
            cp_commit();
            cp_wait<1>();
        } else {
            cp_wait<0>();
        }
        __syncthreads();

        const int st = tile & 1;
        const float* Af = smA[st];
        const __nv_bfloat16* Bh = smBh[st];
        const __nv_bfloat16* Bl = smBl[st];

        unsigned ah[2][4], al[2][4];
        #pragma unroll
        for (int mt = 0; mt < 2; ++mt) {
            int r = wm * 32 + mt * 16 + qr;
            float2 f0 = *(const float2*)(Af + r * BKSF + qc);
            float2 f1 = *(const float2*)(Af + (r + 8) * BKSF + qc);
            float2 f2 = *(const float2*)(Af + r * BKSF + qc + 8);
            float2 f3 = *(const float2*)(Af + (r + 8) * BKSF + qc + 8);
            split2(f0, ah[mt][0], al[mt][0]);
            split2(f1, ah[mt][1], al[mt][1]);
            split2(f2, ah[mt][2], al[mt][2]);
            split2(f3, ah[mt][3], al[mt][3]);
        }

        #pragma unroll
        for (int nt = 0; nt < 8; ++nt) {
            int n = wn * 64 + nt * 8 + qr;
            unsigned bh0 = *(const unsigned*)(Bh + n * BKS + qc);
            unsigned bh1 = *(const unsigned*)(Bh + n * BKS + qc + 8);
            unsigned bl0 = *(const unsigned*)(Bl + n * BKS + qc);
            unsigned bl1 = *(const unsigned*)(Bl + n * BKS + qc + 8);
            #pragma unroll
            for (int mt = 0; mt < 2; ++mt) {
                mma16816(acc[mt][nt], ah[mt], bh0, bh1);
                mma16816(acc[mt][nt], ah[mt], bl0, bl1);
                mma16816(acc[mt][nt], al[mt], bh0, bh1);
            }
        }
        __syncthreads();
    }

    // attention weights for this thread's 16 columns (2 per nt)
    float wl[8][2], wr[8][2];
    #pragma unroll
    for (int nt = 0; nt < 8; ++nt) {
        int cc = bn + wn * 64 + nt * 8 + qc;
        float2 l2 = *(const float2*)(attn_l + cc);
        float2 r2 = *(const float2*)(attn_r + cc);
        wl[nt][0] = l2.x; wl[nt][1] = l2.y;
        wr[nt][0] = r2.x; wr[nt][1] = r2.y;
    }
    const int h0 = (bn + wn * 64) >> 5;

    // epilogue: stores + fused el/er partial reduction
    #pragma unroll
    for (int mt = 0; mt < 2; ++mt) {
        int r0 = bm + wm * 32 + mt * 16 + qr;
        float elA[2] = {0.f, 0.f}, erA[2] = {0.f, 0.f};
        float elB[2] = {0.f, 0.f}, erB[2] = {0.f, 0.f};
        #pragma unroll
        for (int nt = 0; nt < 8; ++nt) {
            int hg = nt >> 2;
            int cc = bn + wn * 64 + nt * 8 + qc;
            if (r0 < N_NODES) {
                *(float2*)(g_h + (long)r0 * HD + cc) =
                    make_float2(acc[mt][nt][0], acc[mt][nt][1]);
                *(__half2*)(g_hh + (long)r0 * HD + cc) =
                    __floats2half2_rn(acc[mt][nt][0], acc[mt][nt][1]);
            }
            if (r0 + 8 < N_NODES) {
                *(float2*)(g_h + (long)(r0 + 8) * HD + cc) =
                    make_float2(acc[mt][nt][2], acc[mt][nt][3]);
                *(__half2*)(g_hh + (long)(r0 + 8) * HD + cc) =
                    __floats2half2_rn(acc[mt][nt][2], acc[mt][nt][3]);
            }
            elA[hg] += acc[mt][nt][0] * wl[nt][0] + acc[mt][nt][1] * wl[nt][1];
            erA[hg] += acc[mt][nt][0] * wr[nt][0] + acc[mt][nt][1] * wr[nt][1];
            elB[hg] += acc[mt][nt][2] * wl[nt][0] + acc[mt][nt][3] * wl[nt][1];
            erB[hg] += acc[mt][nt][2] * wr[nt][0] + acc[mt][nt][3] * wr[nt][1];
        }
        if (r0 < N_NODES) {
            atomicAdd(&g_el[r0 * HEADS + h0],     elA[0]);
            atomicAdd(&g_el[r0 * HEADS + h0 + 1], elA[1]);
            atomicAdd(&g_er[r0 * HEADS + h0],     erA[0]);
            atomicAdd(&g_er[r0 * HEADS + h0 + 1], erA[1]);
        }
        if (r0 + 8 < N_NODES) {
            atomicAdd(&g_el[(r0 + 8) * HEADS + h0],     elB[0]);
            atomicAdd(&g_el[(r0 + 8) * HEADS + h0 + 1], elB[1]);
            atomicAdd(&g_er[(r0 + 8) * HEADS + h0],     erB[0]);
            atomicAdd(&g_er[(r0 + 8) * HEADS + h0 + 1], erB[1]);
        }
    }
}

// ---------------- CSR build ----------------------------------------------------
// khist also computes C = fold(W_e, attn_e) in block 0 (needed by kscatter later)
__global__ void khist(const int* __restrict__ dst,
                      const float* __restrict__ W_e,
                      const float* __restrict__ attn_e) {
    int t = threadIdx.x;
    if (blockIdx.x == 0 && t < 64) {
        int k = t >> 3, h = t & 7;
        float s = 0.f;
        #pragma unroll
        for (int d = 0; d < DOUT; ++d)
            s += W_e[k * HD + h * DOUT + d] * attn_e[h * DOUT + d];
        g_C[k * 8 + h] = s;
    }
    int e = blockIdx.x * 256 + t;
    if (e < N_EDGES) atomicAdd(&g_cnt[dst[e]], 1);
}

__global__ __launch_bounds__(256) void kscan_part() {
    __shared__ int ws[8];
    int t = threadIdx.x, lane = t & 31, w = t >> 5;
    int i = blockIdx.x * 256 + t;
    int v = (i < N_NODES) ? g_cnt[i] : 0;
    int sv = v;
    #pragma unroll
    for (int d = 1; d < 32; d <<= 1) {
        int x = __shfl_up_sync(0xffffffffu, sv, d);
        if (lane >= d) sv += x;
    }
    if (lane == 31) ws[w] = sv;
    __syncthreads();
    if (t < 8) {
        int x = ws[t];
        #pragma unroll
        for (int d = 1; d < 8; d <<= 1) {
            int y = __shfl_up_sync(0xffu, x, d);
            if (t >= d) x += y;
        }
        ws[t] = x;
    }
    __syncthreads();
    int excl = sv - v + ((w > 0) ? ws[w - 1] : 0);
    if (i < N_NODES) g_start[i] = excl;
    if (t == 255) g_bsum[blockIdx.x] = ws[7];
}

// add block offsets (each block reduces g_bsum[0..bid) itself), init cursors
__global__ __launch_bounds__(256) void kscan_add() {
    __shared__ int ws[8];
    __shared__ int offs;
    int t = threadIdx.x, lane = t & 31, w = t >> 5;
    int bid = blockIdx.x;
    int v = (t < bid) ? g_bsum[t] : 0;        // bid <= 195 < 256
    #pragma unroll
    for (int d = 16; d > 0; d >>= 1)
        v += __shfl_xor_sync(0xffffffffu, v, d);
    if (lane == 0) ws[w] = v;
    __syncthreads();
    if (t == 0) {
        int o = 0;
        #pragma unroll
        for (int i = 0; i < 8; ++i) o += ws[i];
        offs = o;
    }
    __syncthreads();
    int i = bid * 256 + t;
    if (i < N_NODES) {
        int s = g_start[i] + offs;
        g_start[i] = s;
        g_cur[i]   = s;
    }
}

// scatter + fold edge_emb @ C into g_ee (grouped by dst)
__global__ __launch_bounds__(256) void kscatter(const int* __restrict__ src,
                                                const int* __restrict__ dst,
                                                const float* __restrict__ edge_emb) {
    __shared__ float Cs[64];
    int t = threadIdx.x;
    if (t < 64) Cs[t] = g_C[t];
    __syncthreads();

    int e = blockIdx.x * 256 + t;
    if (e >= N_EDGES) return;
    int pos = atomicAdd(&g_cur[dst[e]], 1);
    g_osrc[pos] = src[e];

    const float4* ep = (const float4*)(edge_emb + (long)e * HEADS);
    float4 e0 = ep[0], e1 = ep[1];
    float ein[8] = {e0.x, e0.y, e0.z, e0.w, e1.x, e1.y, e1.z, e1.w};
    float ee[8];
    #pragma unroll
    for (int h = 0; h < 8; ++h) {
        float s = 0.f;
        #pragma unroll
        for (int k = 0; k < 8; ++k) s += ein[k] * Cs[k * 8 + h];
        ee[h] = s;
    }
    float4* op = (float4*)(g_ee + (long)pos * HEADS);
    op[0] = make_float4(ee[0], ee[1], ee[2], ee[3]);
    op[1] = make_float4(ee[4], ee[5], ee[6], ee[7]);
}

// ---------------- K4f: fused softmax + aggregation, one warp per dst node ----
// Every lane computes p for ITS OWN head (lane>>2): same-address 4-lane loads
// broadcast for free, __expf costs the same per warp either way -> no shfls,
// no predication, s needs no reduction.
__device__ __forceinline__ void accum(float* acc, float a, uint4 r) {
    float2 f0 = __half22float2(*(__half2*)&r.x);
    float2 f1 = __half22float2(*(__half2*)&r.y);
    float2 f2 = __half22float2(*(__half2*)&r.z);
    float2 f3 = __half22float2(*(__half2*)&r.w);
    acc[0] += a * f0.x; acc[1] += a * f0.y;
    acc[2] += a * f1.x; acc[3] += a * f1.y;
    acc[4] += a * f2.x; acc[5] += a * f2.y;
    acc[6] += a * f3.x; acc[7] += a * f3.y;
}

__device__ __forceinline__ float lrelu_exp(float x) {
    x = (x > 0.f) ? x : NEG_SLOPE * x;
    return __expf(x);
}

__global__ __launch_bounds__(256) void k4f(const float* __restrict__ bias,
                                           float* __restrict__ out) {
    __shared__ float sb[HD];
    int t = threadIdx.x;
    sb[t] = bias[t];
    __syncthreads();

    int warp = t >> 5, lane = t & 31;
    int node = blockIdx.x * 8 + warp;
    if (node >= N_NODES) return;

    int beg = g_start[node];
    int end = beg + g_cnt[node];

    const int hsel = lane >> 2;                      // this lane's head
    float er_h = g_er[node * HEADS + hsel];

    float acc[8] = {0.f, 0.f, 0.f, 0.f, 0.f, 0.f, 0.f, 0.f};
    float s = 0.f;

    int j = beg;
    int n0 = 0, n1 = 0, n2 = 0, n3 = 0;
    if (j + 3 < end) {
        n0 = g_osrc[j];     n1 = g_osrc[j + 1];
        n2 = g_osrc[j + 2]; n3 = g_osrc[j + 3];
    }
    while (j + 3 < end) {
        // gathers for current quad (issue first)
        uint4 ra = *(const uint4*)(g_hh + (long)n0 * HD + lane * 8);
        uint4 rb = *(const uint4*)(g_hh + (long)n1 * HD + lane * 8);
        uint4 rc = *(const uint4*)(g_hh + (long)n2 * HD + lane * 8);
        uint4 rd = *(const uint4*)(g_hh + (long)n3 * HD + lane * 8);

        float el0 = g_el[n0 * HEADS + hsel];
        float el1 = g_el[n1 * HEADS + hsel];
        float el2 = g_el[n2 * HEADS + hsel];
        float el3 = g_el[n3 * HEADS + hsel];
        float ee0 = g_ee[(long)(j)     * HEADS + hsel];
        float ee1 = g_ee[(long)(j + 1) * HEADS + hsel];
        float ee2 = g_ee[(long)(j + 2) * HEADS + hsel];
        float ee3 = g_ee[(long)(j + 3) * HEADS + hsel];

        // prefetch next quad's src ids while computing
        int jn = j + 4;
        if (jn + 3 < end) {
            n0 = g_osrc[jn];     n1 = g_osrc[jn + 1];
            n2 = g_osrc[jn + 2]; n3 = g_osrc[jn + 3];
        }

        float p0 = lrelu_exp(el0 + er_h + ee0);
        float p1 = lrelu_exp(el1 + er_h + ee1);
        float p2 = lrelu_exp(el2 + er_h + ee2);
        float p3 = lrelu_exp(el3 + er_h + ee3);
        s += (p0 + p1) + (p2 + p3);

        accum(acc, p0, ra);
        accum(acc, p1, rb);
        accum(acc, p2, rc);
        accum(acc, p3, rd);
        j = jn;
    }
    for (; j < end; ++j) {
        int sn = g_osrc[j];
        uint4 ra = *(const uint4*)(g_hh + (long)sn * HD + lane * 8);
        float el0 = g_el[sn * HEADS + hsel];
        float ee0 = g_ee[(long)j * HEADS + hsel];
        float p0 = lrelu_exp(el0 + er_h + ee0);
        s += p0;
        accum(acc, p0, ra);
    }

    float inv = 1.f / (s + 1e-9f);

    float* op = out + (long)node * HD + lane * 8;
    const float* bp = sb + lane * 8;
    *(float4*)(op)     = make_float4(acc[0] * inv + bp[0], acc[1] * inv + bp[1],
                                     acc[2] * inv + bp[2], acc[3] * inv + bp[3]);
    *(float4*)(op + 4) = make_float4(acc[4] * inv + bp[4], acc[5] * inv + bp[5],
                                     acc[6] * inv + bp[6], acc[7] * inv + bp[7]);
}

// ---------------- launch ------------------------------------------------------
extern "C" void kernel_launch(void* const* d_in, const int* in_sizes, int n_in,
                              void* d_out, int out_size) {
    const float* feat     = (const float*)d_in[0];
    const float* edge_emb = (const float*)d_in[1];
    const int*   src      = (const int*)  d_in[2];
    const int*   dst      = (const int*)  d_in[3];
    const float* W_src    = (const float*)d_in[4];
    const float* W_e      = (const float*)d_in[5];
    const float* attn_l   = (const float*)d_in[6];
    const float* attn_r   = (const float*)d_in[7];
    const float* attn_e   = (const float*)d_in[8];
    const float* bias     = (const float*)d_in[9];
    float* out = (float*)d_out;

    void *cnt_ptr = nullptr, *el_ptr = nullptr, *er_ptr = nullptr;
    cudaGetSymbolAddress(&cnt_ptr, g_cnt);
    cudaGetSymbolAddress(&el_ptr,  g_el);
    cudaGetSymbolAddress(&er_ptr,  g_er);

    cudaMemsetAsync(cnt_ptr, 0, N_NODES * sizeof(int));
    khist     <<<(N_EDGES + 255) / 256, 256>>>(dst, W_e, attn_e);
    kscan_part<<<NB_SCAN, 256>>>();
    kscan_add <<<NB_SCAN, 256>>>();
    kscatter  <<<(N_EDGES + 255) / 256, 256>>>(src, dst, edge_emb);

    kconvB<<<HD, HD>>>(W_src);

    cudaMemsetAsync(el_ptr, 0, N_NODES * HEADS * sizeof(float));
    cudaMemsetAsync(er_ptr, 0, N_NODES * HEADS * sizeof(float));

    dim3 g1((N_NODES + 127) / 128, 2);
    k1_mma<<<g1, 256>>>(feat, attn_l, attn_r);

    k4f<<<(N_NODES + 7) / 8, 256>>>(bias, out);
}

// round 12
// speedup vs baseline: 2.8078x; 1.1118x over previous
#include <cuda_runtime.h>
#include <cuda_bf16.h>
#include <cuda_fp16.h>

#define N_NODES 50000
#define N_EDGES 800000
#define HEADS 8
#define DOUT 32
#define HD 256          // HEADS*DOUT == IN_FEATS == 256
#define NEG_SLOPE 0.2f
#define NB_SCAN 196     // ceil(N_NODES/256)

// ---------------- scratch (static device globals; no allocation) -------------
__device__ float g_h [N_NODES * HD];      // projected node features f32
__device__ __half g_hh[N_NODES * HD];     // projected node features fp16 (gather)
__device__ float g_el[N_NODES * HEADS];
__device__ float g_er[N_NODES * HEADS];
__device__ float g_C [HEADS * HEADS];     // folded W_e * attn_e (k-major)

__device__ __nv_bfloat16 g_Bhi[HD * HD];  // W_src^T split hi  [n][k]
__device__ __nv_bfloat16 g_Blo[HD * HD];  // W_src^T split lo  [n][k]

// CSR-by-dst scratch
__device__ int   g_cnt  [N_NODES];
__device__ int   g_start[N_NODES];
__device__ int   g_cur  [N_NODES];
__device__ int   g_osrc [N_EDGES];        // src ids grouped by dst
__device__ float g_ee   [N_EDGES * HEADS];// edge attention term grouped by dst
__device__ int   g_bsum [NB_SCAN];

// ---------------- conv B: W_src f32 [k][n] -> hi/lo bf16 transposed [n][k] ---
__global__ void kconvB(const float* __restrict__ B) {
    int k = blockIdx.x;
    int n = threadIdx.x;
    float v = B[k * HD + n];
    __nv_bfloat16 h = __float2bfloat16(v);
    __nv_bfloat16 l = __float2bfloat16(v - __bfloat162float(h));
    g_Bhi[n * HD + k] = h;
    g_Blo[n * HD + k] = l;
}

// ---------------- cp.async helpers -------------------------------------------
__device__ __forceinline__ void cp16(unsigned dst, const void* src, bool pred) {
    asm volatile("cp.async.cg.shared.global [%0], [%1], 16, %2;"
                 :: "r"(dst), "l"(src), "r"(pred ? 16 : 0));
}
__device__ __forceinline__ void cp_commit() {
    asm volatile("cp.async.commit_group;");
}
template <int N> __device__ __forceinline__ void cp_wait() {
    asm volatile("cp.async.wait_group %0;" :: "n"(N));
}

__device__ __forceinline__ void mma16816(float* c, const unsigned* a,
                                         unsigned b0, unsigned b1) {
    asm volatile("mma.sync.aligned.m16n8k16.row.col.f32.bf16.bf16.f32 "
                 "{%0,%1,%2,%3}, {%4,%5,%6,%7}, {%8,%9}, {%0,%1,%2,%3};"
                 : "+f"(c[0]), "+f"(c[1]), "+f"(c[2]), "+f"(c[3])
                 : "r"(a[0]), "r"(a[1]), "r"(a[2]), "r"(a[3]), "r"(b0), "r"(b1));
}

// truncation split of 2 consecutive f32 -> packed bf16x2 hi (exact) + lo (rn)
__device__ __forceinline__ void split2(float2 f, unsigned& hi, unsigned& lo) {
    unsigned ux = __float_as_uint(f.x), uy = __float_as_uint(f.y);
    hi = __byte_perm(ux, uy, 0x7632);
    float hx = __uint_as_float(ux & 0xffff0000u);
    float hy = __uint_as_float(uy & 0xffff0000u);
    __nv_bfloat162 l = __floats2bfloat162_rn(f.x - hx, f.y - hy);
    lo = *(unsigned*)&l;
}

// ---------------- K1: split-bf16 tensor-core GEMM + fused el/er --------------
#define BKS  24      // bf16 B row stride
#define BKSF 20      // f32 A row stride
__global__ __launch_bounds__(256, 2) void k1_mma(const float* __restrict__ A,
                                                 const float* __restrict__ attn_l,
                                                 const float* __restrict__ attn_r) {
    __shared__ float         smA [2][128 * BKSF];
    __shared__ __nv_bfloat16 smBh[2][128 * BKS];
    __shared__ __nv_bfloat16 smBl[2][128 * BKS];

    const int t    = threadIdx.x;
    const int warp = t >> 5;
    const int lane = t & 31;
    const int wm   = warp >> 1;
    const int wn   = warp & 1;
    const int bm   = blockIdx.x * 128;
    const int bn   = blockIdx.y * 128;

    const int lr = t >> 1;
    const int lc = (t & 1) * 8;
    const bool arow_ok = (bm + lr) < N_NODES;
    const long a_goff  = (long)(bm + lr) * HD + lc;
    const long b_goff  = (long)(bn + lr) * HD + lc;
    const unsigned sA_off = (unsigned)((lr * BKSF + lc) * sizeof(float));
    const unsigned sB_off = (unsigned)((lr * BKS + lc) * sizeof(__nv_bfloat16));

    unsigned aA[2], aBh[2], aBl[2];
    #pragma unroll
    for (int s = 0; s < 2; ++s) {
        aA [s] = (unsigned)__cvta_generic_to_shared(&smA [s][0]) + sA_off;
        aBh[s] = (unsigned)__cvta_generic_to_shared(&smBh[s][0]) + sB_off;
        aBl[s] = (unsigned)__cvta_generic_to_shared(&smBl[s][0]) + sB_off;
    }

    float acc[2][8][4];
    #pragma unroll
    for (int i = 0; i < 2; ++i)
        #pragma unroll
        for (int j = 0; j < 8; ++j)
            #pragma unroll
            for (int q = 0; q < 4; ++q) acc[i][j][q] = 0.f;

    {
        cp16(aA[0],      A + a_goff,     arow_ok);
        cp16(aA[0] + 16, A + a_goff + 4, arow_ok);
        cp16(aBh[0], g_Bhi + b_goff, true);
        cp16(aBl[0], g_Blo + b_goff, true);
        cp_commit();
    }

    const int qr = lane >> 2;
    const int qc = (lane & 3) * 2;

    #pragma unroll 1
    for (int tile = 0; tile < 16; ++tile) {
        if (tile < 15) {
            int st = (tile + 1) & 1;
            int k0 = (tile + 1) * 16;
            cp16(aA[st],      A + a_goff + k0,     arow_ok);
            cp16(aA[st] + 16, A + a_goff + k0 + 4, arow_ok);
            cp16(aBh[st], g_Bhi + b_goff + k0, true);
            cp16(aBl[st], g_Blo + b_goff + k0, true);
            cp_commit();
            cp_wait<1>();
        } else {
            cp_wait<0>();
        }
        __syncthreads();

        const int st = tile & 1;
        const float* Af = smA[st];
        const __nv_bfloat16* Bh = smBh[st];
        const __nv_bfloat16* Bl = smBl[st];

        unsigned ah[2][4], al[2][4];
        #pragma unroll
        for (int mt = 0; mt < 2; ++mt) {
            int r = wm * 32 + mt * 16 + qr;
            float2 f0 = *(const float2*)(Af + r * BKSF + qc);
            float2 f1 = *(const float2*)(Af + (r + 8) * BKSF + qc);
            float2 f2 = *(const float2*)(Af + r * BKSF + qc + 8);
            float2 f3 = *(const float2*)(Af + (r + 8) * BKSF + qc + 8);
            split2(f0, ah[mt][0], al[mt][0]);
            split2(f1, ah[mt][1], al[mt][1]);
            split2(f2, ah[mt][2], al[mt][2]);
            split2(f3, ah[mt][3], al[mt][3]);
        }

        #pragma unroll
        for (int nt = 0; nt < 8; ++nt) {
            int n = wn * 64 + nt * 8 + qr;
            unsigned bh0 = *(const unsigned*)(Bh + n * BKS + qc);
            unsigned bh1 = *(const unsigned*)(Bh + n * BKS + qc + 8);
            unsigned bl0 = *(const unsigned*)(Bl + n * BKS + qc);
            unsigned bl1 = *(const unsigned*)(Bl + n * BKS + qc + 8);
            #pragma unroll
            for (int mt = 0; mt < 2; ++mt) {
                mma16816(acc[mt][nt], ah[mt], bh0, bh1);
                mma16816(acc[mt][nt], ah[mt], bl0, bl1);
                mma16816(acc[mt][nt], al[mt], bh0, bh1);
            }
        }
        __syncthreads();
    }

    // attention weights for this thread's 16 columns (2 per nt)
    float wl[8][2], wr[8][2];
    #pragma unroll
    for (int nt = 0; nt < 8; ++nt) {
        int cc = bn + wn * 64 + nt * 8 + qc;
        float2 l2 = *(const float2*)(attn_l + cc);
        float2 r2 = *(const float2*)(attn_r + cc);
        wl[nt][0] = l2.x; wl[nt][1] = l2.y;
        wr[nt][0] = r2.x; wr[nt][1] = r2.y;
    }
    const int h0 = (bn + wn * 64) >> 5;

    // epilogue: stores + fused el/er partial reduction
    #pragma unroll
    for (int mt = 0; mt < 2; ++mt) {
        int r0 = bm + wm * 32 + mt * 16 + qr;
        float elA[2] = {0.f, 0.f}, erA[2] = {0.f, 0.f};
        float elB[2] = {0.f, 0.f}, erB[2] = {0.f, 0.f};
        #pragma unroll
        for (int nt = 0; nt < 8; ++nt) {
            int hg = nt >> 2;
            int cc = bn + wn * 64 + nt * 8 + qc;
            if (r0 < N_NODES) {
                *(float2*)(g_h + (long)r0 * HD + cc) =
                    make_float2(acc[mt][nt][0], acc[mt][nt][1]);
                *(__half2*)(g_hh + (long)r0 * HD + cc) =
                    __floats2half2_rn(acc[mt][nt][0], acc[mt][nt][1]);
            }
            if (r0 + 8 < N_NODES) {
                *(float2*)(g_h + (long)(r0 + 8) * HD + cc) =
                    make_float2(acc[mt][nt][2], acc[mt][nt][3]);
                *(__half2*)(g_hh + (long)(r0 + 8) * HD + cc) =
                    __floats2half2_rn(acc[mt][nt][2], acc[mt][nt][3]);
            }
            elA[hg] += acc[mt][nt][0] * wl[nt][0] + acc[mt][nt][1] * wl[nt][1];
            erA[hg] += acc[mt][nt][0] * wr[nt][0] + acc[mt][nt][1] * wr[nt][1];
            elB[hg] += acc[mt][nt][2] * wl[nt][0] + acc[mt][nt][3] * wl[nt][1];
            erB[hg] += acc[mt][nt][2] * wr[nt][0] + acc[mt][nt][3] * wr[nt][1];
        }
        if (r0 < N_NODES) {
            atomicAdd(&g_el[r0 * HEADS + h0],     elA[0]);
            atomicAdd(&g_el[r0 * HEADS + h0 + 1], elA[1]);
            atomicAdd(&g_er[r0 * HEADS + h0],     erA[0]);
            atomicAdd(&g_er[r0 * HEADS + h0 + 1], erA[1]);
        }
        if (r0 + 8 < N_NODES) {
            atomicAdd(&g_el[(r0 + 8) * HEADS + h0],     elB[0]);
            atomicAdd(&g_el[(r0 + 8) * HEADS + h0 + 1], elB[1]);
            atomicAdd(&g_er[(r0 + 8) * HEADS + h0],     erB[0]);
            atomicAdd(&g_er[(r0 + 8) * HEADS + h0 + 1], erB[1]);
        }
    }
}

// ---------------- CSR build ----------------------------------------------------
// khist also computes C = fold(W_e, attn_e) in block 0 (needed by kscatter later)
__global__ void khist(const int* __restrict__ dst,
                      const float* __restrict__ W_e,
                      const float* __restrict__ attn_e) {
    int t = threadIdx.x;
    if (blockIdx.x == 0 && t < 64) {
        int k = t >> 3, h = t & 7;
        float s = 0.f;
        #pragma unroll
        for (int d = 0; d < DOUT; ++d)
            s += W_e[k * HD + h * DOUT + d] * attn_e[h * DOUT + d];
        g_C[k * 8 + h] = s;
    }
    int e = blockIdx.x * 256 + t;
    if (e < N_EDGES) atomicAdd(&g_cnt[dst[e]], 1);
}

__global__ __launch_bounds__(256) void kscan_part() {
    __shared__ int ws[8];
    int t = threadIdx.x, lane = t & 31, w = t >> 5;
    int i = blockIdx.x * 256 + t;
    int v = (i < N_NODES) ? g_cnt[i] : 0;
    int sv = v;
    #pragma unroll
    for (int d = 1; d < 32; d <<= 1) {
        int x = __shfl_up_sync(0xffffffffu, sv, d);
        if (lane >= d) sv += x;
    }
    if (lane == 31) ws[w] = sv;
    __syncthreads();
    if (t < 8) {
        int x = ws[t];
        #pragma unroll
        for (int d = 1; d < 8; d <<= 1) {
            int y = __shfl_up_sync(0xffu, x, d);
            if (t >= d) x += y;
        }
        ws[t] = x;
    }
    __syncthreads();
    int excl = sv - v + ((w > 0) ? ws[w - 1] : 0);
    if (i < N_NODES) g_start[i] = excl;
    if (t == 255) g_bsum[blockIdx.x] = ws[7];
}

// add block offsets (each block reduces g_bsum[0..bid) itself), init cursors
__global__ __launch_bounds__(256) void kscan_add() {
    __shared__ int ws[8];
    __shared__ int offs;
    int t = threadIdx.x, lane = t & 31, w = t >> 5;
    int bid = blockIdx.x;
    int v = (t < bid) ? g_bsum[t] : 0;        // bid <= 195 < 256
    #pragma unroll
    for (int d = 16; d > 0; d >>= 1)
        v += __shfl_xor_sync(0xffffffffu, v, d);
    if (lane == 0) ws[w] = v;
    __syncthreads();
    if (t == 0) {
        int o = 0;
        #pragma unroll
        for (int i = 0; i < 8; ++i) o += ws[i];
        offs = o;
    }
    __syncthreads();
    int i = bid * 256 + t;
    if (i < N_NODES) {
        int s = g_start[i] + offs;
        g_start[i] = s;
        g_cur[i]   = s;
    }
}

// scatter + fold edge_emb @ C into g_ee (grouped by dst)
__global__ __launch_bounds__(256) void kscatter(const int* __restrict__ src,
                                                const int* __restrict__ dst,
                                                const float* __restrict__ edge_emb) {
    __shared__ float Cs[64];
    int t = threadIdx.x;
    if (t < 64) Cs[t] = g_C[t];
    __syncthreads();

    int e = blockIdx.x * 256 + t;
    if (e >= N_EDGES) return;
    int pos = atomicAdd(&g_cur[dst[e]], 1);
    g_osrc[pos] = src[e];

    const float4* ep = (const float4*)(edge_emb + (long)e * HEADS);
    float4 e0 = ep[0], e1 = ep[1];
    float ein[8] = {e0.x, e0.y, e0.z, e0.w, e1.x, e1.y, e1.z, e1.w};
    float ee[8];
    #pragma unroll
    for (int h = 0; h < 8; ++h) {
        float s = 0.f;
        #pragma unroll
        for (int k = 0; k < 8; ++k) s += ein[k] * Cs[k * 8 + h];
        ee[h] = s;
    }
    float4* op = (float4*)(g_ee + (long)pos * HEADS);
    op[0] = make_float4(ee[0], ee[1], ee[2], ee[3]);
    op[1] = make_float4(ee[4], ee[5], ee[6], ee[7]);
}

// ---------------- K4f: fused softmax + aggregation, one warp per dst node ----
__device__ __forceinline__ void accum(float* acc, float a, uint4 r) {
    float2 f0 = __half22float2(*(__half2*)&r.x);
    float2 f1 = __half22float2(*(__half2*)&r.y);
    float2 f2 = __half22float2(*(__half2*)&r.z);
    float2 f3 = __half22float2(*(__half2*)&r.w);
    acc[0] += a * f0.x; acc[1] += a * f0.y;
    acc[2] += a * f1.x; acc[3] += a * f1.y;
    acc[4] += a * f2.x; acc[5] += a * f2.y;
    acc[6] += a * f3.x; acc[7] += a * f3.y;
}

__device__ __forceinline__ float lrelu_exp(float x) {
    x = (x > 0.f) ? x : NEG_SLOPE * x;
    return __expf(x);
}

__global__ __launch_bounds__(256) void k4f(const float* __restrict__ bias,
                                           float* __restrict__ out) {
    __shared__ float sb[HD];
    int t = threadIdx.x;
    sb[t] = bias[t];
    __syncthreads();

    int warp = t >> 5, lane = t & 31;
    int node = blockIdx.x * 8 + warp;
    if (node >= N_NODES) return;

    int beg = g_start[node];
    int end = beg + g_cnt[node];

    const int hsel = lane >> 2;                      // this lane's head
    float er_h = g_er[node * HEADS + hsel];

    float acc[8] = {0.f, 0.f, 0.f, 0.f, 0.f, 0.f, 0.f, 0.f};
    float s = 0.f;

    int j = beg;
    int n0 = 0, n1 = 0, n2 = 0, n3 = 0;
    if (j + 3 < end) {
        n0 = g_osrc[j];     n1 = g_osrc[j + 1];
        n2 = g_osrc[j + 2]; n3 = g_osrc[j + 3];
    }
    while (j + 3 < end) {
        uint4 ra = *(const uint4*)(g_hh + (long)n0 * HD + lane * 8);
        uint4 rb = *(const uint4*)(g_hh + (long)n1 * HD + lane * 8);
        uint4 rc = *(const uint4*)(g_hh + (long)n2 * HD + lane * 8);
        uint4 rd = *(const uint4*)(g_hh + (long)n3 * HD + lane * 8);

        float el0 = g_el[n0 * HEADS + hsel];
        float el1 = g_el[n1 * HEADS + hsel];
        float el2 = g_el[n2 * HEADS + hsel];
        float el3 = g_el[n3 * HEADS + hsel];
        float ee0 = g_ee[(long)(j)     * HEADS + hsel];
        float ee1 = g_ee[(long)(j + 1) * HEADS + hsel];
        float ee2 = g_ee[(long)(j + 2) * HEADS + hsel];
        float ee3 = g_ee[(long)(j + 3) * HEADS + hsel];

        int jn = j + 4;
        if (jn + 3 < end) {
            n0 = g_osrc[jn];     n1 = g_osrc[jn + 1];
            n2 = g_osrc[jn + 2]; n3 = g_osrc[jn + 3];
        }

        float p0 = lrelu_exp(el0 + er_h + ee0);
        float p1 = lrelu_exp(el1 + er_h + ee1);
        float p2 = lrelu_exp(el2 + er_h + ee2);
        float p3 = lrelu_exp(el3 + er_h + ee3);
        s += (p0 + p1) + (p2 + p3);

        accum(acc, p0, ra);
        accum(acc, p1, rb);
        accum(acc, p2, rc);
        accum(acc, p3, rd);
        j = jn;
    }
    for (; j < end; ++j) {
        int sn = g_osrc[j];
        uint4 ra = *(const uint4*)(g_hh + (long)sn * HD + lane * 8);
        float el0 = g_el[sn * HEADS + hsel];
        float ee0 = g_ee[(long)j * HEADS + hsel];
        float p0 = lrelu_exp(el0 + er_h + ee0);
        s += p0;
        accum(acc, p0, ra);
    }

    float inv = 1.f / (s + 1e-9f);

    float* op = out + (long)node * HD + lane * 8;
    const float* bp = sb + lane * 8;
    *(float4*)(op)     = make_float4(acc[0] * inv + bp[0], acc[1] * inv + bp[1],
                                     acc[2] * inv + bp[2], acc[3] * inv + bp[3]);
    *(float4*)(op + 4) = make_float4(acc[4] * inv + bp[4], acc[5] * inv + bp[5],
                                     acc[6] * inv + bp[6], acc[7] * inv + bp[7]);
}

// ---------------- launch: fork CSR chain onto a side stream -------------------
extern "C" void kernel_launch(void* const* d_in, const int* in_sizes, int n_in,
                              void* d_out, int out_size) {
    const float* feat     = (const float*)d_in[0];
    const float* edge_emb = (const float*)d_in[1];
    const int*   src      = (const int*)  d_in[2];
    const int*   dst      = (const int*)  d_in[3];
    const float* W_src    = (const float*)d_in[4];
    const float* W_e      = (const float*)d_in[5];
    const float* attn_l   = (const float*)d_in[6];
    const float* attn_r   = (const float*)d_in[7];
    const float* attn_e   = (const float*)d_in[8];
    const float* bias     = (const float*)d_in[9];
    float* out = (float*)d_out;

    // one-time host resources (created during the un-captured correctness call;
    // the captured work is identical on every call)
    static cudaStream_t s2 = nullptr;
    static cudaEvent_t evFork = nullptr, evJoin = nullptr;
    if (s2 == nullptr) {
        cudaStreamCreateWithFlags(&s2, cudaStreamNonBlocking);
        cudaEventCreateWithFlags(&evFork, cudaEventDisableTiming);
        cudaEventCreateWithFlags(&evJoin, cudaEventDisableTiming);
    }

    void *cnt_ptr = nullptr, *el_ptr = nullptr, *er_ptr = nullptr;
    cudaGetSymbolAddress(&cnt_ptr, g_cnt);
    cudaGetSymbolAddress(&el_ptr,  g_el);
    cudaGetSymbolAddress(&er_ptr,  g_er);

    // fork: CSR chain on s2, GEMM chain on the main (capture) stream
    cudaEventRecord(evFork, 0);
    cudaStreamWaitEvent(s2, evFork, 0);

    // --- s2: CSR build (independent of GEMM) ---
    cudaMemsetAsync(cnt_ptr, 0, N_NODES * sizeof(int), s2);
    khist     <<<(N_EDGES + 255) / 256, 256, 0, s2>>>(dst, W_e, attn_e);
    kscan_part<<<NB_SCAN, 256, 0, s2>>>();
    kscan_add <<<NB_SCAN, 256, 0, s2>>>();
    kscatter  <<<(N_EDGES + 255) / 256, 256, 0, s2>>>(src, dst, edge_emb);
    cudaEventRecord(evJoin, s2);

    // --- main stream: weights conv + GEMM (+ fused el/er) ---
    kconvB<<<HD, HD>>>(W_src);
    cudaMemsetAsync(el_ptr, 0, N_NODES * HEADS * sizeof(float));
    cudaMemsetAsync(er_ptr, 0, N_NODES * HEADS * sizeof(float));
    dim3 g1((N_NODES + 127) / 128, 2);
    k1_mma<<<g1, 256>>>(feat, attn_l, attn_r);

    // join, then fused softmax+aggregation
    cudaStreamWaitEvent(0, evJoin, 0);
    k4f<<<(N_NODES + 7) / 8, 256>>>(bias, out);
}

// round 13
// speedup vs baseline: 3.1741x; 1.1305x over previous
#include <cuda_runtime.h>
#include <cuda_bf16.h>
#include <cuda_fp16.h>

#define N_NODES 50000
#define N_EDGES 800000
#define HEADS 8
#define DOUT 32
#define HD 256          // HEADS*DOUT == IN_FEATS == 256
#define NEG_SLOPE 0.2f
#define NB_SCAN 196     // ceil(N_NODES/256)

// ---------------- scratch (static device globals; no allocation) -------------
__device__ __half g_hh[N_NODES * HD];     // projected node features fp16 (gather)
__device__ float g_el[N_NODES * HEADS];
__device__ float g_er[N_NODES * HEADS];
__device__ float g_C [HEADS * HEADS];     // folded W_e * attn_e (k-major)

__device__ __nv_bfloat16 g_Bhi[HD * HD];  // W_src^T split hi  [n][k]
__device__ __nv_bfloat16 g_Blo[HD * HD];  // W_src^T split lo  [n][k]

// CSR-by-dst scratch
__device__ int   g_cnt  [N_NODES];
__device__ int   g_start[N_NODES];
__device__ int   g_cur  [N_NODES];
__device__ int   g_osrc [N_EDGES];        // src ids grouped by dst
__device__ float g_ee   [N_EDGES * HEADS];// edge attention term grouped by dst
__device__ int   g_bsum [NB_SCAN];

// ---------------- conv B: W_src f32 [k][n] -> hi/lo bf16 transposed [n][k] ---
__global__ void kconvB(const float* __restrict__ B) {
    int k = blockIdx.x;
    int n = threadIdx.x;
    float v = B[k * HD + n];
    __nv_bfloat16 h = __float2bfloat16(v);
    __nv_bfloat16 l = __float2bfloat16(v - __bfloat162float(h));
    g_Bhi[n * HD + k] = h;
    g_Blo[n * HD + k] = l;
}

// ---------------- cp.async helpers -------------------------------------------
__device__ __forceinline__ void cp16(unsigned dst, const void* src, bool pred) {
    asm volatile("cp.async.cg.shared.global [%0], [%1], 16, %2;"
                 :: "r"(dst), "l"(src), "r"(pred ? 16 : 0));
}
__device__ __forceinline__ void cp_commit() {
    asm volatile("cp.async.commit_group;");
}
template <int N> __device__ __forceinline__ void cp_wait() {
    asm volatile("cp.async.wait_group %0;" :: "n"(N));
}

__device__ __forceinline__ void mma16816(float* c, const unsigned* a,
                                         unsigned b0, unsigned b1) {
    asm volatile("mma.sync.aligned.m16n8k16.row.col.f32.bf16.bf16.f32 "
                 "{%0,%1,%2,%3}, {%4,%5,%6,%7}, {%8,%9}, {%0,%1,%2,%3};"
                 : "+f"(c[0]), "+f"(c[1]), "+f"(c[2]), "+f"(c[3])
                 : "r"(a[0]), "r"(a[1]), "r"(a[2]), "r"(a[3]), "r"(b0), "r"(b1));
}

// truncation split of 2 consecutive f32 -> packed bf16x2 hi (exact) + lo (rn)
__device__ __forceinline__ void split2(float2 f, unsigned& hi, unsigned& lo) {
    unsigned ux = __float_as_uint(f.x), uy = __float_as_uint(f.y);
    hi = __byte_perm(ux, uy, 0x7632);
    float hx = __uint_as_float(ux & 0xffff0000u);
    float hy = __uint_as_float(uy & 0xffff0000u);
    __nv_bfloat162 l = __floats2bfloat162_rn(f.x - hx, f.y - hy);
    lo = *(unsigned*)&l;
}

// ---------------- K1: split-bf16 tensor-core GEMM + fused el/er --------------
// 3-stage cp.async pipeline, dynamic smem. No f32 h output; el/er via
// quad-shfl reduction + plain stores (no atomics, no memset).
#define BKS   24      // bf16 B row stride
#define BKSF  20      // f32 A row stride
#define A_ST  (128 * BKSF)            // floats per A stage
#define B_ST  (128 * BKS)             // bf16 per B stage
#define SMEM_K1 (3 * A_ST * 4 + 3 * B_ST * 2 * 2)   // 67584 bytes

__global__ __launch_bounds__(256, 2) void k1_mma(const float* __restrict__ A,
                                                 const float* __restrict__ attn_l,
                                                 const float* __restrict__ attn_r) {
    extern __shared__ char dsm[];
    float*         smA  = (float*)dsm;                         // 3 stages
    __nv_bfloat16* smBh = (__nv_bfloat16*)(dsm + 3 * A_ST * 4);
    __nv_bfloat16* smBl = smBh + 3 * B_ST;

    const int t    = threadIdx.x;
    const int warp = t >> 5;
    const int lane = t & 31;
    const int wm   = warp >> 1;
    const int wn   = warp & 1;
    const int bm   = blockIdx.x * 128;
    const int bn   = blockIdx.y * 128;

    const int lr = t >> 1;
    const int lc = (t & 1) * 8;
    const bool arow_ok = (bm + lr) < N_NODES;
    const long a_goff  = (long)(bm + lr) * HD + lc;
    const long b_goff  = (long)(bn + lr) * HD + lc;
    const unsigned sA_off = (unsigned)((lr * BKSF + lc) * sizeof(float));
    const unsigned sB_off = (unsigned)((lr * BKS + lc) * sizeof(__nv_bfloat16));

    unsigned aA[3], aBh[3], aBl[3];
    #pragma unroll
    for (int s = 0; s < 3; ++s) {
        aA [s] = (unsigned)__cvta_generic_to_shared(smA  + s * A_ST) + sA_off;
        aBh[s] = (unsigned)__cvta_generic_to_shared(smBh + s * B_ST) + sB_off;
        aBl[s] = (unsigned)__cvta_generic_to_shared(smBl + s * B_ST) + sB_off;
    }

    float acc[2][8][4];
    #pragma unroll
    for (int i = 0; i < 2; ++i)
        #pragma unroll
        for (int j = 0; j < 8; ++j)
            #pragma unroll
            for (int q = 0; q < 4; ++q) acc[i][j][q] = 0.f;

    // prologue: tiles 0 and 1
    #pragma unroll
    for (int pt = 0; pt < 2; ++pt) {
        int k0 = pt * 16;
        cp16(aA[pt],      A + a_goff + k0,     arow_ok);
        cp16(aA[pt] + 16, A + a_goff + k0 + 4, arow_ok);
        cp16(aBh[pt], g_Bhi + b_goff + k0, true);
        cp16(aBl[pt], g_Blo + b_goff + k0, true);
        cp_commit();
    }

    const int qr = lane >> 2;
    const int qc = (lane & 3) * 2;

    #pragma unroll 1
    for (int tile = 0; tile < 16; ++tile) {
        if (tile + 2 < 16) {
            int st = (tile + 2) % 3;
            int k0 = (tile + 2) * 16;
            cp16(aA[st],      A + a_goff + k0,     arow_ok);
            cp16(aA[st] + 16, A + a_goff + k0 + 4, arow_ok);
            cp16(aBh[st], g_Bhi + b_goff + k0, true);
            cp16(aBl[st], g_Blo + b_goff + k0, true);
            cp_commit();
            cp_wait<2>();
        } else if (tile == 14) {
            cp_wait<1>();
        } else {
            cp_wait<0>();
        }
        __syncthreads();

        const int st = tile % 3;
        const float* Af = smA + st * A_ST;
        const __nv_bfloat16* Bh = smBh + st * B_ST;
        const __nv_bfloat16* Bl = smBl + st * B_ST;

        unsigned ah[2][4], al[2][4];
        #pragma unroll
        for (int mt = 0; mt < 2; ++mt) {
            int r = wm * 32 + mt * 16 + qr;
            float2 f0 = *(const float2*)(Af + r * BKSF + qc);
            float2 f1 = *(const float2*)(Af + (r + 8) * BKSF + qc);
            float2 f2 = *(const float2*)(Af + r * BKSF + qc + 8);
            float2 f3 = *(const float2*)(Af + (r + 8) * BKSF + qc + 8);
            split2(f0, ah[mt][0], al[mt][0]);
            split2(f1, ah[mt][1], al[mt][1]);
            split2(f2, ah[mt][2], al[mt][2]);
            split2(f3, ah[mt][3], al[mt][3]);
        }

        #pragma unroll
        for (int nt = 0; nt < 8; ++nt) {
            int n = wn * 64 + nt * 8 + qr;
            unsigned bh0 = *(const unsigned*)(Bh + n * BKS + qc);
            unsigned bh1 = *(const unsigned*)(Bh + n * BKS + qc + 8);
            unsigned bl0 = *(const unsigned*)(Bl + n * BKS + qc);
            unsigned bl1 = *(const unsigned*)(Bl + n * BKS + qc + 8);
            #pragma unroll
            for (int mt = 0; mt < 2; ++mt) {
                mma16816(acc[mt][nt], ah[mt], bh0, bh1);
                mma16816(acc[mt][nt], ah[mt], bl0, bl1);
                mma16816(acc[mt][nt], al[mt], bh0, bh1);
            }
        }
        __syncthreads();
    }

    // attention weights for this thread's 16 columns (2 per nt)
    float wl[8][2], wr[8][2];
    #pragma unroll
    for (int nt = 0; nt < 8; ++nt) {
        int cc = bn + wn * 64 + nt * 8 + qc;
        float2 l2 = *(const float2*)(attn_l + cc);
        float2 r2 = *(const float2*)(attn_r + cc);
        wl[nt][0] = l2.x; wl[nt][1] = l2.y;
        wr[nt][0] = r2.x; wr[nt][1] = r2.y;
    }
    const int h0 = (bn + wn * 64) >> 5;    // even; this warp owns heads h0,h0+1

    // epilogue: fp16 stores + quad-reduced el/er plain stores
    #pragma unroll
    for (int mt = 0; mt < 2; ++mt) {
        int r0 = bm + wm * 32 + mt * 16 + qr;
        float elA[2] = {0.f, 0.f}, erA[2] = {0.f, 0.f};
        float elB[2] = {0.f, 0.f}, erB[2] = {0.f, 0.f};
        #pragma unroll
        for (int nt = 0; nt < 8; ++nt) {
            int hg = nt >> 2;
            int cc = bn + wn * 64 + nt * 8 + qc;
            if (r0 < N_NODES)
                *(__half2*)(g_hh + (long)r0 * HD + cc) =
                    __floats2half2_rn(acc[mt][nt][0], acc[mt][nt][1]);
            if (r0 + 8 < N_NODES)
                *(__half2*)(g_hh + (long)(r0 + 8) * HD + cc) =
                    __floats2half2_rn(acc[mt][nt][2], acc[mt][nt][3]);
            elA[hg] += acc[mt][nt][0] * wl[nt][0] + acc[mt][nt][1] * wl[nt][1];
            erA[hg] += acc[mt][nt][0] * wr[nt][0] + acc[mt][nt][1] * wr[nt][1];
            elB[hg] += acc[mt][nt][2] * wl[nt][0] + acc[mt][nt][3] * wl[nt][1];
            erB[hg] += acc[mt][nt][2] * wr[nt][0] + acc[mt][nt][3] * wr[nt][1];
        }
        // reduce across the 4 lanes of this quad (same qr, lane&3 = 0..3)
        #pragma unroll
        for (int d = 1; d < 4; d <<= 1) {
            elA[0] += __shfl_xor_sync(0xffffffffu, elA[0], d);
            elA[1] += __shfl_xor_sync(0xffffffffu, elA[1], d);
            erA[0] += __shfl_xor_sync(0xffffffffu, erA[0], d);
            erA[1] += __shfl_xor_sync(0xffffffffu, erA[1], d);
            elB[0] += __shfl_xor_sync(0xffffffffu, elB[0], d);
            elB[1] += __shfl_xor_sync(0xffffffffu, elB[1], d);
            erB[0] += __shfl_xor_sync(0xffffffffu, erB[0], d);
            erB[1] += __shfl_xor_sync(0xffffffffu, erB[1], d);
        }
        if ((lane & 3) == 0) {
            if (r0 < N_NODES) {
                *(float2*)(g_el + r0 * HEADS + h0) = make_float2(elA[0], elA[1]);
                *(float2*)(g_er + r0 * HEADS + h0) = make_float2(erA[0], erA[1]);
            }
            if (r0 + 8 < N_NODES) {
                *(float2*)(g_el + (r0 + 8) * HEADS + h0) = make_float2(elB[0], elB[1]);
                *(float2*)(g_er + (r0 + 8) * HEADS + h0) = make_float2(erB[0], erB[1]);
            }
        }
    }
}

// ---------------- CSR build ----------------------------------------------------
// khist also computes C = fold(W_e, attn_e) in block 0 (needed by kscatter later)
__global__ void khist(const int* __restrict__ dst,
                      const float* __restrict__ W_e,
                      const float* __restrict__ attn_e) {
    int t = threadIdx.x;
    if (blockIdx.x == 0 && t < 64) {
        int k = t >> 3, h = t & 7;
        float s = 0.f;
        #pragma unroll
        for (int d = 0; d < DOUT; ++d)
            s += W_e[k * HD + h * DOUT + d] * attn_e[h * DOUT + d];
        g_C[k * 8 + h] = s;
    }
    int e = blockIdx.x * 256 + t;
    if (e < N_EDGES) atomicAdd(&g_cnt[dst[e]], 1);
}

__global__ __launch_bounds__(256) void kscan_part() {
    __shared__ int ws[8];
    int t = threadIdx.x, lane = t & 31, w = t >> 5;
    int i = blockIdx.x * 256 + t;
    int v = (i < N_NODES) ? g_cnt[i] : 0;
    int sv = v;
    #pragma unroll
    for (int d = 1; d < 32; d <<= 1) {
        int x = __shfl_up_sync(0xffffffffu, sv, d);
        if (lane >= d) sv += x;
    }
    if (lane == 31) ws[w] = sv;
    __syncthreads();
    if (t < 8) {
        int x = ws[t];
        #pragma unroll
        for (int d = 1; d < 8; d <<= 1) {
            int y = __shfl_up_sync(0xffu, x, d);
            if (t >= d) x += y;
        }
        ws[t] = x;
    }
    __syncthreads();
    int excl = sv - v + ((w > 0) ? ws[w - 1] : 0);
    if (i < N_NODES) g_start[i] = excl;
    if (t == 255) g_bsum[blockIdx.x] = ws[7];
}

// add block offsets (each block reduces g_bsum[0..bid) itself), init cursors
__global__ __launch_bounds__(256) void kscan_add() {
    __shared__ int ws[8];
    __shared__ int offs;
    int t = threadIdx.x, lane = t & 31, w = t >> 5;
    int bid = blockIdx.x;
    int v = (t < bid) ? g_bsum[t] : 0;        // bid <= 195 < 256
    #pragma unroll
    for (int d = 16; d > 0; d >>= 1)
        v += __shfl_xor_sync(0xffffffffu, v, d);
    if (lane == 0) ws[w] = v;
    __syncthreads();
    if (t == 0) {
        int o = 0;
        #pragma unroll
        for (int i = 0; i < 8; ++i) o += ws[i];
        offs = o;
    }
    __syncthreads();
    int i = bid * 256 + t;
    if (i < N_NODES) {
        int s = g_start[i] + offs;
        g_start[i] = s;
        g_cur[i]   = s;
    }
}

// scatter + fold edge_emb @ C into g_ee (grouped by dst)
__global__ __launch_bounds__(256) void kscatter(const int* __restrict__ src,
                                                const int* __restrict__ dst,
                                                const float* __restrict__ edge_emb) {
    __shared__ float Cs[64];
    int t = threadIdx.x;
    if (t < 64) Cs[t] = g_C[t];
    __syncthreads();

    int e = blockIdx.x * 256 + t;
    if (e >= N_EDGES) return;
    int pos = atomicAdd(&g_cur[dst[e]], 1);
    g_osrc[pos] = src[e];

    const float4* ep = (const float4*)(edge_emb + (long)e * HEADS);
    float4 e0 = ep[0], e1 = ep[1];
    float ein[8] = {e0.x, e0.y, e0.z, e0.w, e1.x, e1.y, e1.z, e1.w};
    float ee[8];
    #pragma unroll
    for (int h = 0; h < 8; ++h) {
        float s = 0.f;
        #pragma unroll
        for (int k = 0; k < 8; ++k) s += ein[k] * Cs[k * 8 + h];
        ee[h] = s;
    }
    float4* op = (float4*)(g_ee + (long)pos * HEADS);
    op[0] = make_float4(ee[0], ee[1], ee[2], ee[3]);
    op[1] = make_float4(ee[4], ee[5], ee[6], ee[7]);
}

// ---------------- K4f: fused softmax + aggregation, one warp per dst node ----
__device__ __forceinline__ void accum(float* acc, float a, uint4 r) {
    float2 f0 = __half22float2(*(__half2*)&r.x);
    float2 f1 = __half22float2(*(__half2*)&r.y);
    float2 f2 = __half22float2(*(__half2*)&r.z);
    float2 f3 = __half22float2(*(__half2*)&r.w);
    acc[0] += a * f0.x; acc[1] += a * f0.y;
    acc[2] += a * f1.x; acc[3] += a * f1.y;
    acc[4] += a * f2.x; acc[5] += a * f2.y;
    acc[6] += a * f3.x; acc[7] += a * f3.y;
}

__device__ __forceinline__ float lrelu_exp(float x) {
    x = (x > 0.f) ? x : NEG_SLOPE * x;
    return __expf(x);
}

__global__ __launch_bounds__(256) void k4f(const float* __restrict__ bias,
                                           float* __restrict__ out) {
    __shared__ float sb[HD];
    int t = threadIdx.x;
    sb[t] = bias[t];
    __syncthreads();

    int warp = t >> 5, lane = t & 31;
    int node = blockIdx.x * 8 + warp;
    if (node >= N_NODES) return;

    int beg = g_start[node];
    int end = beg + g_cnt[node];

    const int hsel = lane >> 2;
    float er_h = g_er[node * HEADS + hsel];

    float acc[8] = {0.f, 0.f, 0.f, 0.f, 0.f, 0.f, 0.f, 0.f};
    float s = 0.f;

    int j = beg;
    int n0 = 0, n1 = 0, n2 = 0, n3 = 0;
    if (j + 3 < end) {
        n0 = g_osrc[j];     n1 = g_osrc[j + 1];
        n2 = g_osrc[j + 2]; n3 = g_osrc[j + 3];
    }
    while (j + 3 < end) {
        uint4 ra = *(const uint4*)(g_hh + (long)n0 * HD + lane * 8);
        uint4 rb = *(const uint4*)(g_hh + (long)n1 * HD + lane * 8);
        uint4 rc = *(const uint4*)(g_hh + (long)n2 * HD + lane * 8);
        uint4 rd = *(const uint4*)(g_hh + (long)n3 * HD + lane * 8);

        float el0 = g_el[n0 * HEADS + hsel];
        float el1 = g_el[n1 * HEADS + hsel];
        float el2 = g_el[n2 * HEADS + hsel];
        float el3 = g_el[n3 * HEADS + hsel];
        float ee0 = g_ee[(long)(j)     * HEADS + hsel];
        float ee1 = g_ee[(long)(j + 1) * HEADS + hsel];
        float ee2 = g_ee[(long)(j + 2) * HEADS + hsel];
        float ee3 = g_ee[(long)(j + 3) * HEADS + hsel];

        int jn = j + 4;
        if (jn + 3 < end) {
            n0 = g_osrc[jn];     n1 = g_osrc[jn + 1];
            n2 = g_osrc[jn + 2]; n3 = g_osrc[jn + 3];
        }

        float p0 = lrelu_exp(el0 + er_h + ee0);
        float p1 = lrelu_exp(el1 + er_h + ee1);
        float p2 = lrelu_exp(el2 + er_h + ee2);
        float p3 = lrelu_exp(el3 + er_h + ee3);
        s += (p0 + p1) + (p2 + p3);

        accum(acc, p0, ra);
        accum(acc, p1, rb);
        accum(acc, p2, rc);
        accum(acc, p3, rd);
        j = jn;
    }
    for (; j < end; ++j) {
        int sn = g_osrc[j];
        uint4 ra = *(const uint4*)(g_hh + (long)sn * HD + lane * 8);
        float el0 = g_el[sn * HEADS + hsel];
        float ee0 = g_ee[(long)j * HEADS + hsel];
        float p0 = lrelu_exp(el0 + er_h + ee0);
        s += p0;
        accum(acc, p0, ra);
    }

    float inv = 1.f / (s + 1e-9f);

    float* op = out + (long)node * HD + lane * 8;
    const float* bp = sb + lane * 8;
    *(float4*)(op)     = make_float4(acc[0] * inv + bp[0], acc[1] * inv + bp[1],
                                     acc[2] * inv + bp[2], acc[3] * inv + bp[3]);
    *(float4*)(op + 4) = make_float4(acc[4] * inv + bp[4], acc[5] * inv + bp[5],
                                     acc[6] * inv + bp[6], acc[7] * inv + bp[7]);
}

// ---------------- launch: fork CSR chain onto a side stream -------------------
extern "C" void kernel_launch(void* const* d_in, const int* in_sizes, int n_in,
                              void* d_out, int out_size) {
    const float* feat     = (const float*)d_in[0];
    const float* edge_emb = (const float*)d_in[1];
    const int*   src      = (const int*)  d_in[2];
    const int*   dst      = (const int*)  d_in[3];
    const float* W_src    = (const float*)d_in[4];
    const float* W_e      = (const float*)d_in[5];
    const float* attn_l   = (const float*)d_in[6];
    const float* attn_r   = (const float*)d_in[7];
    const float* attn_e   = (const float*)d_in[8];
    const float* bias     = (const float*)d_in[9];
    float* out = (float*)d_out;

    static cudaStream_t s2 = nullptr;
    static cudaEvent_t evFork = nullptr, evJoin = nullptr;
    if (s2 == nullptr) {
        cudaStreamCreateWithFlags(&s2, cudaStreamNonBlocking);
        cudaEventCreateWithFlags(&evFork, cudaEventDisableTiming);
        cudaEventCreateWithFlags(&evJoin, cudaEventDisableTiming);
        cudaFuncSetAttribute(k1_mma, cudaFuncAttributeMaxDynamicSharedMemorySize,
                             SMEM_K1);
    }

    void* cnt_ptr = nullptr;
    cudaGetSymbolAddress(&cnt_ptr, g_cnt);

    // fork: CSR chain on s2, GEMM chain on the main (capture) stream
    cudaEventRecord(evFork, 0);
    cudaStreamWaitEvent(s2, evFork, 0);

    // --- s2: CSR build (independent of GEMM) ---
    cudaMemsetAsync(cnt_ptr, 0, N_NODES * sizeof(int), s2);
    khist     <<<(N_EDGES + 255) / 256, 256, 0, s2>>>(dst, W_e, attn_e);
    kscan_part<<<NB_SCAN, 256, 0, s2>>>();
    kscan_add <<<NB_SCAN, 256, 0, s2>>>();
    kscatter  <<<(N_EDGES + 255) / 256, 256, 0, s2>>>(src, dst, edge_emb);
    cudaEventRecord(evJoin, s2);

    // --- main stream: weights conv + GEMM (+ fused el/er) ---
    kconvB<<<HD, HD>>>(W_src);
    dim3 g1((N_NODES + 127) / 128, 2);
    k1_mma<<<g1, 256, SMEM_K1>>>(feat, attn_l, attn_r);

    // join, then fused softmax+aggregation
    cudaStreamWaitEvent(0, evJoin, 0);
    k4f<<<(N_NODES + 7) / 8, 256>>>(bias, out);
}

// round 15
// speedup vs baseline: 3.2918x; 1.0371x over previous
#include <cuda_runtime.h>
#include <cuda_bf16.h>
#include <cuda_fp16.h>

#define N_NODES 50000
#define N_EDGES 800000
#define HEADS 8
#define DOUT 32
#define HD 256          // HEADS*DOUT == IN_FEATS == 256
#define NEG_SLOPE 0.2f
#define NB_SCAN 196     // ceil(N_NODES/256)

// ---------------- scratch (static device globals; no allocation) -------------
__device__ __half g_hh[N_NODES * HD];     // projected node features fp16 (gather)
__device__ float g_el[N_NODES * HEADS];
__device__ float g_er[N_NODES * HEADS];
__device__ float g_C [HEADS * HEADS];     // folded W_e * attn_e (k-major)

__device__ __nv_bfloat16 g_Bhi[HD * HD];  // W_src^T split hi  [n][k]
__device__ __nv_bfloat16 g_Blo[HD * HD];  // W_src^T split lo  [n][k]

// CSR-by-dst scratch
__device__ int    g_cnt  [N_NODES];
__device__ int    g_start[N_NODES + 1];   // +1: sentinel = N_EDGES
__device__ int    g_cur  [N_NODES];
__device__ int    g_osrc [N_EDGES];       // src ids grouped by dst
__device__ __half g_eeh  [N_EDGES * HEADS];// edge attention term (fp16), grouped
__device__ int    g_bsum [NB_SCAN];

// ---------------- conv B: W_src f32 [k][n] -> hi/lo bf16 transposed [n][k] ---
__global__ void kconvB(const float* __restrict__ B) {
    int k = blockIdx.x;
    int n = threadIdx.x;
    float v = B[k * HD + n];
    __nv_bfloat16 h = __float2bfloat16(v);
    __nv_bfloat16 l = __float2bfloat16(v - __bfloat162float(h));
    g_Bhi[n * HD + k] = h;
    g_Blo[n * HD + k] = l;
}

// ---------------- cp.async helpers -------------------------------------------
__device__ __forceinline__ void cp16(unsigned dst, const void* src, bool pred) {
    asm volatile("cp.async.cg.shared.global [%0], [%1], 16, %2;"
                 :: "r"(dst), "l"(src), "r"(pred ? 16 : 0));
}
__device__ __forceinline__ void cp_commit() {
    asm volatile("cp.async.commit_group;");
}
template <int N> __device__ __forceinline__ void cp_wait() {
    asm volatile("cp.async.wait_group %0;" :: "n"(N));
}

__device__ __forceinline__ void mma16816(float* c, const unsigned* a,
                                         unsigned b0, unsigned b1) {
    asm volatile("mma.sync.aligned.m16n8k16.row.col.f32.bf16.bf16.f32 "
                 "{%0,%1,%2,%3}, {%4,%5,%6,%7}, {%8,%9}, {%0,%1,%2,%3};"
                 : "+f"(c[0]), "+f"(c[1]), "+f"(c[2]), "+f"(c[3])
                 : "r"(a[0]), "r"(a[1]), "r"(a[2]), "r"(a[3]), "r"(b0), "r"(b1));
}

// truncation split of 2 consecutive f32 -> packed bf16x2 hi (exact) + lo (rn)
__device__ __forceinline__ void split2(float2 f, unsigned& hi, unsigned& lo) {
    unsigned ux = __float_as_uint(f.x), uy = __float_as_uint(f.y);
    hi = __byte_perm(ux, uy, 0x7632);
    float hx = __uint_as_float(ux & 0xffff0000u);
    float hy = __uint_as_float(uy & 0xffff0000u);
    __nv_bfloat162 l = __floats2bfloat162_rn(f.x - hx, f.y - hy);
    lo = *(unsigned*)&l;
}

// ---------------- K1: split-bf16 tensor-core GEMM + fused el/er --------------
// 4-stage cp.async pipeline (distance 3), dynamic smem 90 KB, 2 CTAs/SM.
#define BKS   24      // bf16 B row stride
#define BKSF  20      // f32 A row stride
#define A_ST  (128 * BKSF)            // floats per A stage
#define B_ST  (128 * BKS)             // bf16 per B stage
#define NSTG  4
#define SMEM_K1 (NSTG * A_ST * 4 + NSTG * B_ST * 2 * 2)   // 90112 bytes

__global__ __launch_bounds__(256, 2) void k1_mma(const float* __restrict__ A,
                                                 const float* __restrict__ attn_l,
                                                 const float* __restrict__ attn_r) {
    extern __shared__ char dsm[];
    float*         smA  = (float*)dsm;                         // NSTG stages
    __nv_bfloat16* smBh = (__nv_bfloat16*)(dsm + NSTG * A_ST * 4);
    __nv_bfloat16* smBl = smBh + NSTG * B_ST;

    const int t    = threadIdx.x;
    const int warp = t >> 5;
    const int lane = t & 31;
    const int wm   = warp >> 1;
    const int wn   = warp & 1;
    const int bm   = blockIdx.x * 128;
    const int bn   = blockIdx.y * 128;

    const int lr = t >> 1;
    const int lc = (t & 1) * 8;
    const bool arow_ok = (bm + lr) < N_NODES;
    const long a_goff  = (long)(bm + lr) * HD + lc;
    const long b_goff  = (long)(bn + lr) * HD + lc;
    const unsigned sA_off = (unsigned)((lr * BKSF + lc) * sizeof(float));
    const unsigned sB_off = (unsigned)((lr * BKS + lc) * sizeof(__nv_bfloat16));

    unsigned aA[NSTG], aBh[NSTG], aBl[NSTG];
    #pragma unroll
    for (int s = 0; s < NSTG; ++s) {
        aA [s] = (unsigned)__cvta_generic_to_shared(smA  + s * A_ST) + sA_off;
        aBh[s] = (unsigned)__cvta_generic_to_shared(smBh + s * B_ST) + sB_off;
        aBl[s] = (unsigned)__cvta_generic_to_shared(smBl + s * B_ST) + sB_off;
    }

    float acc[2][8][4];
    #pragma unroll
    for (int i = 0; i < 2; ++i)
        #pragma unroll
        for (int j = 0; j < 8; ++j)
            #pragma unroll
            for (int q = 0; q < 4; ++q) acc[i][j][q] = 0.f;

    // prologue: tiles 0..2
    #pragma unroll
    for (int pt = 0; pt < 3; ++pt) {
        int k0 = pt * 16;
        cp16(aA[pt],      A + a_goff + k0,     arow_ok);
        cp16(aA[pt] + 16, A + a_goff + k0 + 4, arow_ok);
        cp16(aBh[pt], g_Bhi + b_goff + k0, true);
        cp16(aBl[pt], g_Blo + b_goff + k0, true);
        cp_commit();
    }

    const int qr = lane >> 2;
    const int qc = (lane & 3) * 2;

    #pragma unroll 1
    for (int tile = 0; tile < 16; ++tile) {
        if (tile + 3 < 16) {
            int st = (tile + 3) & 3;
            int k0 = (tile + 3) * 16;
            cp16(aA[st],      A + a_goff + k0,     arow_ok);
            cp16(aA[st] + 16, A + a_goff + k0 + 4, arow_ok);
            cp16(aBh[st], g_Bhi + b_goff + k0, true);
            cp16(aBl[st], g_Blo + b_goff + k0, true);
            cp_commit();
            cp_wait<3>();
        } else if (tile == 13) {
            cp_wait<2>();
        } else if (tile == 14) {
            cp_wait<1>();
        } else {
            cp_wait<0>();
        }
        __syncthreads();

        const int st = tile & 3;
        const float* Af = smA + st * A_ST;
        const __nv_bfloat16* Bh = smBh + st * B_ST;
        const __nv_bfloat16* Bl = smBl + st * B_ST;

        unsigned ah[2][4], al[2][4];
        #pragma unroll
        for (int mt = 0; mt < 2; ++mt) {
            int r = wm * 32 + mt * 16 + qr;
            float2 f0 = *(const float2*)(Af + r * BKSF + qc);
            float2 f1 = *(const float2*)(Af + (r + 8) * BKSF + qc);
            float2 f2 = *(const float2*)(Af + r * BKSF + qc + 8);
            float2 f3 = *(const float2*)(Af + (r + 8) * BKSF + qc + 8);
            split2(f0, ah[mt][0], al[mt][0]);
            split2(f1, ah[mt][1], al[mt][1]);
            split2(f2, ah[mt][2], al[mt][2]);
            split2(f3, ah[mt][3], al[mt][3]);
        }

        #pragma unroll
        for (int nt = 0; nt < 8; ++nt) {
            int n = wn * 64 + nt * 8 + qr;
            unsigned bh0 = *(const unsigned*)(Bh + n * BKS + qc);
            unsigned bh1 = *(const unsigned*)(Bh + n * BKS + qc + 8);
            unsigned bl0 = *(const unsigned*)(Bl + n * BKS + qc);
            unsigned bl1 = *(const unsigned*)(Bl + n * BKS + qc + 8);
            #pragma unroll
            for (int mt = 0; mt < 2; ++mt) {
                mma16816(acc[mt][nt], ah[mt], bh0, bh1);
                mma16816(acc[mt][nt], ah[mt], bl0, bl1);
                mma16816(acc[mt][nt], al[mt], bh0, bh1);
            }
        }
        __syncthreads();
    }

    // attention weights for this thread's 16 columns (2 per nt)
    float wl[8][2], wr[8][2];
    #pragma unroll
    for (int nt = 0; nt < 8; ++nt) {
        int cc = bn + wn * 64 + nt * 8 + qc;
        float2 l2 = *(const float2*)(attn_l + cc);
        float2 r2 = *(const float2*)(attn_r + cc);
        wl[nt][0] = l2.x; wl[nt][1] = l2.y;
        wr[nt][0] = r2.x; wr[nt][1] = r2.y;
    }
    const int h0 = (bn + wn * 64) >> 5;    // even; this warp owns heads h0,h0+1

    // epilogue: fp16 stores + quad-reduced el/er plain stores
    #pragma unroll
    for (int mt = 0; mt < 2; ++mt) {
        int r0 = bm + wm * 32 + mt * 16 + qr;
        float elA[2] = {0.f, 0.f}, erA[2] = {0.f, 0.f};
        float elB[2] = {0.f, 0.f}, erB[2] = {0.f, 0.f};
        #pragma unroll
        for (int nt = 0; nt < 8; ++nt) {
            int hg = nt >> 2;
            int cc = bn + wn * 64 + nt * 8 + qc;
            if (r0 < N_NODES)
                *(__half2*)(g_hh + (long)r0 * HD + cc) =
                    __floats2half2_rn(acc[mt][nt][0], acc[mt][nt][1]);
            if (r0 + 8 < N_NODES)
                *(__half2*)(g_hh + (long)(r0 + 8) * HD + cc) =
                    __floats2half2_rn(acc[mt][nt][2], acc[mt][nt][3]);
            elA[hg] += acc[mt][nt][0] * wl[nt][0] + acc[mt][nt][1] * wl[nt][1];
            erA[hg] += acc[mt][nt][0] * wr[nt][0] + acc[mt][nt][1] * wr[nt][1];
            elB[hg] += acc[mt][nt][2] * wl[nt][0] + acc[mt][nt][3] * wl[nt][1];
            erB[hg] += acc[mt][nt][2] * wr[nt][0] + acc[mt][nt][3] * wr[nt][1];
        }
        #pragma unroll
        for (int d = 1; d < 4; d <<= 1) {
            elA[0] += __shfl_xor_sync(0xffffffffu, elA[0], d);
            elA[1] += __shfl_xor_sync(0xffffffffu, elA[1], d);
            erA[0] += __shfl_xor_sync(0xffffffffu, erA[0], d);
            erA[1] += __shfl_xor_sync(0xffffffffu, erA[1], d);
            elB[0] += __shfl_xor_sync(0xffffffffu, elB[0], d);
            elB[1] += __shfl_xor_sync(0xffffffffu, elB[1], d);
            erB[0] += __shfl_xor_sync(0xffffffffu, erB[0], d);
            erB[1] += __shfl_xor_sync(0xffffffffu, erB[1], d);
        }
        if ((lane & 3) == 0) {
            if (r0 < N_NODES) {
                *(float2*)(g_el + r0 * HEADS + h0) = make_float2(elA[0], elA[1]);
                *(float2*)(g_er + r0 * HEADS + h0) = make_float2(erA[0], erA[1]);
            }
            if (r0 + 8 < N_NODES) {
                *(float2*)(g_el + (r0 + 8) * HEADS + h0) = make_float2(elB[0], elB[1]);
                *(float2*)(g_er + (r0 + 8) * HEADS + h0) = make_float2(erB[0], erB[1]);
            }
        }
    }
}

// ---------------- CSR build ----------------------------------------------------
// khist also computes C = fold(W_e, attn_e) in block 0 (needed by kscatter later)
__global__ void khist(const int* __restrict__ dst,
                      const float* __restrict__ W_e,
                      const float* __restrict__ attn_e) {
    int t = threadIdx.x;
    if (blockIdx.x == 0 && t < 64) {
        int k = t >> 3, h = t & 7;
        float s = 0.f;
        #pragma unroll
        for (int d = 0; d < DOUT; ++d)
            s += W_e[k * HD + h * DOUT + d] * attn_e[h * DOUT + d];
        g_C[k * 8 + h] = s;
    }
    int e = blockIdx.x * 256 + t;
    if (e < N_EDGES) atomicAdd(&g_cnt[dst[e]], 1);
}

// per-block scan; also zeroes g_cnt after reading (self-restoring for replay)
__global__ __launch_bounds__(256) void kscan_part() {
    __shared__ int ws[8];
    int t = threadIdx.x, lane = t & 31, w = t >> 5;
    int i = blockIdx.x * 256 + t;
    int v = (i < N_NODES) ? g_cnt[i] : 0;
    int sv = v;
    #pragma unroll
    for (int d = 1; d < 32; d <<= 1) {
        int x = __shfl_up_sync(0xffffffffu, sv, d);
        if (lane >= d) sv += x;
    }
    if (lane == 31) ws[w] = sv;
    __syncthreads();
    if (t < 8) {
        int x = ws[t];
        #pragma unroll
        for (int d = 1; d < 8; d <<= 1) {
            int y = __shfl_up_sync(0xffu, x, d);
            if (t >= d) x += y;
        }
        ws[t] = x;
    }
    __syncthreads();
    int excl = sv - v + ((w > 0) ? ws[w - 1] : 0);
    if (i < N_NODES) {
        g_start[i] = excl;
        g_cnt[i]   = 0;           // restore invariant for next graph replay
    }
    if (t == 255) g_bsum[blockIdx.x] = ws[7];
}

// add block offsets (each block reduces g_bsum[0..bid) itself), init cursors
__global__ __launch_bounds__(256) void kscan_add() {
    __shared__ int ws[8];
    __shared__ int offs;
    int t = threadIdx.x, lane = t & 31, w = t >> 5;
    int bid = blockIdx.x;
    int v = (t < bid) ? g_bsum[t] : 0;        // bid <= 195 < 256
    #pragma unroll
    for (int d = 16; d > 0; d >>= 1)
        v += __shfl_xor_sync(0xffffffffu, v, d);
    if (lane == 0) ws[w] = v;
    __syncthreads();
    if (t == 0) {
        int o = 0;
        #pragma unroll
        for (int i = 0; i < 8; ++i) o += ws[i];
        offs = o;
    }
    __syncthreads();
    int i = bid * 256 + t;
    if (i < N_NODES) {
        int s = g_start[i] + offs;
        g_start[i] = s;
        g_cur[i]   = s;
    }
    if (bid == 0 && t == 0) g_start[N_NODES] = N_EDGES;   // sentinel
}

// scatter + fold edge_emb @ C into g_eeh (fp16, grouped by dst)
__global__ __launch_bounds__(256) void kscatter(const int* __restrict__ src,
                                                const int* __restrict__ dst,
                                                const float* __restrict__ edge_emb) {
    __shared__ float Cs[64];
    int t = threadIdx.x;
    if (t < 64) Cs[t] = g_C[t];
    __syncthreads();

    int e = blockIdx.x * 256 + t;
    if (e >= N_EDGES) return;
    int pos = atomicAdd(&g_cur[dst[e]], 1);
    g_osrc[pos] = src[e];

    const float4* ep = (const float4*)(edge_emb + (long)e * HEADS);
    float4 e0 = ep[0], e1 = ep[1];
    float ein[8] = {e0.x, e0.y, e0.z, e0.w, e1.x, e1.y, e1.z, e1.w};
    float ee[8];
    #pragma unroll
    for (int h = 0; h < 8; ++h) {
        float s = 0.f;
        #pragma unroll
        for (int k = 0; k < 8; ++k) s += ein[k] * Cs[k * 8 + h];
        ee[h] = s;
    }
    __half2 p0 = __floats2half2_rn(ee[0], ee[1]);
    __half2 p1 = __floats2half2_rn(ee[2], ee[3]);
    __half2 p2 = __floats2half2_rn(ee[4], ee[5]);
    __half2 p3 = __floats2half2_rn(ee[6], ee[7]);
    uint4 packed = make_uint4(*(unsigned*)&p0, *(unsigned*)&p1,
                              *(unsigned*)&p2, *(unsigned*)&p3);
    *(uint4*)(g_eeh + (long)pos * HEADS) = packed;
}

// ---------------- K4f: fused softmax + aggregation, one warp per dst node ----
__device__ __forceinline__ void accum(float* acc, float a, uint4 r) {
    float2 f0 = __half22float2(*(__half2*)&r.x);
    float2 f1 = __half22float2(*(__half2*)&r.y);
    float2 f2 = __half22float2(*(__half2*)&r.z);
    float2 f3 = __half22float2(*(__half2*)&r.w);
    acc[0] += a * f0.x; acc[1] += a * f0.y;
    acc[2] += a * f1.x; acc[3] += a * f1.y;
    acc[4] += a * f2.x; acc[5] += a * f2.y;
    acc[6] += a * f3.x; acc[7] += a * f3.y;
}

__device__ __forceinline__ float lrelu_exp(float x) {
    x = (x > 0.f) ? x : NEG_SLOPE * x;
    return __expf(x);
}

__global__ __launch_bounds__(256) void k4f(const float* __restrict__ bias,
                                           float* __restrict__ out) {
    __shared__ float sb[HD];
    int t = threadIdx.x;
    sb[t] = bias[t];
    __syncthreads();

    int warp = t >> 5, lane = t & 31;
    int node = blockIdx.x * 8 + warp;
    if (node >= N_NODES) return;

    int beg = g_start[node];
    int end = g_start[node + 1];

    const int hsel = lane >> 2;
    float er_h = g_er[node * HEADS + hsel];

    float acc[8] = {0.f, 0.f, 0.f, 0.f, 0.f, 0.f, 0.f, 0.f};
    float s = 0.f;

    int j = beg;
    int n0 = 0, n1 = 0, n2 = 0, n3 = 0;
    if (j + 3 < end) {
        n0 = g_osrc[j];     n1 = g_osrc[j + 1];
        n2 = g_osrc[j + 2]; n3 = g_osrc[j + 3];
    }
    while (j + 3 < end) {
        uint4 ra = *(const uint4*)(g_hh + (long)n0 * HD + lane * 8);
        uint4 rb = *(const uint4*)(g_hh + (long)n1 * HD + lane * 8);
        uint4 rc = *(const uint4*)(g_hh + (long)n2 * HD + lane * 8);
        uint4 rd = *(const uint4*)(g_hh + (long)n3 * HD + lane * 8);

        float el0 = g_el[n0 * HEADS + hsel];
        float el1 = g_el[n1 * HEADS + hsel];
        float el2 = g_el[n2 * HEADS + hsel];
        float el3 = g_el[n3 * HEADS + hsel];
        float ee0 = __half2float(g_eeh[(long)(j)     * HEADS + hsel]);
        float ee1 = __half2float(g_eeh[(long)(j + 1) * HEADS + hsel]);
        float ee2 = __half2float(g_eeh[(long)(j + 2) * HEADS + hsel]);
        float ee3 = __half2float(g_eeh[(long)(j + 3) * HEADS + hsel]);

        int jn = j + 4;
        if (jn + 3 < end) {
            n0 = g_osrc[jn];     n1 = g_osrc[jn + 1];
            n2 = g_osrc[jn + 2]; n3 = g_osrc[jn + 3];
        }

        float p0 = lrelu_exp(el0 + er_h + ee0);
        float p1 = lrelu_exp(el1 + er_h + ee1);
        float p2 = lrelu_exp(el2 + er_h + ee2);
        float p3 = lrelu_exp(el3 + er_h + ee3);
        s += (p0 + p1) + (p2 + p3);

        accum(acc, p0, ra);
        accum(acc, p1, rb);
        accum(acc, p2, rc);
        accum(acc, p3, rd);
        j = jn;
    }
    for (; j < end; ++j) {
        int sn = g_osrc[j];
        uint4 ra = *(const uint4*)(g_hh + (long)sn * HD + lane * 8);
        float el0 = g_el[sn * HEADS + hsel];
        float ee0 = __half2float(g_eeh[(long)j * HEADS + hsel]);
        float p0 = lrelu_exp(el0 + er_h + ee0);
        s += p0;
        accum(acc, p0, ra);
    }

    float inv = 1.f / (s + 1e-9f);

    float* op = out + (long)node * HD + lane * 8;
    const float* bp = sb + lane * 8;
    *(float4*)(op)     = make_float4(acc[0] * inv + bp[0], acc[1] * inv + bp[1],
                                     acc[2] * inv + bp[2], acc[3] * inv + bp[3]);
    *(float4*)(op + 4) = make_float4(acc[4] * inv + bp[4], acc[5] * inv + bp[5],
                                     acc[6] * inv + bp[6], acc[7] * inv + bp[7]);
}

// ---------------- launch: fork CSR chain onto a side stream -------------------
extern "C" void kernel_launch(void* const* d_in, const int* in_sizes, int n_in,
                              void* d_out, int out_size) {
    const float* feat     = (const float*)d_in[0];
    const float* edge_emb = (const float*)d_in[1];
    const int*   src      = (const int*)  d_in[2];
    const int*   dst      = (const int*)  d_in[3];
    const float* W_src    = (const float*)d_in[4];
    const float* W_e      = (const float*)d_in[5];
    const float* attn_l   = (const float*)d_in[6];
    const float* attn_r   = (const float*)d_in[7];
    const float* attn_e   = (const float*)d_in[8];
    const float* bias     = (const float*)d_in[9];
    float* out = (float*)d_out;

    static cudaStream_t s2 = nullptr;
    static cudaEvent_t evFork = nullptr, evJoin = nullptr;
    if (s2 == nullptr) {
        cudaStreamCreateWithFlags(&s2, cudaStreamNonBlocking);
        cudaEventCreateWithFlags(&evFork, cudaEventDisableTiming);
        cudaEventCreateWithFlags(&evJoin, cudaEventDisableTiming);
        cudaFuncSetAttribute(k1_mma, cudaFuncAttributeMaxDynamicSharedMemorySize,
                             SMEM_K1);
    }

    // fork: CSR chain on s2, GEMM chain on the main (capture) stream
    cudaEventRecord(evFork, 0);
    cudaStreamWaitEvent(s2, evFork, 0);

    // --- s2: CSR build (independent of GEMM; g_cnt is zero by invariant) ---
    khist     <<<(N_EDGES + 255) / 256, 256, 0, s2>>>(dst, W_e, attn_e);
    kscan_part<<<NB_SCAN, 256, 0, s2>>>();
    kscan_add <<<NB_SCAN, 256, 0, s2>>>();
    kscatter  <<<(N_EDGES + 255) / 256, 256, 0, s2>>>(src, dst, edge_emb);
    cudaEventRecord(evJoin, s2);

    // --- main stream: weights conv + GEMM (+ fused el/er) ---
    kconvB<<<HD, HD>>>(W_src);
    dim3 g1((N_NODES + 127) / 128, 2);
    k1_mma<<<g1, 256, SMEM_K1>>>(feat, attn_l, attn_r);

    // join, then fused softmax+aggregation
    cudaStreamWaitEvent(0, evJoin, 0);
    k4f<<<(N_NODES + 7) / 8, 256>>>(bias, out);
}